// round 1
// baseline (speedup 1.0000x reference)
#include <cuda_runtime.h>
#include <cuda_bf16.h>
#include <math.h>

// ---------------- problem constants ----------------
#define Bb   4
#define Ss   4096
#define Dd   768
#define Hh   12
#define Mm   256
#define DhD  64
#define NROWS (Bb*Ss)        // 16384
#define NBH   (Bb*Hh)        // 48
#define NHR   (NBH*Ss)       // 196608
#define FFH   (4*Dd)         // 3072

#define NORM_C   0.35355339059327373f   // 64^-0.25
#define RATIO_C  0.0625f                // 256^-0.5
#define DIAG_C   0.0625f                // 0.5 * norm^2 = 0.5/8
#define EPS_K    1e-4f
#define LN_EPS   1e-5f

// ---------------- scratch (device globals; allocation-free) ----------------
__device__ float g_h1[NROWS*Dd];         // ln1 out, reused as ln2 out
__device__ float g_qh[NHR*DhD];          // q in [b,h,s,dh]
__device__ float g_kh[NHR*DhD];
__device__ float g_vh[NHR*DhD];
__device__ float g_big[(size_t)NHR*Mm];  // qp raw/exp, later FFN mid (16384*3072 == NHR*Mm)
__device__ float g_kp [(size_t)NHR*Mm];  // kp raw/exp
__device__ float g_diagq[NHR];
__device__ float g_diagk[NHR];
__device__ float g_ksum_part[NBH*8*Mm];
__device__ float g_ksum[NBH*Mm];
__device__ float g_ctxT[NBH*DhD*Mm];     // ctx transposed: [bh][dh][m]
__device__ float g_dinv[NHR];
__device__ float g_attnh[NHR*DhD];       // attn in [b,h,s,dh]
__device__ float g_attn[NROWS*Dd];       // attn in [b,s,D]
__device__ float g_x2[NROWS*Dd];         // residual after attention
__device__ float g_maxpart[1024];
__device__ float g_gmax;

// ---------------- epilogue modes ----------------
enum { EPI_BIAS=0, EPI_BIAS_RES=1, EPI_BIAS_GELU=2, EPI_SCALE=3, EPI_ROWSCALE=4, EPI_QKV=5 };

// ---------------- generic NT GEMM: C[m,n] = sum_k A[m,k]*B[n,k] (+epilogue) ----------------
// A [M,K] row-major lda, B [N,K] row-major ldb. Batched over blockIdx.z via strides.
template<int BM,int BN,int BK,int TM,int TN,int EPI>
__global__ void __launch_bounds__((BM/TM)*(BN/TN))
gemm_nt(const float* __restrict__ A, int lda, long long sA,
        const float* __restrict__ B, int ldb, long long sB,
        float* __restrict__ C, int ldc, long long sC,
        int M, int N, int K,
        const float* __restrict__ bias,
        const float* __restrict__ res,
        const float* __restrict__ rowscale,
        float alpha)
{
    constexpr int TX = BN/TN, TY = BM/TM, THREADS = TX*TY;
    constexpr int KV = BK/4;
    constexpr int ALD = (BM*KV)/THREADS;
    constexpr int BLD = (BN*KV)/THREADS;
    static_assert(ALD*THREADS == BM*KV, "A tile load mismatch");
    static_assert(BLD*THREADS == BN*KV, "B tile load mismatch");

    __shared__ float As[BK][BM];
    __shared__ float Bs[BK][BN];

    const int z = blockIdx.z;
    A += (long long)z*sA;  B += (long long)z*sB;  C += (long long)z*sC;

    const int brow = blockIdx.y*BM;
    const int bcol = blockIdx.x*BN;
    const int tid  = threadIdx.x;
    const int tx   = tid % TX;
    const int ty   = tid / TX;

    float acc[TM][TN];
    #pragma unroll
    for (int i=0;i<TM;i++)
        #pragma unroll
        for (int j=0;j<TN;j++) acc[i][j]=0.f;

    for (int k0=0; k0<K; k0+=BK) {
        #pragma unroll
        for (int l=0;l<ALD;l++){
            int idx = tid + l*THREADS;
            int r = idx / KV, kc = idx % KV;
            float4 t4 = *reinterpret_cast<const float4*>(A + (long long)(brow+r)*lda + k0 + kc*4);
            As[kc*4+0][r]=t4.x; As[kc*4+1][r]=t4.y; As[kc*4+2][r]=t4.z; As[kc*4+3][r]=t4.w;
        }
        #pragma unroll
        for (int l=0;l<BLD;l++){
            int idx = tid + l*THREADS;
            int r = idx / KV, kc = idx % KV;
            float4 t4 = *reinterpret_cast<const float4*>(B + (long long)(bcol+r)*ldb + k0 + kc*4);
            Bs[kc*4+0][r]=t4.x; Bs[kc*4+1][r]=t4.y; Bs[kc*4+2][r]=t4.z; Bs[kc*4+3][r]=t4.w;
        }
        __syncthreads();
        #pragma unroll
        for (int k=0;k<BK;k++){
            float ar[TM], br[TN];
            #pragma unroll
            for (int i=0;i<TM;i+=4){
                float4 t=*reinterpret_cast<const float4*>(&As[k][ty*TM+i]);
                ar[i]=t.x; ar[i+1]=t.y; ar[i+2]=t.z; ar[i+3]=t.w;
            }
            #pragma unroll
            for (int j=0;j<TN;j+=4){
                float4 t=*reinterpret_cast<const float4*>(&Bs[k][tx*TN+j]);
                br[j]=t.x; br[j+1]=t.y; br[j+2]=t.z; br[j+3]=t.w;
            }
            #pragma unroll
            for (int i=0;i<TM;i++)
                #pragma unroll
                for (int j=0;j<TN;j++)
                    acc[i][j] = fmaf(ar[i], br[j], acc[i][j]);
        }
        __syncthreads();
    }

    const int crow0 = brow + ty*TM;
    const int ccol0 = bcol + tx*TN;
    #pragma unroll
    for (int i=0;i<TM;i++){
        const int gr = crow0 + i;
        float rs = 1.0f;
        if (EPI==EPI_ROWSCALE) rs = rowscale[(long long)z*M + gr];
        #pragma unroll
        for (int j=0;j<TN;j+=4){
            const int gc = ccol0 + j;
            float vv[4];
            #pragma unroll
            for (int u=0;u<4;u++){
                float v = acc[i][j+u];
                if (EPI==EPI_BIAS || EPI==EPI_BIAS_RES || EPI==EPI_BIAS_GELU || EPI==EPI_QKV)
                    v += bias[gc+u];
                if (EPI==EPI_BIAS_RES)  v += res[(long long)gr*ldc + gc + u];
                if (EPI==EPI_BIAS_GELU) v = 0.5f*v*(1.0f+erff(v*0.70710678118654752f));
                if (EPI==EPI_SCALE)     v *= alpha;
                if (EPI==EPI_ROWSCALE)  v *= rs;
                vv[u]=v;
            }
            float4 o; o.x=vv[0]; o.y=vv[1]; o.z=vv[2]; o.w=vv[3];
            if (EPI==EPI_QKV){
                int b_ = gr>>12, s_ = gr&4095, h_ = gc>>6, dh_ = gc&63;
                *reinterpret_cast<float4*>(C + ((((long long)(b_*Hh+h_))<<12) + s_)*DhD + dh_) = o;
            } else {
                *reinterpret_cast<float4*>(C + (long long)gr*ldc + gc) = o;
            }
        }
    }
}

// ---------------- LayerNorm (row = 768, 256 threads/block) ----------------
__global__ void ln_kernel(const float* __restrict__ x, const float* __restrict__ g,
                          const float* __restrict__ b, float* __restrict__ out)
{
    const int row = blockIdx.x;
    const float* xr = x + (long long)row*Dd;
    float v[3]; float s=0.f, ss=0.f;
    #pragma unroll
    for (int i=0;i<3;i++){ v[i]=xr[threadIdx.x + i*256]; s+=v[i]; ss+=v[i]*v[i]; }
    #pragma unroll
    for (int o=16;o;o>>=1){ s+=__shfl_xor_sync(0xffffffffu,s,o); ss+=__shfl_xor_sync(0xffffffffu,ss,o); }
    __shared__ float rs_[8], rss_[8];
    const int lane = threadIdx.x & 31, w = threadIdx.x >> 5;
    if (lane==0){ rs_[w]=s; rss_[w]=ss; }
    __syncthreads();
    s=0.f; ss=0.f;
    #pragma unroll
    for (int i=0;i<8;i++){ s+=rs_[i]; ss+=rss_[i]; }
    const float mu  = s*(1.0f/Dd);
    const float var = ss*(1.0f/Dd) - mu*mu;
    const float rstd = rsqrtf(var + LN_EPS);
    float* outr = out + (long long)row*Dd;
    #pragma unroll
    for (int i=0;i<3;i++){
        int c = threadIdx.x + i*256;
        outr[c] = (v[i]-mu)*rstd*g[c] + b[c];
    }
}

// ---------------- diag: 0.0625 * sum(q^2) over head dim (warp per row) ----------------
__global__ void diag_kernel(const float* __restrict__ src, float* __restrict__ dst)
{
    const int lane = threadIdx.x & 31, w = threadIdx.x >> 5;
    const long long row = (long long)blockIdx.x*8 + w;
    float2 v = reinterpret_cast<const float2*>(src + row*DhD)[lane];
    float s = v.x*v.x + v.y*v.y;
    #pragma unroll
    for (int o=16;o;o>>=1) s += __shfl_xor_sync(0xffffffffu,s,o);
    if (lane==0) dst[row] = DIAG_C * s;
}

// ---------------- q features: row max + exp, in place (warp per row of 256) ----------------
__global__ void expq_kernel(float* __restrict__ qp, const float* __restrict__ diag)
{
    const int lane = threadIdx.x & 31, w = threadIdx.x >> 5;
    const long long row = (long long)blockIdx.x*8 + w;
    float4* p = reinterpret_cast<float4*>(qp + row*Mm);
    float4 a = p[lane], c = p[lane+32];
    float mx = fmaxf(fmaxf(fmaxf(a.x,a.y),fmaxf(a.z,a.w)),
                     fmaxf(fmaxf(c.x,c.y),fmaxf(c.z,c.w)));
    #pragma unroll
    for (int o=16;o;o>>=1) mx = fmaxf(mx, __shfl_xor_sync(0xffffffffu,mx,o));
    const float d = diag[row] + mx;
    a.x = RATIO_C*(expf(a.x-d)+EPS_K); a.y = RATIO_C*(expf(a.y-d)+EPS_K);
    a.z = RATIO_C*(expf(a.z-d)+EPS_K); a.w = RATIO_C*(expf(a.w-d)+EPS_K);
    c.x = RATIO_C*(expf(c.x-d)+EPS_K); c.y = RATIO_C*(expf(c.y-d)+EPS_K);
    c.z = RATIO_C*(expf(c.z-d)+EPS_K); c.w = RATIO_C*(expf(c.w-d)+EPS_K);
    p[lane]=a; p[lane+32]=c;
}

// ---------------- global max over kp raw ----------------
__global__ void max1_kernel(const float* __restrict__ kp)
{
    const long long n = (long long)NHR*Mm;
    float m = -3.402823466e38f;
    for (long long i = (long long)blockIdx.x*blockDim.x + threadIdx.x; i<n;
         i += (long long)gridDim.x*blockDim.x)
        m = fmaxf(m, kp[i]);
    #pragma unroll
    for (int o=16;o;o>>=1) m = fmaxf(m, __shfl_xor_sync(0xffffffffu,m,o));
    __shared__ float sm[8];
    const int lane = threadIdx.x & 31, w = threadIdx.x >> 5;
    if (lane==0) sm[w]=m;
    __syncthreads();
    if (threadIdx.x==0){
        float t = sm[0];
        #pragma unroll
        for (int i=1;i<8;i++) t = fmaxf(t, sm[i]);
        g_maxpart[blockIdx.x] = t;
    }
}
__global__ void max2_kernel()
{
    float m = -3.402823466e38f;
    for (int i=threadIdx.x; i<1024; i+=256) m = fmaxf(m, g_maxpart[i]);
    #pragma unroll
    for (int o=16;o;o>>=1) m = fmaxf(m, __shfl_xor_sync(0xffffffffu,m,o));
    __shared__ float sm[8];
    const int lane = threadIdx.x & 31, w = threadIdx.x >> 5;
    if (lane==0) sm[w]=m;
    __syncthreads();
    if (threadIdx.x==0){
        float t = sm[0];
        #pragma unroll
        for (int i=1;i<8;i++) t = fmaxf(t, sm[i]);
        g_gmax = t;
    }
}

// ---------------- k features: global max + exp, in place (elementwise) ----------------
__global__ void expk_kernel(float* __restrict__ kp, const float* __restrict__ diag)
{
    const long long i4 = (long long)blockIdx.x*blockDim.x + threadIdx.x; // float4 idx
    const float gm = g_gmax;
    const long long row = i4 >> 6;      // (i4*4)/256
    const float d = diag[row] + gm;
    float4* p = reinterpret_cast<float4*>(kp);
    float4 v = p[i4];
    v.x = RATIO_C*(expf(v.x-d)+EPS_K); v.y = RATIO_C*(expf(v.y-d)+EPS_K);
    v.z = RATIO_C*(expf(v.z-d)+EPS_K); v.w = RATIO_C*(expf(v.w-d)+EPS_K);
    p[i4] = v;
}

// ---------------- k_sum over S (two stage) ----------------
__global__ void ksum_part_kernel(const float* __restrict__ kp)
{
    const int bh = blockIdx.x, split = blockIdx.y, m = threadIdx.x;
    const float* p = kp + ((long long)bh*Ss + (long long)split*512)*Mm + m;
    float s = 0.f;
    for (int i=0;i<512;i++) s += p[(long long)i*Mm];
    g_ksum_part[(bh*8+split)*Mm + m] = s;
}
__global__ void ksum_red_kernel()
{
    const int bh = blockIdx.x, m = threadIdx.x;
    float s = 0.f;
    #pragma unroll
    for (int i=0;i<8;i++) s += g_ksum_part[(bh*8+i)*Mm + m];
    g_ksum[bh*Mm + m] = s;
}

// ---------------- ctx^T[bh][dh][m] = sum_s kp[bh,s,m]*v[bh,s,dh] ----------------
__global__ void __launch_bounds__(256)
ctx_kernel(const float* __restrict__ kp, const float* __restrict__ vh, float* __restrict__ ctxT)
{
    const int z = blockIdx.z;             // bh
    const int mtile = blockIdx.y;         // 4 tiles of 64 m
    __shared__ float As[16][64];          // kp [s][m]
    __shared__ float Bs[16][64];          // v  [s][dh]
    const int tid = threadIdx.x;
    const int tx = tid % 16;              // dh/4
    const int ty = tid / 16;              // m/4
    const int r = tid / 16, c = tid % 16; // loader map

    const float* kpb = kp + (long long)z*Ss*Mm + mtile*64;
    const float* vhb = vh + (long long)z*Ss*DhD;

    float acc[4][4];
    #pragma unroll
    for (int i=0;i<4;i++)
        #pragma unroll
        for (int j=0;j<4;j++) acc[i][j]=0.f;

    for (int s0=0; s0<Ss; s0+=16){
        *reinterpret_cast<float4*>(&As[r][c*4]) =
            *reinterpret_cast<const float4*>(kpb + (long long)(s0+r)*Mm + c*4);
        *reinterpret_cast<float4*>(&Bs[r][c*4]) =
            *reinterpret_cast<const float4*>(vhb + (long long)(s0+r)*DhD + c*4);
        __syncthreads();
        #pragma unroll
        for (int k=0;k<16;k++){
            float4 a4 = *reinterpret_cast<const float4*>(&As[k][ty*4]);
            float4 b4 = *reinterpret_cast<const float4*>(&Bs[k][tx*4]);
            float ar[4]={a4.x,a4.y,a4.z,a4.w}, br[4]={b4.x,b4.y,b4.z,b4.w};
            #pragma unroll
            for (int i=0;i<4;i++)
                #pragma unroll
                for (int j=0;j<4;j++) acc[i][j] = fmaf(ar[i], br[j], acc[i][j]);
        }
        __syncthreads();
    }
    // store transposed: ctxT[z][dh][m]
    #pragma unroll
    for (int i=0;i<4;i++)
        #pragma unroll
        for (int j=0;j<4;j++){
            int m_  = mtile*64 + ty*4 + i;
            int dh_ = tx*4 + j;
            ctxT[(long long)z*DhD*Mm + (long long)dh_*Mm + m_] = acc[i][j];
        }
}

// ---------------- d_inv (warp per row) ----------------
__global__ void dinv_kernel(const float* __restrict__ qp, float* __restrict__ dinv)
{
    const int lane = threadIdx.x & 31, w = threadIdx.x >> 5;
    const long long row = (long long)blockIdx.x*8 + w;
    const int bh = (int)(row >> 12);
    const float4* p  = reinterpret_cast<const float4*>(qp + row*Mm);
    const float4* ks = reinterpret_cast<const float4*>(g_ksum + (long long)bh*Mm);
    float4 a = p[lane], b = p[lane+32], ka = ks[lane], kb = ks[lane+32];
    float s = a.x*ka.x + a.y*ka.y + a.z*ka.z + a.w*ka.w
            + b.x*kb.x + b.y*kb.y + b.z*kb.z + b.w*kb.w;
    #pragma unroll
    for (int o=16;o;o>>=1) s += __shfl_xor_sync(0xffffffffu,s,o);
    if (lane==0) dinv[row] = 1.0f/s;
}

// ---------------- transpose attn [b,h,s,dh] -> [b,s,D] ----------------
__global__ void trans_kernel(const float* __restrict__ attnh, float* __restrict__ out)
{
    const long long i4 = (long long)blockIdx.x*blockDim.x + threadIdx.x;
    const long long idx = i4*4;
    const int row = (int)(idx / Dd);
    const int col = (int)(idx % Dd);
    const int b_ = row>>12, s_ = row&4095, h_ = col>>6, dh_ = col&63;
    *reinterpret_cast<float4*>(out + idx) =
        *reinterpret_cast<const float4*>(attnh + ((((long long)(b_*Hh+h_))<<12)+s_)*DhD + dh_);
}

// ---------------- host ----------------
extern "C" void kernel_launch(void* const* d_in, const int* in_sizes, int n_in,
                              void* d_out, int out_size)
{
    const float* x    = (const float*)d_in[0];
    const float* proj = (const float*)d_in[1];
    const float* wq   = (const float*)d_in[2];
    const float* bq   = (const float*)d_in[3];
    const float* wk   = (const float*)d_in[4];
    const float* bk   = (const float*)d_in[5];
    const float* wv   = (const float*)d_in[6];
    const float* bv   = (const float*)d_in[7];
    const float* wo   = (const float*)d_in[8];
    const float* bo   = (const float*)d_in[9];
    const float* ln1g = (const float*)d_in[10];
    const float* ln1b = (const float*)d_in[11];
    const float* ln2g = (const float*)d_in[12];
    const float* ln2b = (const float*)d_in[13];
    const float* w1   = (const float*)d_in[14];
    const float* b1   = (const float*)d_in[15];
    const float* w2   = (const float*)d_in[16];
    const float* b2   = (const float*)d_in[17];
    float* out = (float*)d_out;

    void *p;
    float *h1, *qh, *kh, *vh, *qp, *kp, *dq, *dk, *ctxT, *dinv, *attnh, *attn, *x2;
    cudaGetSymbolAddress(&p, g_h1);    h1    = (float*)p;
    cudaGetSymbolAddress(&p, g_qh);    qh    = (float*)p;
    cudaGetSymbolAddress(&p, g_kh);    kh    = (float*)p;
    cudaGetSymbolAddress(&p, g_vh);    vh    = (float*)p;
    cudaGetSymbolAddress(&p, g_big);   qp    = (float*)p;
    cudaGetSymbolAddress(&p, g_kp);    kp    = (float*)p;
    cudaGetSymbolAddress(&p, g_diagq); dq    = (float*)p;
    cudaGetSymbolAddress(&p, g_diagk); dk    = (float*)p;
    cudaGetSymbolAddress(&p, g_ctxT);  ctxT  = (float*)p;
    cudaGetSymbolAddress(&p, g_dinv);  dinv  = (float*)p;
    cudaGetSymbolAddress(&p, g_attnh); attnh = (float*)p;
    cudaGetSymbolAddress(&p, g_attn);  attn  = (float*)p;
    cudaGetSymbolAddress(&p, g_x2);    x2    = (float*)p;
    float* mid = qp; // alias: qp dead before FFN mid is written

    // 1. LN1
    ln_kernel<<<NROWS, 256>>>(x, ln1g, ln1b, h1);

    // 2-4. QKV projections, stored directly in [b,h,s,dh]
    gemm_nt<128,128,8,8,8,EPI_QKV><<<dim3(6,128,1),256>>>(
        h1,Dd,0, wq,Dd,0, qh,DhD,0, NROWS,Dd,Dd, bq,nullptr,nullptr,0.f);
    gemm_nt<128,128,8,8,8,EPI_QKV><<<dim3(6,128,1),256>>>(
        h1,Dd,0, wk,Dd,0, kh,DhD,0, NROWS,Dd,Dd, bk,nullptr,nullptr,0.f);
    gemm_nt<128,128,8,8,8,EPI_QKV><<<dim3(6,128,1),256>>>(
        h1,Dd,0, wv,Dd,0, vh,DhD,0, NROWS,Dd,Dd, bv,nullptr,nullptr,0.f);

    // 5. diag terms
    diag_kernel<<<NHR/8, 256>>>(qh, dq);
    diag_kernel<<<NHR/8, 256>>>(kh, dk);

    // 6-7. dd = norm * (q/k @ proj^T), single big GEMM each
    gemm_nt<128,128,8,8,8,EPI_SCALE><<<dim3(2,NHR/128,1),256>>>(
        qh,DhD,0, proj,DhD,0, qp,Mm,0, NHR,Mm,DhD, nullptr,nullptr,nullptr,NORM_C);
    gemm_nt<128,128,8,8,8,EPI_SCALE><<<dim3(2,NHR/128,1),256>>>(
        kh,DhD,0, proj,DhD,0, kp,Mm,0, NHR,Mm,DhD, nullptr,nullptr,nullptr,NORM_C);

    // 8. global max of dd_k
    max1_kernel<<<1024, 256>>>(kp);
    max2_kernel<<<1, 256>>>();

    // 9-10. FAVOR+ exp features (in place)
    expq_kernel<<<NHR/8, 256>>>(qp, dq);
    expk_kernel<<<(NHR*(Mm/4))/256, 256>>>(kp, dk);

    // 11. k_sum
    ksum_part_kernel<<<dim3(NBH,8,1), 256>>>(kp);
    ksum_red_kernel<<<NBH, 256>>>();

    // 12. ctx^T = (kp^T @ v)^T
    ctx_kernel<<<dim3(1,4,NBH), 256>>>(kp, vh, ctxT);

    // 13. d_inv
    dinv_kernel<<<NHR/8, 256>>>(qp, dinv);

    // 14. attn_h = d_inv * (qp @ ctx), batched over bh
    gemm_nt<128,64,16,8,4,EPI_ROWSCALE><<<dim3(1,Ss/128,NBH),256>>>(
        qp,Mm,(long long)Ss*Mm, ctxT,Mm,(long long)DhD*Mm, attnh,DhD,(long long)Ss*DhD,
        Ss,DhD,Mm, nullptr,nullptr,dinv,0.f);

    // 15. transpose to [b,s,D]
    trans_kernel<<<(NROWS*Dd/4)/256, 256>>>(attnh, attn);

    // 16. x2 = x + attn @ wo^T + bo
    gemm_nt<128,128,8,8,8,EPI_BIAS_RES><<<dim3(6,128,1),256>>>(
        attn,Dd,0, wo,Dd,0, x2,Dd,0, NROWS,Dd,Dd, bo,x,nullptr,0.f);

    // 17. LN2
    ln_kernel<<<NROWS, 256>>>(x2, ln2g, ln2b, h1);

    // 18. mid = gelu(h1 @ w1^T + b1)
    gemm_nt<128,128,8,8,8,EPI_BIAS_GELU><<<dim3(FFH/128,128,1),256>>>(
        h1,Dd,0, w1,Dd,0, mid,FFH,0, NROWS,FFH,Dd, b1,nullptr,nullptr,0.f);

    // 19. out = x2 + mid @ w2^T + b2
    gemm_nt<128,128,8,8,8,EPI_BIAS_RES><<<dim3(6,128,1),256>>>(
        mid,FFH,0, w2,FFH,0, out,Dd,0, NROWS,Dd,FFH, b2,x2,nullptr,0.f);
}

// round 4
// speedup vs baseline: 2.4519x; 2.4519x over previous
#include <cuda_runtime.h>
#include <cuda_bf16.h>
#include <math.h>
#include <stdint.h>

// ---------------- problem constants ----------------
#define Bb   4
#define Ss   4096
#define Dd   768
#define Hh   12
#define Mm   256
#define DhD  64
#define NROWS (Bb*Ss)        // 16384
#define NBH   (Bb*Hh)        // 48
#define NHR   (NBH*Ss)       // 196608
#define FFH   (4*Dd)         // 3072

#define NORM_C   0.35355339059327373f   // 64^-0.25
#define RATIO_C  0.0625f                // 256^-0.5
#define DIAG_C   0.0625f                // 0.5 * norm^2 = 0.5/8
#define EPS_K    1e-4f
#define LN_EPS   1e-5f

// ---------------- scratch (device globals; allocation-free) ----------------
__device__ float g_h1[NROWS*Dd];         // ln1 out, reused as ln2 out
__device__ float g_qh[NHR*DhD];          // q in [b,h,s,dh]
__device__ float g_kh[NHR*DhD];
__device__ float g_vh[NHR*DhD];
__device__ float g_big[(size_t)NHR*Mm];  // qp raw/exp, later FFN mid
__device__ float g_kp [(size_t)NHR*Mm];  // kp raw/exp
__device__ float g_diagq[NHR];
__device__ float g_diagk[NHR];
__device__ float g_ksum_part[NBH*8*Mm];
__device__ float g_ksum[NBH*Mm];
__device__ float g_ctxT[NBH*DhD*Mm];     // ctx transposed: [bh][dh][m]
__device__ float g_dinv[NHR];
__device__ float g_attnh[NHR*DhD];       // attn in [b,h,s,dh]
__device__ float g_attn[NROWS*Dd];       // attn in [b,s,D]
__device__ float g_x2[NROWS*Dd];         // residual after attention
__device__ float g_maxpart[1024];
__device__ float g_gmax;

// ---------------- epilogue modes ----------------
enum { EPI_BIAS=0, EPI_BIAS_RES=1, EPI_BIAS_GELU=2, EPI_SCALE=3, EPI_ROWSCALE=4, EPI_QKV=5 };

__device__ __forceinline__ uint32_t f2tf32(float x){
    uint32_t o; asm("cvt.rna.tf32.f32 %0, %1;" : "=r"(o) : "f"(x)); return o;
}

__device__ __forceinline__ void mma_tf32(float* d, const uint32_t* a, const uint32_t* b){
    asm volatile("mma.sync.aligned.m16n8k8.row.col.f32.tf32.tf32.f32 "
        "{%0,%1,%2,%3}, {%4,%5,%6,%7}, {%8,%9}, {%0,%1,%2,%3};"
        : "+f"(d[0]),"+f"(d[1]),"+f"(d[2]),"+f"(d[3])
        : "r"(a[0]),"r"(a[1]),"r"(a[2]),"r"(a[3]), "r"(b[0]),"r"(b[1]));
}

// ================= tensor-core TF32 NT GEMM via mma.sync =================
// C[m,n] = sum_k A[m,k]*B[n,k] (+ epilogue). BK=32, warp tile 64x32.
// BM,BN in {128}x{128,64}. M,N multiples of BM,BN; K multiple of 32.
template<int BM,int BN,int EPI>
__global__ void __launch_bounds__(32*(BM/64)*(BN/32))
gemm_mma(const float* __restrict__ A, int lda, long long strA,
         const float* __restrict__ B, int ldb, long long strB,
         float* __restrict__ C, int ldc, long long strC,
         int M, int N, int K,
         const float* __restrict__ bias,
         const float* __restrict__ res,
         const float* __restrict__ rowscale,
         float alpha)
{
    constexpr int WY = BM/64, WX = BN/32, THREADS = 32*WY*WX;
    constexpr int LDK = 36;                     // 32 + 4 pad (word stride)
    constexpr int ALD = (BM*8)/THREADS;         // float4 loads per thread (A)
    constexpr int BLD = (BN*8)/THREADS;

    __shared__ uint32_t As[BM*LDK];
    __shared__ uint32_t Bs[BN*LDK];

    const int z = blockIdx.z;
    A += (long long)z*strA;  B += (long long)z*strB;  C += (long long)z*strC;

    const int brow = blockIdx.y*BM;
    const int bcol = blockIdx.x*BN;
    const int tid  = threadIdx.x;
    const int wid  = tid >> 5;
    const int lane = tid & 31;
    const int wx   = wid % WX, wy = wid / WX;
    const int warp_m = wy*64, warp_n = wx*32;
    const int g = lane >> 2, t = lane & 3;

    float acc[4][4][4];
    #pragma unroll
    for (int i=0;i<4;i++)
        #pragma unroll
        for (int j=0;j<4;j++)
            #pragma unroll
            for (int u=0;u<4;u++) acc[i][j][u]=0.f;

    float4 pa[ALD], pb[BLD];

    // load first tile
    #pragma unroll
    for (int l=0;l<ALD;l++){
        const int idx = tid + l*THREADS, r = idx>>3, c4 = idx&7;
        pa[l] = *reinterpret_cast<const float4*>(A + (long long)(brow+r)*lda + c4*4);
    }
    #pragma unroll
    for (int l=0;l<BLD;l++){
        const int idx = tid + l*THREADS, r = idx>>3, c4 = idx&7;
        pb[l] = *reinterpret_cast<const float4*>(B + (long long)(bcol+r)*ldb + c4*4);
    }
    #pragma unroll
    for (int l=0;l<ALD;l++){
        const int idx = tid + l*THREADS, r = idx>>3, c4 = idx&7;
        uint4 u = { f2tf32(pa[l].x), f2tf32(pa[l].y), f2tf32(pa[l].z), f2tf32(pa[l].w) };
        *reinterpret_cast<uint4*>(&As[r*LDK + c4*4]) = u;
    }
    #pragma unroll
    for (int l=0;l<BLD;l++){
        const int idx = tid + l*THREADS, r = idx>>3, c4 = idx&7;
        uint4 u = { f2tf32(pb[l].x), f2tf32(pb[l].y), f2tf32(pb[l].z), f2tf32(pb[l].w) };
        *reinterpret_cast<uint4*>(&Bs[r*LDK + c4*4]) = u;
    }
    __syncthreads();

    for (int k0=0; k0<K; k0+=32){
        const bool has_next = (k0+32) < K;
        if (has_next){
            #pragma unroll
            for (int l=0;l<ALD;l++){
                const int idx = tid + l*THREADS, r = idx>>3, c4 = idx&7;
                pa[l] = *reinterpret_cast<const float4*>(A + (long long)(brow+r)*lda + k0+32 + c4*4);
            }
            #pragma unroll
            for (int l=0;l<BLD;l++){
                const int idx = tid + l*THREADS, r = idx>>3, c4 = idx&7;
                pb[l] = *reinterpret_cast<const float4*>(B + (long long)(bcol+r)*ldb + k0+32 + c4*4);
            }
        }

        #pragma unroll
        for (int kk=0; kk<4; ++kk){
            uint32_t af[4][4], bf[4][2];
            #pragma unroll
            for (int mt=0; mt<4; ++mt){
                const int m0 = warp_m + mt*16;
                af[mt][0] = As[(m0+g  )*LDK + kk*8 + t    ];
                af[mt][1] = As[(m0+g+8)*LDK + kk*8 + t    ];
                af[mt][2] = As[(m0+g  )*LDK + kk*8 + t + 4];
                af[mt][3] = As[(m0+g+8)*LDK + kk*8 + t + 4];
            }
            #pragma unroll
            for (int nt=0; nt<4; ++nt){
                const int n0 = warp_n + nt*8;
                bf[nt][0] = Bs[(n0+g)*LDK + kk*8 + t    ];
                bf[nt][1] = Bs[(n0+g)*LDK + kk*8 + t + 4];
            }
            #pragma unroll
            for (int mt=0; mt<4; ++mt)
                #pragma unroll
                for (int nt=0; nt<4; ++nt)
                    mma_tf32(acc[mt][nt], af[mt], bf[nt]);
        }
        __syncthreads();

        if (has_next){
            #pragma unroll
            for (int l=0;l<ALD;l++){
                const int idx = tid + l*THREADS, r = idx>>3, c4 = idx&7;
                uint4 u = { f2tf32(pa[l].x), f2tf32(pa[l].y), f2tf32(pa[l].z), f2tf32(pa[l].w) };
                *reinterpret_cast<uint4*>(&As[r*LDK + c4*4]) = u;
            }
            #pragma unroll
            for (int l=0;l<BLD;l++){
                const int idx = tid + l*THREADS, r = idx>>3, c4 = idx&7;
                uint4 u = { f2tf32(pb[l].x), f2tf32(pb[l].y), f2tf32(pb[l].z), f2tf32(pb[l].w) };
                *reinterpret_cast<uint4*>(&Bs[r*LDK + c4*4]) = u;
            }
            __syncthreads();
        }
    }

    // -------- epilogue --------
    #pragma unroll
    for (int mt=0; mt<4; ++mt){
        const int r0 = brow + warp_m + mt*16 + g;
        const int r1 = r0 + 8;
        float rs0 = 1.f, rs1 = 1.f;
        if (EPI==EPI_ROWSCALE){
            rs0 = rowscale[(long long)z*M + r0];
            rs1 = rowscale[(long long)z*M + r1];
        }
        #pragma unroll
        for (int nt=0; nt<4; ++nt){
            const int c0 = bcol + warp_n + nt*8 + 2*t;
            float v00 = acc[mt][nt][0], v01 = acc[mt][nt][1];
            float v10 = acc[mt][nt][2], v11 = acc[mt][nt][3];
            if (EPI==EPI_BIAS || EPI==EPI_BIAS_RES || EPI==EPI_BIAS_GELU || EPI==EPI_QKV){
                const float b0 = bias[c0], b1 = bias[c0+1];
                v00 += b0; v01 += b1; v10 += b0; v11 += b1;
            }
            if (EPI==EPI_BIAS_RES){
                v00 += res[(long long)r0*ldc + c0];   v01 += res[(long long)r0*ldc + c0+1];
                v10 += res[(long long)r1*ldc + c0];   v11 += res[(long long)r1*ldc + c0+1];
            }
            if (EPI==EPI_BIAS_GELU){
                v00 = 0.5f*v00*(1.0f+erff(v00*0.70710678118654752f));
                v01 = 0.5f*v01*(1.0f+erff(v01*0.70710678118654752f));
                v10 = 0.5f*v10*(1.0f+erff(v10*0.70710678118654752f));
                v11 = 0.5f*v11*(1.0f+erff(v11*0.70710678118654752f));
            }
            if (EPI==EPI_SCALE){ v00*=alpha; v01*=alpha; v10*=alpha; v11*=alpha; }
            if (EPI==EPI_ROWSCALE){ v00*=rs0; v01*=rs0; v10*=rs1; v11*=rs1; }

            float2 o0; o0.x=v00; o0.y=v01;
            float2 o1; o1.x=v10; o1.y=v11;
            if (EPI==EPI_QKV){
                const int h_ = c0>>6, dh_ = c0&63;
                const int b0_ = r0>>12, s0_ = r0&4095;
                const int b1_ = r1>>12, s1_ = r1&4095;
                *reinterpret_cast<float2*>(C + ((((long long)(b0_*Hh+h_))<<12)+s0_)*DhD + dh_) = o0;
                *reinterpret_cast<float2*>(C + ((((long long)(b1_*Hh+h_))<<12)+s1_)*DhD + dh_) = o1;
            } else {
                *reinterpret_cast<float2*>(C + (long long)r0*ldc + c0) = o0;
                *reinterpret_cast<float2*>(C + (long long)r1*ldc + c0) = o1;
            }
        }
    }
}

// ---------------- LayerNorm (row = 768, 256 threads/block) ----------------
__global__ void ln_kernel(const float* __restrict__ x, const float* __restrict__ g,
                          const float* __restrict__ b, float* __restrict__ out)
{
    const int row = blockIdx.x;
    const float* xr = x + (long long)row*Dd;
    float v[3]; float s=0.f, ss=0.f;
    #pragma unroll
    for (int i=0;i<3;i++){ v[i]=xr[threadIdx.x + i*256]; s+=v[i]; ss+=v[i]*v[i]; }
    #pragma unroll
    for (int o=16;o;o>>=1){ s+=__shfl_xor_sync(0xffffffffu,s,o); ss+=__shfl_xor_sync(0xffffffffu,ss,o); }
    __shared__ float rs_[8], rss_[8];
    const int lane = threadIdx.x & 31, w = threadIdx.x >> 5;
    if (lane==0){ rs_[w]=s; rss_[w]=ss; }
    __syncthreads();
    s=0.f; ss=0.f;
    #pragma unroll
    for (int i=0;i<8;i++){ s+=rs_[i]; ss+=rss_[i]; }
    const float mu  = s*(1.0f/Dd);
    const float var = ss*(1.0f/Dd) - mu*mu;
    const float rstd = rsqrtf(var + LN_EPS);
    float* outr = out + (long long)row*Dd;
    #pragma unroll
    for (int i=0;i<3;i++){
        int c = threadIdx.x + i*256;
        outr[c] = (v[i]-mu)*rstd*g[c] + b[c];
    }
}

// ---------------- diag: 0.0625 * sum(q^2) over head dim (warp per row) ----------------
__global__ void diag_kernel(const float* __restrict__ src, float* __restrict__ dst)
{
    const int lane = threadIdx.x & 31, w = threadIdx.x >> 5;
    const long long row = (long long)blockIdx.x*8 + w;
    float2 v = reinterpret_cast<const float2*>(src + row*DhD)[lane];
    float s = v.x*v.x + v.y*v.y;
    #pragma unroll
    for (int o=16;o;o>>=1) s += __shfl_xor_sync(0xffffffffu,s,o);
    if (lane==0) dst[row] = DIAG_C * s;
}

// ---------------- q features: row max + exp, in place (warp per row of 256) ----------------
__global__ void expq_kernel(float* __restrict__ qp, const float* __restrict__ diag)
{
    const int lane = threadIdx.x & 31, w = threadIdx.x >> 5;
    const long long row = (long long)blockIdx.x*8 + w;
    float4* p = reinterpret_cast<float4*>(qp + row*Mm);
    float4 a = p[lane], c = p[lane+32];
    float mx = fmaxf(fmaxf(fmaxf(a.x,a.y),fmaxf(a.z,a.w)),
                     fmaxf(fmaxf(c.x,c.y),fmaxf(c.z,c.w)));
    #pragma unroll
    for (int o=16;o;o>>=1) mx = fmaxf(mx, __shfl_xor_sync(0xffffffffu,mx,o));
    const float d = diag[row] + mx;
    a.x = RATIO_C*(expf(a.x-d)+EPS_K); a.y = RATIO_C*(expf(a.y-d)+EPS_K);
    a.z = RATIO_C*(expf(a.z-d)+EPS_K); a.w = RATIO_C*(expf(a.w-d)+EPS_K);
    c.x = RATIO_C*(expf(c.x-d)+EPS_K); c.y = RATIO_C*(expf(c.y-d)+EPS_K);
    c.z = RATIO_C*(expf(c.z-d)+EPS_K); c.w = RATIO_C*(expf(c.w-d)+EPS_K);
    p[lane]=a; p[lane+32]=c;
}

// ---------------- global max over kp raw ----------------
__global__ void max1_kernel(const float* __restrict__ kp)
{
    const long long n = (long long)NHR*Mm;
    float m = -3.402823466e38f;
    for (long long i = (long long)blockIdx.x*blockDim.x + threadIdx.x; i<n;
         i += (long long)gridDim.x*blockDim.x)
        m = fmaxf(m, kp[i]);
    #pragma unroll
    for (int o=16;o;o>>=1) m = fmaxf(m, __shfl_xor_sync(0xffffffffu,m,o));
    __shared__ float sm[8];
    const int lane = threadIdx.x & 31, w = threadIdx.x >> 5;
    if (lane==0) sm[w]=m;
    __syncthreads();
    if (threadIdx.x==0){
        float tt = sm[0];
        #pragma unroll
        for (int i=1;i<8;i++) tt = fmaxf(tt, sm[i]);
        g_maxpart[blockIdx.x] = tt;
    }
}
__global__ void max2_kernel()
{
    float m = -3.402823466e38f;
    for (int i=threadIdx.x; i<1024; i+=256) m = fmaxf(m, g_maxpart[i]);
    #pragma unroll
    for (int o=16;o;o>>=1) m = fmaxf(m, __shfl_xor_sync(0xffffffffu,m,o));
    __shared__ float sm[8];
    const int lane = threadIdx.x & 31, w = threadIdx.x >> 5;
    if (lane==0) sm[w]=m;
    __syncthreads();
    if (threadIdx.x==0){
        float tt = sm[0];
        #pragma unroll
        for (int i=1;i<8;i++) tt = fmaxf(tt, sm[i]);
        g_gmax = tt;
    }
}

// ---------------- k features: global max + exp, in place (elementwise) ----------------
__global__ void expk_kernel(float* __restrict__ kp, const float* __restrict__ diag)
{
    const long long i4 = (long long)blockIdx.x*blockDim.x + threadIdx.x; // float4 idx
    const float gm = g_gmax;
    const long long row = i4 >> 6;      // (i4*4)/256
    const float d = diag[row] + gm;
    float4* p = reinterpret_cast<float4*>(kp);
    float4 v = p[i4];
    v.x = RATIO_C*(expf(v.x-d)+EPS_K); v.y = RATIO_C*(expf(v.y-d)+EPS_K);
    v.z = RATIO_C*(expf(v.z-d)+EPS_K); v.w = RATIO_C*(expf(v.w-d)+EPS_K);
    p[i4] = v;
}

// ---------------- k_sum over S (two stage) ----------------
__global__ void ksum_part_kernel(const float* __restrict__ kp)
{
    const int bh = blockIdx.x, split = blockIdx.y, m = threadIdx.x;
    const float* p = kp + ((long long)bh*Ss + (long long)split*512)*Mm + m;
    float s = 0.f;
    for (int i=0;i<512;i++) s += p[(long long)i*Mm];
    g_ksum_part[(bh*8+split)*Mm + m] = s;
}
__global__ void ksum_red_kernel()
{
    const int bh = blockIdx.x, m = threadIdx.x;
    float s = 0.f;
    #pragma unroll
    for (int i=0;i<8;i++) s += g_ksum_part[(bh*8+i)*Mm + m];
    g_ksum[bh*Mm + m] = s;
}

// ---------------- ctx^T[bh][dh][m] = sum_s kp[bh,s,m]*v[bh,s,dh] ----------------
__global__ void __launch_bounds__(256)
ctx_kernel(const float* __restrict__ kp, const float* __restrict__ vh, float* __restrict__ ctxT)
{
    const int z = blockIdx.z;             // bh
    const int mtile = blockIdx.y;         // 4 tiles of 64 m
    __shared__ float As[16][64];          // kp [s][m]
    __shared__ float Bs[16][64];          // v  [s][dh]
    const int tid = threadIdx.x;
    const int tx = tid % 16;              // dh/4
    const int ty = tid / 16;              // m/4
    const int r = tid / 16, c = tid % 16; // loader map

    const float* kpb = kp + (long long)z*Ss*Mm + mtile*64;
    const float* vhb = vh + (long long)z*Ss*DhD;

    float acc[4][4];
    #pragma unroll
    for (int i=0;i<4;i++)
        #pragma unroll
        for (int j=0;j<4;j++) acc[i][j]=0.f;

    for (int s0=0; s0<Ss; s0+=16){
        *reinterpret_cast<float4*>(&As[r][c*4]) =
            *reinterpret_cast<const float4*>(kpb + (long long)(s0+r)*Mm + c*4);
        *reinterpret_cast<float4*>(&Bs[r][c*4]) =
            *reinterpret_cast<const float4*>(vhb + (long long)(s0+r)*DhD + c*4);
        __syncthreads();
        #pragma unroll
        for (int k=0;k<16;k++){
            float4 a4 = *reinterpret_cast<const float4*>(&As[k][ty*4]);
            float4 b4 = *reinterpret_cast<const float4*>(&Bs[k][tx*4]);
            float ar[4]={a4.x,a4.y,a4.z,a4.w}, br[4]={b4.x,b4.y,b4.z,b4.w};
            #pragma unroll
            for (int i=0;i<4;i++)
                #pragma unroll
                for (int j=0;j<4;j++) acc[i][j] = fmaf(ar[i], br[j], acc[i][j]);
        }
        __syncthreads();
    }
    #pragma unroll
    for (int i=0;i<4;i++)
        #pragma unroll
        for (int j=0;j<4;j++){
            int m_  = mtile*64 + ty*4 + i;
            int dh_ = tx*4 + j;
            ctxT[(long long)z*DhD*Mm + (long long)dh_*Mm + m_] = acc[i][j];
        }
}

// ---------------- d_inv (warp per row) ----------------
__global__ void dinv_kernel(const float* __restrict__ qp, float* __restrict__ dinv)
{
    const int lane = threadIdx.x & 31, w = threadIdx.x >> 5;
    const long long row = (long long)blockIdx.x*8 + w;
    const int bh = (int)(row >> 12);
    const float4* p  = reinterpret_cast<const float4*>(qp + row*Mm);
    const float4* ks = reinterpret_cast<const float4*>(g_ksum + (long long)bh*Mm);
    float4 a = p[lane], b = p[lane+32], ka = ks[lane], kb = ks[lane+32];
    float s = a.x*ka.x + a.y*ka.y + a.z*ka.z + a.w*ka.w
            + b.x*kb.x + b.y*kb.y + b.z*kb.z + b.w*kb.w;
    #pragma unroll
    for (int o=16;o;o>>=1) s += __shfl_xor_sync(0xffffffffu,s,o);
    if (lane==0) dinv[row] = 1.0f/s;
}

// ---------------- transpose attn [b,h,s,dh] -> [b,s,D] ----------------
__global__ void trans_kernel(const float* __restrict__ attnh, float* __restrict__ out)
{
    const long long i4 = (long long)blockIdx.x*blockDim.x + threadIdx.x;
    const long long idx = i4*4;
    const int row = (int)(idx / Dd);
    const int col = (int)(idx % Dd);
    const int b_ = row>>12, s_ = row&4095, h_ = col>>6, dh_ = col&63;
    *reinterpret_cast<float4*>(out + idx) =
        *reinterpret_cast<const float4*>(attnh + ((((long long)(b_*Hh+h_))<<12)+s_)*DhD + dh_);
}

// ---------------- host ----------------
extern "C" void kernel_launch(void* const* d_in, const int* in_sizes, int n_in,
                              void* d_out, int out_size)
{
    const float* x    = (const float*)d_in[0];
    const float* proj = (const float*)d_in[1];
    const float* wq   = (const float*)d_in[2];
    const float* bq   = (const float*)d_in[3];
    const float* wk   = (const float*)d_in[4];
    const float* bk   = (const float*)d_in[5];
    const float* wv   = (const float*)d_in[6];
    const float* bv   = (const float*)d_in[7];
    const float* wo   = (const float*)d_in[8];
    const float* bo   = (const float*)d_in[9];
    const float* ln1g = (const float*)d_in[10];
    const float* ln1b = (const float*)d_in[11];
    const float* ln2g = (const float*)d_in[12];
    const float* ln2b = (const float*)d_in[13];
    const float* w1   = (const float*)d_in[14];
    const float* b1   = (const float*)d_in[15];
    const float* w2   = (const float*)d_in[16];
    const float* b2   = (const float*)d_in[17];
    float* out = (float*)d_out;

    void *p;
    float *h1, *qh, *kh, *vh, *qp, *kp, *dq, *dk, *ctxT, *dinv, *attnh, *attn, *x2;
    cudaGetSymbolAddress(&p, g_h1);    h1    = (float*)p;
    cudaGetSymbolAddress(&p, g_qh);    qh    = (float*)p;
    cudaGetSymbolAddress(&p, g_kh);    kh    = (float*)p;
    cudaGetSymbolAddress(&p, g_vh);    vh    = (float*)p;
    cudaGetSymbolAddress(&p, g_big);   qp    = (float*)p;
    cudaGetSymbolAddress(&p, g_kp);    kp    = (float*)p;
    cudaGetSymbolAddress(&p, g_diagq); dq    = (float*)p;
    cudaGetSymbolAddress(&p, g_diagk); dk    = (float*)p;
    cudaGetSymbolAddress(&p, g_ctxT);  ctxT  = (float*)p;
    cudaGetSymbolAddress(&p, g_dinv);  dinv  = (float*)p;
    cudaGetSymbolAddress(&p, g_attnh); attnh = (float*)p;
    cudaGetSymbolAddress(&p, g_attn);  attn  = (float*)p;
    cudaGetSymbolAddress(&p, g_x2);    x2    = (float*)p;
    float* mid = qp; // alias: qp dead before FFN mid is written

    // 1. LN1
    ln_kernel<<<NROWS, 256>>>(x, ln1g, ln1b, h1);

    // 2-4. QKV projections, stored directly in [b,h,s,dh]
    gemm_mma<128,128,EPI_QKV><<<dim3(6,128,1),256>>>(
        h1,Dd,0, wq,Dd,0, qh,DhD,0, NROWS,Dd,Dd, bq,nullptr,nullptr,0.f);
    gemm_mma<128,128,EPI_QKV><<<dim3(6,128,1),256>>>(
        h1,Dd,0, wk,Dd,0, kh,DhD,0, NROWS,Dd,Dd, bk,nullptr,nullptr,0.f);
    gemm_mma<128,128,EPI_QKV><<<dim3(6,128,1),256>>>(
        h1,Dd,0, wv,Dd,0, vh,DhD,0, NROWS,Dd,Dd, bv,nullptr,nullptr,0.f);

    // 5. diag terms
    diag_kernel<<<NHR/8, 256>>>(qh, dq);
    diag_kernel<<<NHR/8, 256>>>(kh, dk);

    // 6-7. dd = norm * (q/k @ proj^T)   K=64
    gemm_mma<128,128,EPI_SCALE><<<dim3(2,NHR/128,1),256>>>(
        qh,DhD,0, proj,DhD,0, qp,Mm,0, NHR,Mm,DhD, nullptr,nullptr,nullptr,NORM_C);
    gemm_mma<128,128,EPI_SCALE><<<dim3(2,NHR/128,1),256>>>(
        kh,DhD,0, proj,DhD,0, kp,Mm,0, NHR,Mm,DhD, nullptr,nullptr,nullptr,NORM_C);

    // 8. global max of dd_k
    max1_kernel<<<1024, 256>>>(kp);
    max2_kernel<<<1, 256>>>();

    // 9-10. FAVOR+ exp features (in place)
    expq_kernel<<<NHR/8, 256>>>(qp, dq);
    expk_kernel<<<(NHR*(Mm/4))/256, 256>>>(kp, dk);

    // 11. k_sum
    ksum_part_kernel<<<dim3(NBH,8,1), 256>>>(kp);
    ksum_red_kernel<<<NBH, 256>>>();

    // 12. ctx^T = (kp^T @ v)^T
    ctx_kernel<<<dim3(1,4,NBH), 256>>>(kp, vh, ctxT);

    // 13. d_inv
    dinv_kernel<<<NHR/8, 256>>>(qp, dinv);

    // 14. attn_h = d_inv * (qp @ ctx), batched over bh   K=256
    gemm_mma<128,64,EPI_ROWSCALE><<<dim3(1,Ss/128,NBH),128>>>(
        qp,Mm,(long long)Ss*Mm, ctxT,Mm,(long long)DhD*Mm, attnh,DhD,(long long)Ss*DhD,
        Ss,DhD,Mm, nullptr,nullptr,dinv,0.f);

    // 15. transpose to [b,s,D]
    trans_kernel<<<(NROWS*Dd/4)/256, 256>>>(attnh, attn);

    // 16. x2 = x + attn @ wo^T + bo
    gemm_mma<128,128,EPI_BIAS_RES><<<dim3(6,128,1),256>>>(
        attn,Dd,0, wo,Dd,0, x2,Dd,0, NROWS,Dd,Dd, bo,x,nullptr,0.f);

    // 17. LN2
    ln_kernel<<<NROWS, 256>>>(x2, ln2g, ln2b, h1);

    // 18. mid = gelu(h1 @ w1^T + b1)
    gemm_mma<128,128,EPI_BIAS_GELU><<<dim3(FFH/128,128,1),256>>>(
        h1,Dd,0, w1,Dd,0, mid,FFH,0, NROWS,FFH,Dd, b1,nullptr,nullptr,0.f);

    // 19. out = x2 + mid @ w2^T + b2
    gemm_mma<128,128,EPI_BIAS_RES><<<dim3(6,128,1),256>>>(
        mid,FFH,0, w2,FFH,0, out,Dd,0, NROWS,Dd,FFH, b2,x2,nullptr,0.f);
}

// round 5
// speedup vs baseline: 3.0870x; 1.2590x over previous
#include <cuda_runtime.h>
#include <cuda_bf16.h>
#include <math.h>
#include <stdint.h>

// ---------------- problem constants ----------------
#define Bb   4
#define Ss   4096
#define Dd   768
#define Hh   12
#define Mm   256
#define DhD  64
#define NROWS (Bb*Ss)        // 16384
#define NBH   (Bb*Hh)        // 48
#define NHR   (NBH*Ss)       // 196608
#define FFH   (4*Dd)         // 3072

#define NORM_C   0.35355339059327373f   // 64^-0.25
#define RATIO_C  0.0625f                // 256^-0.5
#define DIAG_C   0.0625f                // 0.5 * norm^2 = 0.5/8
#define EPS_K    1e-4f
#define LN_EPS   1e-5f

// ---------------- scratch (device globals; allocation-free) ----------------
__device__ float g_h1[NROWS*Dd];         // ln1 out, reused as ln2 out
__device__ float g_qh[NHR*DhD];          // q in [b,h,s,dh]
__device__ float g_kh[NHR*DhD];
__device__ float g_vh[NHR*DhD];
__device__ float g_big[(size_t)NHR*Mm];  // qp raw/exp, later FFN mid
__device__ float g_kp [(size_t)NHR*Mm];  // kp raw/exp
__device__ float g_diagq[NHR];
__device__ float g_diagk[NHR];
__device__ float g_ksum_part[NBH*8*Mm];
__device__ float g_ksum[NBH*Mm];
__device__ float g_ctxT[NBH*DhD*Mm];     // ctx transposed: [bh][dh][m]
__device__ float g_dinv[NHR];
__device__ float g_attnh[NHR*DhD];       // attn in [b,h,s,dh]
__device__ float g_attn[NROWS*Dd];       // attn in [b,s,D]
__device__ float g_x2[NROWS*Dd];         // residual after attention
__device__ float g_maxpart[1024];
__device__ float g_gmax;

// ---------------- epilogue modes ----------------
enum { EPI_BIAS=0, EPI_BIAS_RES=1, EPI_BIAS_GELU=2, EPI_SCALE=3, EPI_ROWSCALE=4, EPI_QKV=5 };

__device__ __forceinline__ uint32_t smem_u32(const void* p){
    uint32_t a;
    asm("{ .reg .u64 t; cvta.to.shared.u64 t, %1; cvt.u32.u64 %0, t; }" : "=r"(a) : "l"(p));
    return a;
}
__device__ __forceinline__ void cpa16(uint32_t smem_dst, const void* gsrc){
    asm volatile("cp.async.cg.shared.global [%0], [%1], 16;" :: "r"(smem_dst), "l"(gsrc));
}
#define CP_COMMIT() asm volatile("cp.async.commit_group;" ::: "memory")
#define CP_WAIT0()  asm volatile("cp.async.wait_group 0;" ::: "memory")

__device__ __forceinline__ void mma_tf32(float* d, const uint32_t* a, const uint32_t* b){
    asm volatile("mma.sync.aligned.m16n8k8.row.col.f32.tf32.tf32.f32 "
        "{%0,%1,%2,%3}, {%4,%5,%6,%7}, {%8,%9}, {%0,%1,%2,%3};"
        : "+f"(d[0]),"+f"(d[1]),"+f"(d[2]),"+f"(d[3])
        : "r"(a[0]),"r"(a[1]),"r"(a[2]),"r"(a[3]), "r"(b[0]),"r"(b[1]));
}

// ================= tensor-core TF32 NT GEMM via mma.sync + cp.async =================
// C[m,n] = sum_k A[m,k]*B[n,k] (+ epilogue). BK=32, warp tile 64x32, 2-stage pipeline.
// Raw fp32 bits fed to mma.tf32 (HW truncates to tf32).
template<int BM,int BN,int EPI>
__global__ void __launch_bounds__(32*(BM/64)*(BN/32), 2)
gemm_mma(const float* __restrict__ A, int lda, long long strA,
         const float* __restrict__ B, int ldb, long long strB,
         float* __restrict__ C, int ldc, long long strC,
         int M, int N, int K,
         const float* __restrict__ bias,
         const float* __restrict__ res,
         const float* __restrict__ rowscale,
         float alpha)
{
    constexpr int WY = BM/64, WX = BN/32, THREADS = 32*WY*WX;
    constexpr int LDK = 36;                     // 32 + 4 pad (word stride)
    constexpr int AW  = BM*LDK, BW = BN*LDK;    // words per stage
    constexpr int STW = AW + BW;                // stage words
    constexpr int ALD = (BM*8)/THREADS;         // float4 loads per thread (A)
    constexpr int BLD = (BN*8)/THREADS;

    extern __shared__ uint32_t sh[];
    const uint32_t smb = smem_u32(sh);

    const int z = blockIdx.z;
    A += (long long)z*strA;  B += (long long)z*strB;  C += (long long)z*strC;

    const int brow = blockIdx.y*BM;
    const int bcol = blockIdx.x*BN;
    const int tid  = threadIdx.x;
    const int wid  = tid >> 5;
    const int lane = tid & 31;
    const int wx   = wid % WX, wy = wid / WX;
    const int warp_m = wy*64, warp_n = wx*32;
    const int g = lane >> 2, t = lane & 3;

    float acc[4][4][4];
    #pragma unroll
    for (int i=0;i<4;i++)
        #pragma unroll
        for (int j=0;j<4;j++)
            #pragma unroll
            for (int u=0;u<4;u++) acc[i][j][u]=0.f;

    const int nc = K >> 5;

    #define ISSUE_CHUNK(chunk) do{                                            \
        const uint32_t baseA_ = smb + (uint32_t)(((chunk)&1)*STW)*4u;          \
        const uint32_t baseB_ = baseA_ + (uint32_t)AW*4u;                      \
        const float* Ap_ = A + (long long)brow*lda + (chunk)*32;               \
        const float* Bp_ = B + (long long)bcol*ldb + (chunk)*32;               \
        _Pragma("unroll")                                                      \
        for (int l=0;l<ALD;l++){                                               \
            const int idx = tid + l*THREADS, r = idx>>3, c4 = idx&7;           \
            cpa16(baseA_ + (uint32_t)(r*LDK + c4*4)*4u,                        \
                  Ap_ + (long long)r*lda + c4*4);                              \
        }                                                                      \
        _Pragma("unroll")                                                      \
        for (int l=0;l<BLD;l++){                                               \
            const int idx = tid + l*THREADS, r = idx>>3, c4 = idx&7;           \
            cpa16(baseB_ + (uint32_t)(r*LDK + c4*4)*4u,                        \
                  Bp_ + (long long)r*ldb + c4*4);                              \
        }                                                                      \
    }while(0)

    ISSUE_CHUNK(0);
    CP_COMMIT();

    for (int i=0; i<nc; ++i){
        CP_WAIT0();
        __syncthreads();
        if (i+1 < nc){ ISSUE_CHUNK(i+1); CP_COMMIT(); }

        const uint32_t* Asb = sh + (i&1)*STW;
        const uint32_t* Bsb = Asb + AW;

        #pragma unroll
        for (int kk=0; kk<4; ++kk){
            uint32_t af[4][4], bf[4][2];
            #pragma unroll
            for (int mt=0; mt<4; ++mt){
                const int m0 = warp_m + mt*16;
                af[mt][0] = Asb[(m0+g  )*LDK + kk*8 + t    ];
                af[mt][1] = Asb[(m0+g+8)*LDK + kk*8 + t    ];
                af[mt][2] = Asb[(m0+g  )*LDK + kk*8 + t + 4];
                af[mt][3] = Asb[(m0+g+8)*LDK + kk*8 + t + 4];
            }
            #pragma unroll
            for (int nt=0; nt<4; ++nt){
                const int n0 = warp_n + nt*8;
                bf[nt][0] = Bsb[(n0+g)*LDK + kk*8 + t    ];
                bf[nt][1] = Bsb[(n0+g)*LDK + kk*8 + t + 4];
            }
            #pragma unroll
            for (int mt=0; mt<4; ++mt)
                #pragma unroll
                for (int nt=0; nt<4; ++nt)
                    mma_tf32(acc[mt][nt], af[mt], bf[nt]);
        }
    }
    #undef ISSUE_CHUNK

    // -------- epilogue --------
    #pragma unroll
    for (int mt=0; mt<4; ++mt){
        const int r0 = brow + warp_m + mt*16 + g;
        const int r1 = r0 + 8;
        float rs0 = 1.f, rs1 = 1.f;
        if (EPI==EPI_ROWSCALE){
            rs0 = rowscale[(long long)z*M + r0];
            rs1 = rowscale[(long long)z*M + r1];
        }
        #pragma unroll
        for (int nt=0; nt<4; ++nt){
            const int c0 = bcol + warp_n + nt*8 + 2*t;
            float v00 = acc[mt][nt][0], v01 = acc[mt][nt][1];
            float v10 = acc[mt][nt][2], v11 = acc[mt][nt][3];
            if (EPI==EPI_BIAS || EPI==EPI_BIAS_RES || EPI==EPI_BIAS_GELU || EPI==EPI_QKV){
                const float b0 = bias[c0], b1 = bias[c0+1];
                v00 += b0; v01 += b1; v10 += b0; v11 += b1;
            }
            if (EPI==EPI_BIAS_RES){
                v00 += res[(long long)r0*ldc + c0];   v01 += res[(long long)r0*ldc + c0+1];
                v10 += res[(long long)r1*ldc + c0];   v11 += res[(long long)r1*ldc + c0+1];
            }
            if (EPI==EPI_BIAS_GELU){
                v00 = 0.5f*v00*(1.0f+erff(v00*0.70710678118654752f));
                v01 = 0.5f*v01*(1.0f+erff(v01*0.70710678118654752f));
                v10 = 0.5f*v10*(1.0f+erff(v10*0.70710678118654752f));
                v11 = 0.5f*v11*(1.0f+erff(v11*0.70710678118654752f));
            }
            if (EPI==EPI_SCALE){ v00*=alpha; v01*=alpha; v10*=alpha; v11*=alpha; }
            if (EPI==EPI_ROWSCALE){ v00*=rs0; v01*=rs0; v10*=rs1; v11*=rs1; }

            float2 o0; o0.x=v00; o0.y=v01;
            float2 o1; o1.x=v10; o1.y=v11;
            if (EPI==EPI_QKV){
                const int h_ = c0>>6, dh_ = c0&63;
                const int b0_ = r0>>12, s0_ = r0&4095;
                const int b1_ = r1>>12, s1_ = r1&4095;
                *reinterpret_cast<float2*>(C + ((((long long)(b0_*Hh+h_))<<12)+s0_)*DhD + dh_) = o0;
                *reinterpret_cast<float2*>(C + ((((long long)(b1_*Hh+h_))<<12)+s1_)*DhD + dh_) = o1;
            } else {
                *reinterpret_cast<float2*>(C + (long long)r0*ldc + c0) = o0;
                *reinterpret_cast<float2*>(C + (long long)r1*ldc + c0) = o1;
            }
        }
    }
}

#define SMEM_G128x128 (2*(128*36+128*36)*4)   // 73728
#define SMEM_G128x64  (2*(128*36+64*36)*4)    // 55296

// ---------------- LayerNorm (row = 768, 256 threads/block) ----------------
__global__ void ln_kernel(const float* __restrict__ x, const float* __restrict__ g,
                          const float* __restrict__ b, float* __restrict__ out)
{
    const int row = blockIdx.x;
    const float* xr = x + (long long)row*Dd;
    float v[3]; float s=0.f, ss=0.f;
    #pragma unroll
    for (int i=0;i<3;i++){ v[i]=xr[threadIdx.x + i*256]; s+=v[i]; ss+=v[i]*v[i]; }
    #pragma unroll
    for (int o=16;o;o>>=1){ s+=__shfl_xor_sync(0xffffffffu,s,o); ss+=__shfl_xor_sync(0xffffffffu,ss,o); }
    __shared__ float rs_[8], rss_[8];
    const int lane = threadIdx.x & 31, w = threadIdx.x >> 5;
    if (lane==0){ rs_[w]=s; rss_[w]=ss; }
    __syncthreads();
    s=0.f; ss=0.f;
    #pragma unroll
    for (int i=0;i<8;i++){ s+=rs_[i]; ss+=rss_[i]; }
    const float mu  = s*(1.0f/Dd);
    const float var = ss*(1.0f/Dd) - mu*mu;
    const float rstd = rsqrtf(var + LN_EPS);
    float* outr = out + (long long)row*Dd;
    #pragma unroll
    for (int i=0;i<3;i++){
        int c = threadIdx.x + i*256;
        outr[c] = (v[i]-mu)*rstd*g[c] + b[c];
    }
}

// ---------------- diag: 0.0625 * sum(q^2) over head dim (warp per row) ----------------
__global__ void diag_kernel(const float* __restrict__ src, float* __restrict__ dst)
{
    const int lane = threadIdx.x & 31, w = threadIdx.x >> 5;
    const long long row = (long long)blockIdx.x*8 + w;
    float2 v = reinterpret_cast<const float2*>(src + row*DhD)[lane];
    float s = v.x*v.x + v.y*v.y;
    #pragma unroll
    for (int o=16;o;o>>=1) s += __shfl_xor_sync(0xffffffffu,s,o);
    if (lane==0) dst[row] = DIAG_C * s;
}

// ---------------- q features: row max + exp, in place (warp per row of 256) ----------------
__global__ void expq_kernel(float* __restrict__ qp, const float* __restrict__ diag)
{
    const int lane = threadIdx.x & 31, w = threadIdx.x >> 5;
    const long long row = (long long)blockIdx.x*8 + w;
    float4* p = reinterpret_cast<float4*>(qp + row*Mm);
    float4 a = p[lane], c = p[lane+32];
    float mx = fmaxf(fmaxf(fmaxf(a.x,a.y),fmaxf(a.z,a.w)),
                     fmaxf(fmaxf(c.x,c.y),fmaxf(c.z,c.w)));
    #pragma unroll
    for (int o=16;o;o>>=1) mx = fmaxf(mx, __shfl_xor_sync(0xffffffffu,mx,o));
    const float d = diag[row] + mx;
    a.x = RATIO_C*(expf(a.x-d)+EPS_K); a.y = RATIO_C*(expf(a.y-d)+EPS_K);
    a.z = RATIO_C*(expf(a.z-d)+EPS_K); a.w = RATIO_C*(expf(a.w-d)+EPS_K);
    c.x = RATIO_C*(expf(c.x-d)+EPS_K); c.y = RATIO_C*(expf(c.y-d)+EPS_K);
    c.z = RATIO_C*(expf(c.z-d)+EPS_K); c.w = RATIO_C*(expf(c.w-d)+EPS_K);
    p[lane]=a; p[lane+32]=c;
}

// ---------------- global max over kp raw ----------------
__global__ void max1_kernel(const float* __restrict__ kp)
{
    const long long n = (long long)NHR*Mm;
    float m = -3.402823466e38f;
    for (long long i = (long long)blockIdx.x*blockDim.x + threadIdx.x; i<n;
         i += (long long)gridDim.x*blockDim.x)
        m = fmaxf(m, kp[i]);
    #pragma unroll
    for (int o=16;o;o>>=1) m = fmaxf(m, __shfl_xor_sync(0xffffffffu,m,o));
    __shared__ float sm[8];
    const int lane = threadIdx.x & 31, w = threadIdx.x >> 5;
    if (lane==0) sm[w]=m;
    __syncthreads();
    if (threadIdx.x==0){
        float tt = sm[0];
        #pragma unroll
        for (int i=1;i<8;i++) tt = fmaxf(tt, sm[i]);
        g_maxpart[blockIdx.x] = tt;
    }
}
__global__ void max2_kernel()
{
    float m = -3.402823466e38f;
    for (int i=threadIdx.x; i<1024; i+=256) m = fmaxf(m, g_maxpart[i]);
    #pragma unroll
    for (int o=16;o;o>>=1) m = fmaxf(m, __shfl_xor_sync(0xffffffffu,m,o));
    __shared__ float sm[8];
    const int lane = threadIdx.x & 31, w = threadIdx.x >> 5;
    if (lane==0) sm[w]=m;
    __syncthreads();
    if (threadIdx.x==0){
        float tt = sm[0];
        #pragma unroll
        for (int i=1;i<8;i++) tt = fmaxf(tt, sm[i]);
        g_gmax = tt;
    }
}

// ---------------- k features: global max + exp, in place (elementwise) ----------------
__global__ void expk_kernel(float* __restrict__ kp, const float* __restrict__ diag)
{
    const long long i4 = (long long)blockIdx.x*blockDim.x + threadIdx.x; // float4 idx
    const float gm = g_gmax;
    const long long row = i4 >> 6;      // (i4*4)/256
    const float d = diag[row] + gm;
    float4* p = reinterpret_cast<float4*>(kp);
    float4 v = p[i4];
    v.x = RATIO_C*(expf(v.x-d)+EPS_K); v.y = RATIO_C*(expf(v.y-d)+EPS_K);
    v.z = RATIO_C*(expf(v.z-d)+EPS_K); v.w = RATIO_C*(expf(v.w-d)+EPS_K);
    p[i4] = v;
}

// ---------------- k_sum over S (two stage) ----------------
__global__ void ksum_part_kernel(const float* __restrict__ kp)
{
    const int bh = blockIdx.x, split = blockIdx.y, m = threadIdx.x;
    const float* p = kp + ((long long)bh*Ss + (long long)split*512)*Mm + m;
    float s = 0.f;
    for (int i=0;i<512;i++) s += p[(long long)i*Mm];
    g_ksum_part[(bh*8+split)*Mm + m] = s;
}
__global__ void ksum_red_kernel()
{
    const int bh = blockIdx.x, m = threadIdx.x;
    float s = 0.f;
    #pragma unroll
    for (int i=0;i<8;i++) s += g_ksum_part[(bh*8+i)*Mm + m];
    g_ksum[bh*Mm + m] = s;
}

// ---------------- ctx^T[bh][dh][m] = sum_s kp[bh,s,m]*v[bh,s,dh] ----------------
__global__ void __launch_bounds__(256)
ctx_kernel(const float* __restrict__ kp, const float* __restrict__ vh, float* __restrict__ ctxT)
{
    const int z = blockIdx.z;             // bh
    const int mtile = blockIdx.y;         // 4 tiles of 64 m
    __shared__ float As[32][64];          // kp [s][m]
    __shared__ float Bs[32][64];          // v  [s][dh]
    const int tid = threadIdx.x;
    const int tx = tid % 16;              // dh/4
    const int ty = tid / 16;              // m/4

    const float* kpb = kp + (long long)z*Ss*Mm + mtile*64;
    const float* vhb = vh + (long long)z*Ss*DhD;

    float acc[4][4];
    #pragma unroll
    for (int i=0;i<4;i++)
        #pragma unroll
        for (int j=0;j<4;j++) acc[i][j]=0.f;

    for (int s0=0; s0<Ss; s0+=32){
        #pragma unroll
        for (int l=0;l<2;l++){
            const int idx = tid + l*256;
            const int r = idx >> 4, c = idx & 15;
            *reinterpret_cast<float4*>(&As[r][c*4]) =
                *reinterpret_cast<const float4*>(kpb + (long long)(s0+r)*Mm + c*4);
            *reinterpret_cast<float4*>(&Bs[r][c*4]) =
                *reinterpret_cast<const float4*>(vhb + (long long)(s0+r)*DhD + c*4);
        }
        __syncthreads();
        #pragma unroll
        for (int k=0;k<32;k++){
            float4 a4 = *reinterpret_cast<const float4*>(&As[k][ty*4]);
            float4 b4 = *reinterpret_cast<const float4*>(&Bs[k][tx*4]);
            float ar[4]={a4.x,a4.y,a4.z,a4.w}, br[4]={b4.x,b4.y,b4.z,b4.w};
            #pragma unroll
            for (int i=0;i<4;i++)
                #pragma unroll
                for (int j=0;j<4;j++) acc[i][j] = fmaf(ar[i], br[j], acc[i][j]);
        }
        __syncthreads();
    }
    #pragma unroll
    for (int i=0;i<4;i++)
        #pragma unroll
        for (int j=0;j<4;j++){
            int m_  = mtile*64 + ty*4 + i;
            int dh_ = tx*4 + j;
            ctxT[(long long)z*DhD*Mm + (long long)dh_*Mm + m_] = acc[i][j];
        }
}

// ---------------- d_inv (warp per row) ----------------
__global__ void dinv_kernel(const float* __restrict__ qp, float* __restrict__ dinv)
{
    const int lane = threadIdx.x & 31, w = threadIdx.x >> 5;
    const long long row = (long long)blockIdx.x*8 + w;
    const int bh = (int)(row >> 12);
    const float4* p  = reinterpret_cast<const float4*>(qp + row*Mm);
    const float4* ks = reinterpret_cast<const float4*>(g_ksum + (long long)bh*Mm);
    float4 a = p[lane], b = p[lane+32], ka = ks[lane], kb = ks[lane+32];
    float s = a.x*ka.x + a.y*ka.y + a.z*ka.z + a.w*ka.w
            + b.x*kb.x + b.y*kb.y + b.z*kb.z + b.w*kb.w;
    #pragma unroll
    for (int o=16;o;o>>=1) s += __shfl_xor_sync(0xffffffffu,s,o);
    if (lane==0) dinv[row] = 1.0f/s;
}

// ---------------- transpose attn [b,h,s,dh] -> [b,s,D] ----------------
__global__ void trans_kernel(const float* __restrict__ attnh, float* __restrict__ out)
{
    const long long i4 = (long long)blockIdx.x*blockDim.x + threadIdx.x;
    const long long idx = i4*4;
    const int row = (int)(idx / Dd);
    const int col = (int)(idx % Dd);
    const int b_ = row>>12, s_ = row&4095, h_ = col>>6, dh_ = col&63;
    *reinterpret_cast<float4*>(out + idx) =
        *reinterpret_cast<const float4*>(attnh + ((((long long)(b_*Hh+h_))<<12)+s_)*DhD + dh_);
}

// ---------------- host ----------------
extern "C" void kernel_launch(void* const* d_in, const int* in_sizes, int n_in,
                              void* d_out, int out_size)
{
    const float* x    = (const float*)d_in[0];
    const float* proj = (const float*)d_in[1];
    const float* wq   = (const float*)d_in[2];
    const float* bq   = (const float*)d_in[3];
    const float* wk   = (const float*)d_in[4];
    const float* bk   = (const float*)d_in[5];
    const float* wv   = (const float*)d_in[6];
    const float* bv   = (const float*)d_in[7];
    const float* wo   = (const float*)d_in[8];
    const float* bo   = (const float*)d_in[9];
    const float* ln1g = (const float*)d_in[10];
    const float* ln1b = (const float*)d_in[11];
    const float* ln2g = (const float*)d_in[12];
    const float* ln2b = (const float*)d_in[13];
    const float* w1   = (const float*)d_in[14];
    const float* b1   = (const float*)d_in[15];
    const float* w2   = (const float*)d_in[16];
    const float* b2   = (const float*)d_in[17];
    float* out = (float*)d_out;

    void *p;
    float *h1, *qh, *kh, *vh, *qp, *kp, *dq, *dk, *ctxT, *dinv, *attnh, *attn, *x2;
    cudaGetSymbolAddress(&p, g_h1);    h1    = (float*)p;
    cudaGetSymbolAddress(&p, g_qh);    qh    = (float*)p;
    cudaGetSymbolAddress(&p, g_kh);    kh    = (float*)p;
    cudaGetSymbolAddress(&p, g_vh);    vh    = (float*)p;
    cudaGetSymbolAddress(&p, g_big);   qp    = (float*)p;
    cudaGetSymbolAddress(&p, g_kp);    kp    = (float*)p;
    cudaGetSymbolAddress(&p, g_diagq); dq    = (float*)p;
    cudaGetSymbolAddress(&p, g_diagk); dk    = (float*)p;
    cudaGetSymbolAddress(&p, g_ctxT);  ctxT  = (float*)p;
    cudaGetSymbolAddress(&p, g_dinv);  dinv  = (float*)p;
    cudaGetSymbolAddress(&p, g_attnh); attnh = (float*)p;
    cudaGetSymbolAddress(&p, g_attn);  attn  = (float*)p;
    cudaGetSymbolAddress(&p, g_x2);    x2    = (float*)p;
    float* mid = qp; // alias: qp dead before FFN mid is written

    cudaFuncSetAttribute(gemm_mma<128,128,EPI_QKV>,      cudaFuncAttributeMaxDynamicSharedMemorySize, SMEM_G128x128);
    cudaFuncSetAttribute(gemm_mma<128,128,EPI_SCALE>,    cudaFuncAttributeMaxDynamicSharedMemorySize, SMEM_G128x128);
    cudaFuncSetAttribute(gemm_mma<128,128,EPI_BIAS_RES>, cudaFuncAttributeMaxDynamicSharedMemorySize, SMEM_G128x128);
    cudaFuncSetAttribute(gemm_mma<128,128,EPI_BIAS_GELU>,cudaFuncAttributeMaxDynamicSharedMemorySize, SMEM_G128x128);
    cudaFuncSetAttribute(gemm_mma<128,64,EPI_ROWSCALE>,  cudaFuncAttributeMaxDynamicSharedMemorySize, SMEM_G128x64);

    // 1. LN1
    ln_kernel<<<NROWS, 256>>>(x, ln1g, ln1b, h1);

    // 2-4. QKV projections, stored directly in [b,h,s,dh]
    gemm_mma<128,128,EPI_QKV><<<dim3(6,128,1),256,SMEM_G128x128>>>(
        h1,Dd,0, wq,Dd,0, qh,DhD,0, NROWS,Dd,Dd, bq,nullptr,nullptr,0.f);
    gemm_mma<128,128,EPI_QKV><<<dim3(6,128,1),256,SMEM_G128x128>>>(
        h1,Dd,0, wk,Dd,0, kh,DhD,0, NROWS,Dd,Dd, bk,nullptr,nullptr,0.f);
    gemm_mma<128,128,EPI_QKV><<<dim3(6,128,1),256,SMEM_G128x128>>>(
        h1,Dd,0, wv,Dd,0, vh,DhD,0, NROWS,Dd,Dd, bv,nullptr,nullptr,0.f);

    // 5. diag terms
    diag_kernel<<<NHR/8, 256>>>(qh, dq);
    diag_kernel<<<NHR/8, 256>>>(kh, dk);

    // 6-7. dd = norm * (q/k @ proj^T)   K=64
    gemm_mma<128,128,EPI_SCALE><<<dim3(2,NHR/128,1),256,SMEM_G128x128>>>(
        qh,DhD,0, proj,DhD,0, qp,Mm,0, NHR,Mm,DhD, nullptr,nullptr,nullptr,NORM_C);
    gemm_mma<128,128,EPI_SCALE><<<dim3(2,NHR/128,1),256,SMEM_G128x128>>>(
        kh,DhD,0, proj,DhD,0, kp,Mm,0, NHR,Mm,DhD, nullptr,nullptr,nullptr,NORM_C);

    // 8. global max of dd_k
    max1_kernel<<<1024, 256>>>(kp);
    max2_kernel<<<1, 256>>>();

    // 9-10. FAVOR+ exp features (in place)
    expq_kernel<<<NHR/8, 256>>>(qp, dq);
    expk_kernel<<<(NHR*(Mm/4))/256, 256>>>(kp, dk);

    // 11. k_sum
    ksum_part_kernel<<<dim3(NBH,8,1), 256>>>(kp);
    ksum_red_kernel<<<NBH, 256>>>();

    // 12. ctx^T = (kp^T @ v)^T
    ctx_kernel<<<dim3(1,4,NBH), 256>>>(kp, vh, ctxT);

    // 13. d_inv
    dinv_kernel<<<NHR/8, 256>>>(qp, dinv);

    // 14. attn_h = d_inv * (qp @ ctx), batched over bh   K=256
    gemm_mma<128,64,EPI_ROWSCALE><<<dim3(1,Ss/128,NBH),128,SMEM_G128x64>>>(
        qp,Mm,(long long)Ss*Mm, ctxT,Mm,(long long)DhD*Mm, attnh,DhD,(long long)Ss*DhD,
        Ss,DhD,Mm, nullptr,nullptr,dinv,0.f);

    // 15. transpose to [b,s,D]
    trans_kernel<<<(NROWS*Dd/4)/256, 256>>>(attnh, attn);

    // 16. x2 = x + attn @ wo^T + bo
    gemm_mma<128,128,EPI_BIAS_RES><<<dim3(6,128,1),256,SMEM_G128x128>>>(
        attn,Dd,0, wo,Dd,0, x2,Dd,0, NROWS,Dd,Dd, bo,x,nullptr,0.f);

    // 17. LN2
    ln_kernel<<<NROWS, 256>>>(x2, ln2g, ln2b, h1);

    // 18. mid = gelu(h1 @ w1^T + b1)
    gemm_mma<128,128,EPI_BIAS_GELU><<<dim3(FFH/128,128,1),256,SMEM_G128x128>>>(
        h1,Dd,0, w1,Dd,0, mid,FFH,0, NROWS,FFH,Dd, b1,nullptr,nullptr,0.f);

    // 19. out = x2 + mid @ w2^T + b2
    gemm_mma<128,128,EPI_BIAS_RES><<<dim3(6,128,1),256,SMEM_G128x128>>>(
        mid,FFH,0, w2,FFH,0, out,Dd,0, NROWS,Dd,FFH, b2,x2,nullptr,0.f);
}

// round 6
// speedup vs baseline: 4.4253x; 1.4335x over previous
#include <cuda_runtime.h>
#include <cuda_fp16.h>
#include <math.h>
#include <stdint.h>

// ---------------- problem constants ----------------
#define Bb   4
#define Ss   4096
#define Dd   768
#define Hh   12
#define Mm   256
#define DhD  64
#define NROWS (Bb*Ss)        // 16384
#define NBH   (Bb*Hh)        // 48
#define NHR   (NBH*Ss)       // 196608
#define FFH   (4*Dd)         // 3072

#define NORM_C   0.35355339059327373f
#define RATIO_C  0.0625f
#define DIAG_C   0.0625f
#define EPS_K    1e-4f
#define LN_EPS   1e-5f

// ---------------- scratch (device globals; allocation-free) ----------------
__device__ __half g_wqkvh[3*Dd*Dd];
__device__ float  g_bqkv[3*Dd];
__device__ __half g_woh[Dd*Dd];
__device__ __half g_w1h[FFH*Dd];
__device__ __half g_w2h[Dd*FFH];
__device__ __half g_projh[Mm*DhD];
__device__ __half g_h1h[NROWS*Dd];
__device__ __half g_qkvh[3*(size_t)NHR*DhD];      // q,k,v in [sel][b,h,s,dh]
__device__ float  g_ddq[(size_t)NHR*Mm];
__device__ float  g_ddk[(size_t)NHR*Mm];
__device__ __half g_qph[(size_t)NHR*Mm];
__device__ __half g_kph[(size_t)NHR*Mm];
__device__ __half g_midh[(size_t)NROWS*FFH];
__device__ __half g_ctxTh[NBH*DhD*Mm];            // [bh][dh][m]
__device__ __half g_attnhh[(size_t)NHR*DhD];      // [b,h,s,dh]
__device__ __half g_attn2h[(size_t)NROWS*Dd];     // [b,s,D]
__device__ float  g_x2[NROWS*Dd];
__device__ float  g_diagq[NHR];
__device__ float  g_diagk[NHR];
__device__ float  g_ksum_part[NBH*8*Mm];
__device__ float  g_ksum[NBH*Mm];
__device__ float  g_dinv[NHR];
__device__ float  g_maxpart[1024];
__device__ float  g_gmax;

// ---------------- epilogue modes ----------------
enum { EPI_BIAS_RES=1, EPI_BIAS_GELU=2, EPI_SCALE=3, EPI_ROWSCALE=4, EPI_QKV=5 };

__device__ __forceinline__ void cpa16(uint32_t smem_dst, const void* gsrc){
    asm volatile("cp.async.cg.shared.global [%0], [%1], 16;" :: "r"(smem_dst), "l"(gsrc));
}
#define CP_COMMIT() asm volatile("cp.async.commit_group;" ::: "memory")
#define CP_WAIT1()  asm volatile("cp.async.wait_group 1;" ::: "memory")

__device__ __forceinline__ uint32_t smem_u32(const void* p){
    uint32_t a;
    asm("{ .reg .u64 t; cvta.to.shared.u64 t, %1; cvt.u32.u64 %0, t; }" : "=r"(a) : "l"(p));
    return a;
}

__device__ __forceinline__ void mma_f16(float* d, const uint32_t* a, const uint32_t* b){
    asm volatile("mma.sync.aligned.m16n8k16.row.col.f32.f16.f16.f32 "
        "{%0,%1,%2,%3}, {%4,%5,%6,%7}, {%8,%9}, {%0,%1,%2,%3};"
        : "+f"(d[0]),"+f"(d[1]),"+f"(d[2]),"+f"(d[3])
        : "r"(a[0]),"r"(a[1]),"r"(a[2]),"r"(a[3]), "r"(b[0]),"r"(b[1]));
}

// ================= fp16 NT GEMM via mma.sync m16n8k16 + cp.async, 3-stage ============
// C[m,n] = sum_k A[m,k]*B[n,k]. BK=32 halfs, warp tile 64x32.
// Smem rows: 16 b32 words (32 halfs) padded to LDKW=20 (conflict-free fragments).
template<int BM,int BN,int EPI,bool OUTH>
__global__ void __launch_bounds__(32*(BM/64)*(BN/32), 2)
hgemm(const __half* __restrict__ A, int lda, long long strA,
      const __half* __restrict__ B, int ldb, long long strB,
      void* __restrict__ Cv, int ldc, long long strC,
      int M, int N, int K,
      const float* __restrict__ bias,
      const float* __restrict__ res,
      const float* __restrict__ rowscale,
      float alpha)
{
    constexpr int WY = BM/64, WX = BN/32, THREADS = 32*WY*WX;
    constexpr int LDKW = 20;                         // b32 words per row
    constexpr int AW = BM*LDKW;                      // A tile words
    constexpr int SW = (BM+BN)*LDKW;                 // stage words
    constexpr int ALD = (BM*4)/THREADS;              // 16B chunks per thread (A)
    constexpr int BLD = (BN*4)/THREADS;

    extern __shared__ uint32_t sh[];
    const uint32_t smb = smem_u32(sh);

    const int z = blockIdx.z;
    A += (long long)z*strA;  B += (long long)z*strB;
    float*  Cf = (float*)Cv  + (long long)z*strC;
    __half* Ch = (__half*)Cv + (long long)z*strC;

    const int brow = blockIdx.y*BM;
    const int bcol = blockIdx.x*BN;
    const int tid  = threadIdx.x;
    const int wid  = tid >> 5;
    const int lane = tid & 31;
    const int wx   = wid % WX, wy = wid / WX;
    const int warp_m = wy*64, warp_n = wx*32;
    const int g = lane >> 2, t = lane & 3;

    float acc[4][4][4];
    #pragma unroll
    for (int i=0;i<4;i++)
        #pragma unroll
        for (int j=0;j<4;j++)
            #pragma unroll
            for (int u=0;u<4;u++) acc[i][j][u]=0.f;

    const int nc = K >> 5;   // 32-half chunks

    #define HISSUE(chunk) do{                                                  \
        const uint32_t bA_ = smb + (uint32_t)(((chunk)%3)*SW)*4u;              \
        const uint32_t bB_ = bA_ + (uint32_t)AW*4u;                            \
        const __half* Ap_ = A + (long long)brow*lda + (chunk)*32;              \
        const __half* Bp_ = B + (long long)bcol*ldb + (chunk)*32;              \
        _Pragma("unroll")                                                      \
        for (int l=0;l<ALD;l++){                                               \
            const int idx = tid + l*THREADS, r = idx>>2, c4 = idx&3;           \
            cpa16(bA_ + (uint32_t)(r*LDKW + c4*4)*4u,                          \
                  Ap_ + (long long)r*lda + c4*8);                              \
        }                                                                      \
        _Pragma("unroll")                                                      \
        for (int l=0;l<BLD;l++){                                               \
            const int idx = tid + l*THREADS, r = idx>>2, c4 = idx&3;           \
            cpa16(bB_ + (uint32_t)(r*LDKW + c4*4)*4u,                          \
                  Bp_ + (long long)r*ldb + c4*8);                              \
        }                                                                      \
    }while(0)

    if (0 < nc) HISSUE(0);
    CP_COMMIT();
    if (1 < nc) HISSUE(1);
    CP_COMMIT();

    for (int i=0; i<nc; ++i){
        CP_WAIT1();
        __syncthreads();
        if (i+2 < nc) HISSUE(i+2);
        CP_COMMIT();

        const uint32_t* Asb = sh + (i%3)*SW;
        const uint32_t* Bsb = Asb + AW;

        #pragma unroll
        for (int kk=0; kk<2; ++kk){
            uint32_t af[4][4], bf[4][2];
            #pragma unroll
            for (int mt=0; mt<4; ++mt){
                const int m0 = warp_m + mt*16;
                af[mt][0] = Asb[(m0+g  )*LDKW + kk*8 + t    ];
                af[mt][1] = Asb[(m0+g+8)*LDKW + kk*8 + t    ];
                af[mt][2] = Asb[(m0+g  )*LDKW + kk*8 + t + 4];
                af[mt][3] = Asb[(m0+g+8)*LDKW + kk*8 + t + 4];
            }
            #pragma unroll
            for (int nt=0; nt<4; ++nt){
                const int n0 = warp_n + nt*8;
                bf[nt][0] = Bsb[(n0+g)*LDKW + kk*8 + t    ];
                bf[nt][1] = Bsb[(n0+g)*LDKW + kk*8 + t + 4];
            }
            #pragma unroll
            for (int mt=0; mt<4; ++mt)
                #pragma unroll
                for (int nt=0; nt<4; ++nt)
                    mma_f16(acc[mt][nt], af[mt], bf[nt]);
        }
    }
    #undef HISSUE

    // -------- epilogue --------
    #pragma unroll
    for (int mt=0; mt<4; ++mt){
        const int r0 = brow + warp_m + mt*16 + g;
        const int r1 = r0 + 8;
        float rs0 = 1.f, rs1 = 1.f;
        if (EPI==EPI_ROWSCALE){
            rs0 = rowscale[(long long)z*M + r0];
            rs1 = rowscale[(long long)z*M + r1];
        }
        #pragma unroll
        for (int nt=0; nt<4; ++nt){
            const int c0 = bcol + warp_n + nt*8 + 2*t;
            float v00 = acc[mt][nt][0], v01 = acc[mt][nt][1];
            float v10 = acc[mt][nt][2], v11 = acc[mt][nt][3];
            if (EPI==EPI_BIAS_RES || EPI==EPI_BIAS_GELU || EPI==EPI_QKV){
                const float b0 = bias[c0], b1 = bias[c0+1];
                v00 += b0; v01 += b1; v10 += b0; v11 += b1;
            }
            if (EPI==EPI_BIAS_RES){
                v00 += res[(long long)r0*ldc + c0];   v01 += res[(long long)r0*ldc + c0+1];
                v10 += res[(long long)r1*ldc + c0];   v11 += res[(long long)r1*ldc + c0+1];
            }
            if (EPI==EPI_BIAS_GELU){
                v00 = 0.5f*v00*(1.0f+erff(v00*0.70710678118654752f));
                v01 = 0.5f*v01*(1.0f+erff(v01*0.70710678118654752f));
                v10 = 0.5f*v10*(1.0f+erff(v10*0.70710678118654752f));
                v11 = 0.5f*v11*(1.0f+erff(v11*0.70710678118654752f));
            }
            if (EPI==EPI_SCALE){ v00*=alpha; v01*=alpha; v10*=alpha; v11*=alpha; }
            if (EPI==EPI_ROWSCALE){ v00*=rs0; v01*=rs0; v10*=rs1; v11*=rs1; }

            if (EPI==EPI_QKV){
                // c0 in [0,2304): sel = c0/768, cc = c0%768, h=cc>>6, dh=cc&63
                const int sel = c0/Dd, cc = c0 - sel*Dd;
                const int h_ = cc>>6, dh_ = cc&63;
                const int b0_ = r0>>12, s0_ = r0&4095;
                const int b1_ = r1>>12, s1_ = r1&4095;
                __half* base = (__half*)Cv + (size_t)sel*NHR*DhD;
                __half2 o0 = __floats2half2_rn(v00,v01);
                __half2 o1 = __floats2half2_rn(v10,v11);
                *reinterpret_cast<__half2*>(base + ((((long long)(b0_*Hh+h_))<<12)+s0_)*DhD + dh_) = o0;
                *reinterpret_cast<__half2*>(base + ((((long long)(b1_*Hh+h_))<<12)+s1_)*DhD + dh_) = o1;
            } else if (OUTH){
                __half2 o0 = __floats2half2_rn(v00,v01);
                __half2 o1 = __floats2half2_rn(v10,v11);
                *reinterpret_cast<__half2*>(Ch + (long long)r0*ldc + c0) = o0;
                *reinterpret_cast<__half2*>(Ch + (long long)r1*ldc + c0) = o1;
            } else {
                float2 o0; o0.x=v00; o0.y=v01;
                float2 o1; o1.x=v10; o1.y=v11;
                *reinterpret_cast<float2*>(Cf + (long long)r0*ldc + c0) = o0;
                *reinterpret_cast<float2*>(Cf + (long long)r1*ldc + c0) = o1;
            }
        }
    }
}

#define SMEM_H128x128 (3*(128+128)*20*4)   // 61440
#define SMEM_H128x64  (3*(128+64)*20*4)    // 46080

// ---------------- weight conversion ----------------
__global__ void f2h_kernel(const float* __restrict__ s, __half* __restrict__ d, int n4)
{
    const int i = blockIdx.x*256 + threadIdx.x;
    if (i >= n4) return;
    float4 v = reinterpret_cast<const float4*>(s)[i];
    __half2* o = reinterpret_cast<__half2*>(d) + 2*i;
    o[0] = __floats2half2_rn(v.x, v.y);
    o[1] = __floats2half2_rn(v.z, v.w);
}
__global__ void bpack_kernel(const float* bq, const float* bk, const float* bv)
{
    const int i = blockIdx.x*256 + threadIdx.x;
    if (i >= 3*Dd) return;
    const int sel = i/Dd, c = i - sel*Dd;
    g_bqkv[i] = sel==0 ? bq[c] : (sel==1 ? bk[c] : bv[c]);
}

// ---------------- LayerNorm (row=768, 256 threads), half output ----------------
__global__ void ln_kernel(const float* __restrict__ x, const float* __restrict__ g,
                          const float* __restrict__ b, __half* __restrict__ out)
{
    const int row = blockIdx.x;
    const float* xr = x + (long long)row*Dd;
    float v[3]; float s=0.f, ss=0.f;
    #pragma unroll
    for (int i=0;i<3;i++){ v[i]=xr[threadIdx.x + i*256]; s+=v[i]; ss+=v[i]*v[i]; }
    #pragma unroll
    for (int o=16;o;o>>=1){ s+=__shfl_xor_sync(0xffffffffu,s,o); ss+=__shfl_xor_sync(0xffffffffu,ss,o); }
    __shared__ float rs_[8], rss_[8];
    const int lane = threadIdx.x & 31, w = threadIdx.x >> 5;
    if (lane==0){ rs_[w]=s; rss_[w]=ss; }
    __syncthreads();
    s=0.f; ss=0.f;
    #pragma unroll
    for (int i=0;i<8;i++){ s+=rs_[i]; ss+=rss_[i]; }
    const float mu  = s*(1.0f/Dd);
    const float var = ss*(1.0f/Dd) - mu*mu;
    const float rstd = rsqrtf(var + LN_EPS);
    __half* outr = out + (long long)row*Dd;
    #pragma unroll
    for (int i=0;i<3;i++){
        int c = threadIdx.x + i*256;
        outr[c] = __float2half((v[i]-mu)*rstd*g[c] + b[c]);
    }
}

// ---------------- diag: 0.0625 * sum(q^2), half input (warp per row) ----------------
__global__ void diag_kernel(const __half* __restrict__ src, float* __restrict__ dst)
{
    const int lane = threadIdx.x & 31, w = threadIdx.x >> 5;
    const long long row = (long long)blockIdx.x*8 + w;
    __half2 v = reinterpret_cast<const __half2*>(src + row*DhD)[lane];
    float2 f = __half22float2(v);
    float s = f.x*f.x + f.y*f.y;
    #pragma unroll
    for (int o=16;o;o>>=1) s += __shfl_xor_sync(0xffffffffu,s,o);
    if (lane==0) dst[row] = DIAG_C * s;
}

// ---------------- q features: row max + exp; fp32 in, half out ----------------
__global__ void expq_kernel(const float* __restrict__ dd, const float* __restrict__ diag,
                            __half* __restrict__ qph)
{
    const int lane = threadIdx.x & 31, w = threadIdx.x >> 5;
    const long long row = (long long)blockIdx.x*8 + w;
    const float4* p = reinterpret_cast<const float4*>(dd + row*Mm);
    float4 a = p[lane], c = p[lane+32];
    float mx = fmaxf(fmaxf(fmaxf(a.x,a.y),fmaxf(a.z,a.w)),
                     fmaxf(fmaxf(c.x,c.y),fmaxf(c.z,c.w)));
    #pragma unroll
    for (int o=16;o;o>>=1) mx = fmaxf(mx, __shfl_xor_sync(0xffffffffu,mx,o));
    const float d = diag[row] + mx;
    __half2* q = reinterpret_cast<__half2*>(qph + row*Mm);
    q[2*lane  ]    = __floats2half2_rn(RATIO_C*(expf(a.x-d)+EPS_K), RATIO_C*(expf(a.y-d)+EPS_K));
    q[2*lane+1]    = __floats2half2_rn(RATIO_C*(expf(a.z-d)+EPS_K), RATIO_C*(expf(a.w-d)+EPS_K));
    q[2*(lane+32)] = __floats2half2_rn(RATIO_C*(expf(c.x-d)+EPS_K), RATIO_C*(expf(c.y-d)+EPS_K));
    q[2*(lane+32)+1]=__floats2half2_rn(RATIO_C*(expf(c.z-d)+EPS_K), RATIO_C*(expf(c.w-d)+EPS_K));
}

// ---------------- global max over ddk ----------------
__global__ void max1_kernel(const float* __restrict__ dd)
{
    const long long n = (long long)NHR*Mm;
    float m = -3.402823466e38f;
    for (long long i = (long long)blockIdx.x*blockDim.x + threadIdx.x; i<n;
         i += (long long)gridDim.x*blockDim.x)
        m = fmaxf(m, dd[i]);
    #pragma unroll
    for (int o=16;o;o>>=1) m = fmaxf(m, __shfl_xor_sync(0xffffffffu,m,o));
    __shared__ float sm[8];
    const int lane = threadIdx.x & 31, w = threadIdx.x >> 5;
    if (lane==0) sm[w]=m;
    __syncthreads();
    if (threadIdx.x==0){
        float tt = sm[0];
        #pragma unroll
        for (int i=1;i<8;i++) tt = fmaxf(tt, sm[i]);
        g_maxpart[blockIdx.x] = tt;
    }
}
__global__ void max2_kernel()
{
    float m = -3.402823466e38f;
    for (int i=threadIdx.x; i<1024; i+=256) m = fmaxf(m, g_maxpart[i]);
    #pragma unroll
    for (int o=16;o;o>>=1) m = fmaxf(m, __shfl_xor_sync(0xffffffffu,m,o));
    __shared__ float sm[8];
    const int lane = threadIdx.x & 31, w = threadIdx.x >> 5;
    if (lane==0) sm[w]=m;
    __syncthreads();
    if (threadIdx.x==0){
        float tt = sm[0];
        #pragma unroll
        for (int i=1;i<8;i++) tt = fmaxf(tt, sm[i]);
        g_gmax = tt;
    }
}

// ---------------- k features: global max + exp; fp32 in, half out ----------------
__global__ void expk_kernel(const float* __restrict__ dd, const float* __restrict__ diag,
                            __half* __restrict__ kph)
{
    const long long i4 = (long long)blockIdx.x*blockDim.x + threadIdx.x;
    const float gm = g_gmax;
    const long long row = i4 >> 6;
    const float d = diag[row] + gm;
    float4 v = reinterpret_cast<const float4*>(dd)[i4];
    __half2* o = reinterpret_cast<__half2*>(kph) + 2*i4;
    o[0] = __floats2half2_rn(RATIO_C*(expf(v.x-d)+EPS_K), RATIO_C*(expf(v.y-d)+EPS_K));
    o[1] = __floats2half2_rn(RATIO_C*(expf(v.z-d)+EPS_K), RATIO_C*(expf(v.w-d)+EPS_K));
}

// ---------------- k_sum (two stage), half input ----------------
__global__ void ksum_part_kernel(const __half* __restrict__ kp)
{
    const int bh = blockIdx.x, split = blockIdx.y, m = threadIdx.x;
    const __half* p = kp + ((long long)bh*Ss + (long long)split*512)*Mm + m;
    float s = 0.f;
    for (int i=0;i<512;i++) s += __half2float(p[(long long)i*Mm]);
    g_ksum_part[(bh*8+split)*Mm + m] = s;
}
__global__ void ksum_red_kernel()
{
    const int bh = blockIdx.x, m = threadIdx.x;
    float s = 0.f;
    #pragma unroll
    for (int i=0;i<8;i++) s += g_ksum_part[(bh*8+i)*Mm + m];
    g_ksum[bh*Mm + m] = s;
}

// ---------------- ctx^T[bh][dh][m] = sum_s kp[bh,s,m]*v[bh,s,dh]; half in/out ----------
__global__ void __launch_bounds__(256)
ctx_kernel(const __half* __restrict__ kp, const __half* __restrict__ vh, __half* __restrict__ ctxT)
{
    const int z = blockIdx.z;
    const int mtile = blockIdx.y;
    __shared__ float As[32][64];
    __shared__ float Bs[32][64];
    const int tid = threadIdx.x;
    const int tx = tid % 16;
    const int ty = tid / 16;

    const __half* kpb = kp + (long long)z*Ss*Mm + mtile*64;
    const __half* vhb = vh + (long long)z*Ss*DhD;

    float acc[4][4];
    #pragma unroll
    for (int i=0;i<4;i++)
        #pragma unroll
        for (int j=0;j<4;j++) acc[i][j]=0.f;

    for (int s0=0; s0<Ss; s0+=32){
        #pragma unroll
        for (int l=0;l<2;l++){
            const int idx = tid + l*256;
            const int r = idx >> 4, c = idx & 15;
            const __half2* ka = reinterpret_cast<const __half2*>(kpb + (long long)(s0+r)*Mm + c*4);
            float2 k0 = __half22float2(ka[0]), k1 = __half22float2(ka[1]);
            As[r][c*4+0]=k0.x; As[r][c*4+1]=k0.y; As[r][c*4+2]=k1.x; As[r][c*4+3]=k1.y;
            const __half2* va = reinterpret_cast<const __half2*>(vhb + (long long)(s0+r)*DhD + c*4);
            float2 v0 = __half22float2(va[0]), v1 = __half22float2(va[1]);
            Bs[r][c*4+0]=v0.x; Bs[r][c*4+1]=v0.y; Bs[r][c*4+2]=v1.x; Bs[r][c*4+3]=v1.y;
        }
        __syncthreads();
        #pragma unroll
        for (int k=0;k<32;k++){
            float4 a4 = *reinterpret_cast<const float4*>(&As[k][ty*4]);
            float4 b4 = *reinterpret_cast<const float4*>(&Bs[k][tx*4]);
            float ar[4]={a4.x,a4.y,a4.z,a4.w}, br[4]={b4.x,b4.y,b4.z,b4.w};
            #pragma unroll
            for (int i=0;i<4;i++)
                #pragma unroll
                for (int j=0;j<4;j++) acc[i][j] = fmaf(ar[i], br[j], acc[i][j]);
        }
        __syncthreads();
    }
    #pragma unroll
    for (int i=0;i<4;i++)
        #pragma unroll
        for (int j=0;j<4;j++){
            int m_  = mtile*64 + ty*4 + i;
            int dh_ = tx*4 + j;
            ctxT[(long long)z*DhD*Mm + (long long)dh_*Mm + m_] = __float2half(acc[i][j]);
        }
}

// ---------------- d_inv: half qp, fp32 ksum (warp per row) ----------------
__global__ void dinv_kernel(const __half* __restrict__ qp, float* __restrict__ dinv)
{
    const int lane = threadIdx.x & 31, w = threadIdx.x >> 5;
    const long long row = (long long)blockIdx.x*8 + w;
    const int bh = (int)(row >> 12);
    const __half2* p = reinterpret_cast<const __half2*>(qp + row*Mm);
    const float4* ks = reinterpret_cast<const float4*>(g_ksum + (long long)bh*Mm);
    float s = 0.f;
    #pragma unroll
    for (int h=0; h<2; ++h){
        const int li = lane + h*32;
        float2 a0 = __half22float2(p[2*li]), a1 = __half22float2(p[2*li+1]);
        float4 k4 = ks[li];
        s += a0.x*k4.x + a0.y*k4.y + a1.x*k4.z + a1.y*k4.w;
    }
    #pragma unroll
    for (int o=16;o;o>>=1) s += __shfl_xor_sync(0xffffffffu,s,o);
    if (lane==0) dinv[row] = 1.0f/s;
}

// ---------------- transpose attn [b,h,s,dh] -> [b,s,D], half ----------------
__global__ void trans_kernel(const __half* __restrict__ attnh, __half* __restrict__ out)
{
    const long long i8 = (long long)blockIdx.x*blockDim.x + threadIdx.x;
    const long long idx = i8*8;
    const int row = (int)(idx / Dd);
    const int col = (int)(idx % Dd);
    const int b_ = row>>12, s_ = row&4095, h_ = col>>6, dh_ = col&63;
    *reinterpret_cast<uint4*>(out + idx) =
        *reinterpret_cast<const uint4*>(attnh + ((((long long)(b_*Hh+h_))<<12)+s_)*DhD + dh_);
}

// ---------------- host ----------------
extern "C" void kernel_launch(void* const* d_in, const int* in_sizes, int n_in,
                              void* d_out, int out_size)
{
    const float* x    = (const float*)d_in[0];
    const float* proj = (const float*)d_in[1];
    const float* wq   = (const float*)d_in[2];
    const float* bq   = (const float*)d_in[3];
    const float* wk   = (const float*)d_in[4];
    const float* bk   = (const float*)d_in[5];
    const float* wv   = (const float*)d_in[6];
    const float* bv   = (const float*)d_in[7];
    const float* wo   = (const float*)d_in[8];
    const float* bo   = (const float*)d_in[9];
    const float* ln1g = (const float*)d_in[10];
    const float* ln1b = (const float*)d_in[11];
    const float* ln2g = (const float*)d_in[12];
    const float* ln2b = (const float*)d_in[13];
    const float* w1   = (const float*)d_in[14];
    const float* b1   = (const float*)d_in[15];
    const float* w2   = (const float*)d_in[16];
    const float* b2   = (const float*)d_in[17];
    float* out = (float*)d_out;

    void *p;
    __half *wqkvh, *woh, *w1h, *w2h, *projh, *h1h, *qkvh, *qph, *kph, *midh, *ctxTh, *attnhh, *attn2h;
    float *bqkv, *ddq, *ddk, *x2, *dq, *dk, *dinv;
    cudaGetSymbolAddress(&p, g_wqkvh);  wqkvh  = (__half*)p;
    cudaGetSymbolAddress(&p, g_bqkv);   bqkv   = (float*)p;
    cudaGetSymbolAddress(&p, g_woh);    woh    = (__half*)p;
    cudaGetSymbolAddress(&p, g_w1h);    w1h    = (__half*)p;
    cudaGetSymbolAddress(&p, g_w2h);    w2h    = (__half*)p;
    cudaGetSymbolAddress(&p, g_projh);  projh  = (__half*)p;
    cudaGetSymbolAddress(&p, g_h1h);    h1h    = (__half*)p;
    cudaGetSymbolAddress(&p, g_qkvh);   qkvh   = (__half*)p;
    cudaGetSymbolAddress(&p, g_ddq);    ddq    = (float*)p;
    cudaGetSymbolAddress(&p, g_ddk);    ddk    = (float*)p;
    cudaGetSymbolAddress(&p, g_qph);    qph    = (__half*)p;
    cudaGetSymbolAddress(&p, g_kph);    kph    = (__half*)p;
    cudaGetSymbolAddress(&p, g_midh);   midh   = (__half*)p;
    cudaGetSymbolAddress(&p, g_ctxTh);  ctxTh  = (__half*)p;
    cudaGetSymbolAddress(&p, g_attnhh); attnhh = (__half*)p;
    cudaGetSymbolAddress(&p, g_attn2h); attn2h = (__half*)p;
    cudaGetSymbolAddress(&p, g_x2);     x2     = (float*)p;
    cudaGetSymbolAddress(&p, g_diagq);  dq     = (float*)p;
    cudaGetSymbolAddress(&p, g_diagk);  dk     = (float*)p;
    cudaGetSymbolAddress(&p, g_dinv);   dinv   = (float*)p;

    __half* qh = qkvh;
    __half* kh = qkvh + (size_t)NHR*DhD;
    __half* vh = qkvh + 2*(size_t)NHR*DhD;

    cudaFuncSetAttribute(hgemm<128,128,EPI_QKV,true>,       cudaFuncAttributeMaxDynamicSharedMemorySize, SMEM_H128x128);
    cudaFuncSetAttribute(hgemm<128,128,EPI_SCALE,false>,    cudaFuncAttributeMaxDynamicSharedMemorySize, SMEM_H128x128);
    cudaFuncSetAttribute(hgemm<128,128,EPI_BIAS_RES,false>, cudaFuncAttributeMaxDynamicSharedMemorySize, SMEM_H128x128);
    cudaFuncSetAttribute(hgemm<128,128,EPI_BIAS_GELU,true>, cudaFuncAttributeMaxDynamicSharedMemorySize, SMEM_H128x128);
    cudaFuncSetAttribute(hgemm<128,64,EPI_ROWSCALE,true>,   cudaFuncAttributeMaxDynamicSharedMemorySize, SMEM_H128x64);

    // 0. weight conversion (fp32 -> fp16)
    f2h_kernel<<<576, 256>>>(wq, wqkvh,            Dd*Dd/4);
    f2h_kernel<<<576, 256>>>(wk, wqkvh +   Dd*Dd,  Dd*Dd/4);
    f2h_kernel<<<576, 256>>>(wv, wqkvh + 2*Dd*Dd,  Dd*Dd/4);
    f2h_kernel<<<576, 256>>>(wo, woh,              Dd*Dd/4);
    f2h_kernel<<<2304,256>>>(w1, w1h,              FFH*Dd/4);
    f2h_kernel<<<2304,256>>>(w2, w2h,              Dd*FFH/4);
    f2h_kernel<<<16,  256>>>(proj, projh,          Mm*DhD/4);
    bpack_kernel<<<9, 256>>>(bq, bk, bv);

    // 1. LN1 -> half
    ln_kernel<<<NROWS, 256>>>(x, ln1g, ln1b, h1h);

    // 2. fused QKV (N=2304), writes q/k/v half in head layout
    hgemm<128,128,EPI_QKV,true><<<dim3(18,128,1),256,SMEM_H128x128>>>(
        h1h,Dd,0, wqkvh,Dd,0, qkvh,DhD,0, NROWS,3*Dd,Dd, bqkv,nullptr,nullptr,0.f);

    // 3. diag terms
    diag_kernel<<<NHR/8, 256>>>(qh, dq);
    diag_kernel<<<NHR/8, 256>>>(kh, dk);

    // 4. dd = norm * (q/k @ proj^T), fp32 out
    hgemm<128,128,EPI_SCALE,false><<<dim3(2,NHR/128,1),256,SMEM_H128x128>>>(
        qh,DhD,0, projh,DhD,0, ddq,Mm,0, NHR,Mm,DhD, nullptr,nullptr,nullptr,NORM_C);
    hgemm<128,128,EPI_SCALE,false><<<dim3(2,NHR/128,1),256,SMEM_H128x128>>>(
        kh,DhD,0, projh,DhD,0, ddk,Mm,0, NHR,Mm,DhD, nullptr,nullptr,nullptr,NORM_C);

    // 5. global max of ddk
    max1_kernel<<<1024, 256>>>(ddk);
    max2_kernel<<<1, 256>>>();

    // 6. FAVOR+ exp features -> half
    expq_kernel<<<NHR/8, 256>>>(ddq, dq, qph);
    expk_kernel<<<(NHR*(Mm/4))/256, 256>>>(ddk, dk, kph);

    // 7. k_sum
    ksum_part_kernel<<<dim3(NBH,8,1), 256>>>(kph);
    ksum_red_kernel<<<NBH, 256>>>();

    // 8. ctx^T (half)
    ctx_kernel<<<dim3(1,4,NBH), 256>>>(kph, vh, ctxTh);

    // 9. d_inv
    dinv_kernel<<<NHR/8, 256>>>(qph, dinv);

    // 10. attn_h = d_inv * (qp @ ctx) -> half, batched over bh
    hgemm<128,64,EPI_ROWSCALE,true><<<dim3(1,Ss/128,NBH),128,SMEM_H128x64>>>(
        qph,Mm,(long long)Ss*Mm, ctxTh,Mm,(long long)DhD*Mm, attnhh,DhD,(long long)Ss*DhD,
        Ss,DhD,Mm, nullptr,nullptr,dinv,0.f);

    // 11. transpose to [b,s,D] (half)
    trans_kernel<<<(NROWS*Dd/8)/256, 256>>>(attnhh, attn2h);

    // 12. x2 = x + attn @ wo^T + bo  (fp32 out)
    hgemm<128,128,EPI_BIAS_RES,false><<<dim3(6,128,1),256,SMEM_H128x128>>>(
        attn2h,Dd,0, woh,Dd,0, x2,Dd,0, NROWS,Dd,Dd, bo,x,nullptr,0.f);

    // 13. LN2 -> half
    ln_kernel<<<NROWS, 256>>>(x2, ln2g, ln2b, h1h);

    // 14. mid = gelu(h1 @ w1^T + b1) -> half
    hgemm<128,128,EPI_BIAS_GELU,true><<<dim3(FFH/128,128,1),256,SMEM_H128x128>>>(
        h1h,Dd,0, w1h,Dd,0, midh,FFH,0, NROWS,FFH,Dd, b1,nullptr,nullptr,0.f);

    // 15. out = x2 + mid @ w2^T + b2 (fp32 out)
    hgemm<128,128,EPI_BIAS_RES,false><<<dim3(6,128,1),256,SMEM_H128x128>>>(
        midh,FFH,0, w2h,FFH,0, out,Dd,0, NROWS,Dd,FFH, b2,x2,nullptr,0.f);
}

// round 7
// speedup vs baseline: 4.9192x; 1.1116x over previous
#include <cuda_runtime.h>
#include <cuda_fp16.h>
#include <math.h>
#include <stdint.h>

// ---------------- problem constants ----------------
#define Bb   4
#define Ss   4096
#define Dd   768
#define Hh   12
#define Mm   256
#define DhD  64
#define NROWS (Bb*Ss)        // 16384
#define NBH   (Bb*Hh)        // 48
#define NHR   (NBH*Ss)       // 196608
#define FFH   (4*Dd)         // 3072

#define NORM_C   0.35355339059327373f
#define RATIO_C  0.0625f
#define DIAG_C   0.0625f
#define EPS_K    1e-4f
#define LN_EPS   1e-5f

// ---------------- scratch (device globals; allocation-free) ----------------
__device__ __half g_wqkvh[3*Dd*Dd];
__device__ float  g_bqkv[3*Dd];
__device__ __half g_woh[Dd*Dd];
__device__ __half g_w1h[FFH*Dd];
__device__ __half g_w2h[Dd*FFH];
__device__ __half g_projh[Mm*DhD];
__device__ __half g_h1h[NROWS*Dd];
__device__ __half g_qkvh[3*(size_t)NHR*DhD];      // q,k,v in [sel][b,h,s,dh]
__device__ float  g_ddk[(size_t)NHR*Mm];          // dd_k - diag_k
__device__ __half g_qph[(size_t)NHR*Mm];
__device__ __half g_kph[(size_t)NHR*Mm];
__device__ __half g_midh[(size_t)NROWS*FFH];
__device__ __half g_ctxTh[NBH*DhD*Mm];            // [bh][dh][m]
__device__ __half g_attn2h[(size_t)NROWS*Dd];     // [b,s,D]
__device__ float  g_x2[NROWS*Dd];
__device__ float  g_diagq[NHR];
__device__ float  g_diagk[NHR];
__device__ float  g_ksum_part[NBH*8*Mm];
__device__ float  g_ksum[NBH*Mm];
__device__ float  g_dinv[NHR];
__device__ unsigned g_gmax_u;

// ---------------- epilogue modes ----------------
enum { EPI_BIAS_RES=1, EPI_BIAS_GELU=2, EPI_QKV=5, EPI_QFEAT=6, EPI_KMAX=7, EPI_ATTN=8 };

__device__ __forceinline__ void cpa16(uint32_t smem_dst, const void* gsrc){
    asm volatile("cp.async.cg.shared.global [%0], [%1], 16;" :: "r"(smem_dst), "l"(gsrc));
}
#define CP_COMMIT() asm volatile("cp.async.commit_group;" ::: "memory")
#define CP_WAIT1()  asm volatile("cp.async.wait_group 1;" ::: "memory")

__device__ __forceinline__ uint32_t smem_u32(const void* p){
    uint32_t a;
    asm("{ .reg .u64 t; cvta.to.shared.u64 t, %1; cvt.u32.u64 %0, t; }" : "=r"(a) : "l"(p));
    return a;
}

__device__ __forceinline__ void mma_f16(float* d, const uint32_t* a, const uint32_t* b){
    asm volatile("mma.sync.aligned.m16n8k16.row.col.f32.f16.f16.f32 "
        "{%0,%1,%2,%3}, {%4,%5,%6,%7}, {%8,%9}, {%0,%1,%2,%3};"
        : "+f"(d[0]),"+f"(d[1]),"+f"(d[2]),"+f"(d[3])
        : "r"(a[0]),"r"(a[1]),"r"(a[2]),"r"(a[3]), "r"(b[0]),"r"(b[1]));
}
#define LDSM4(r0,r1,r2,r3,addr) \
    asm volatile("ldmatrix.sync.aligned.m8n8.x4.shared.b16 {%0,%1,%2,%3}, [%4];" \
        : "=r"(r0),"=r"(r1),"=r"(r2),"=r"(r3) : "r"(addr))

// ================= fp16 NT GEMM: mma.sync m16n8k16 + cp.async(3-stage) + ldmatrix ======
// C[m,n] = sum_k A[m,k]*B[n,k]. BK=32 halfs; warp tile 64x32; row pad LDKW=20 words.
template<int BM,int BN,int EPI,bool OUTH>
__global__ void __launch_bounds__(32*(BM/64)*(BN/32), 2)
hgemm(const __half* __restrict__ A, int lda, long long strA,
      const __half* __restrict__ B, int ldb, long long strB,
      void* __restrict__ Cv, int ldc, long long strC,
      int M, int N, int K,
      const float* __restrict__ bias,
      const float* __restrict__ res,
      const float* __restrict__ rowscale,
      float alpha)
{
    constexpr int WY = BM/64, WX = BN/32, THREADS = 32*WY*WX;
    constexpr int LDKW = 20;
    constexpr int AW = BM*LDKW;
    constexpr int SW = (BM+BN)*LDKW;
    constexpr int ALD = (BM*4)/THREADS;
    constexpr int BLD = (BN*4)/THREADS;

    extern __shared__ uint32_t sh[];
    __shared__ float s_wmax[(EPI==EPI_KMAX)?8:1];
    const uint32_t smb = smem_u32(sh);

    const int z = blockIdx.z;
    A += (long long)z*strA;  B += (long long)z*strB;
    float*  Cf = (float*)Cv  + (long long)z*strC;
    __half* Ch = (__half*)Cv + (long long)z*strC;

    const int brow = blockIdx.y*BM;
    const int bcol = blockIdx.x*BN;
    const int tid  = threadIdx.x;
    const int wid  = tid >> 5;
    const int lane = tid & 31;
    const int wx   = wid % WX, wy = wid / WX;
    const int warp_m = wy*64, warp_n = wx*32;
    const int g = lane >> 2, t = lane & 3;

    // ldmatrix per-lane byte offsets within a stage
    const uint32_t aoff = (uint32_t)(((warp_m + (lane&15))*LDKW + (lane>>4)*4))*4u;
    const uint32_t boff = (uint32_t)((AW + (warp_n + (lane>>4)*8 + (lane&7))*LDKW + ((lane>>3)&1)*4))*4u;

    float acc[4][4][4];
    #pragma unroll
    for (int i=0;i<4;i++)
        #pragma unroll
        for (int j=0;j<4;j++)
            #pragma unroll
            for (int u=0;u<4;u++) acc[i][j][u]=0.f;

    const int nc = K >> 5;

    #define HISSUE(chunk) do{                                                  \
        const uint32_t bA_ = smb + (uint32_t)(((chunk)%3)*SW)*4u;              \
        const uint32_t bB_ = bA_ + (uint32_t)AW*4u;                            \
        const __half* Ap_ = A + (long long)brow*lda + (chunk)*32;              \
        const __half* Bp_ = B + (long long)bcol*ldb + (chunk)*32;              \
        _Pragma("unroll")                                                      \
        for (int l=0;l<ALD;l++){                                               \
            const int idx = tid + l*THREADS, r = idx>>2, c4 = idx&3;           \
            cpa16(bA_ + (uint32_t)(r*LDKW + c4*4)*4u,                          \
                  Ap_ + (long long)r*lda + c4*8);                              \
        }                                                                      \
        _Pragma("unroll")                                                      \
        for (int l=0;l<BLD;l++){                                               \
            const int idx = tid + l*THREADS, r = idx>>2, c4 = idx&3;           \
            cpa16(bB_ + (uint32_t)(r*LDKW + c4*4)*4u,                          \
                  Bp_ + (long long)r*ldb + c4*8);                              \
        }                                                                      \
    }while(0)

    if (0 < nc) HISSUE(0);
    CP_COMMIT();
    if (1 < nc) HISSUE(1);
    CP_COMMIT();

    for (int i=0; i<nc; ++i){
        CP_WAIT1();
        __syncthreads();
        if (i+2 < nc) HISSUE(i+2);
        CP_COMMIT();

        const uint32_t stg = smb + (uint32_t)((i%3)*SW)*4u;

        #pragma unroll
        for (int kk=0; kk<2; ++kk){
            uint32_t af[4][4], bf[4][2];
            #pragma unroll
            for (int mt=0; mt<4; ++mt)
                LDSM4(af[mt][0],af[mt][1],af[mt][2],af[mt][3],
                      stg + aoff + (uint32_t)((mt*16*LDKW + kk*8))*4u);
            LDSM4(bf[0][0],bf[0][1],bf[1][0],bf[1][1],
                  stg + boff + (uint32_t)(kk*8)*4u);
            LDSM4(bf[2][0],bf[2][1],bf[3][0],bf[3][1],
                  stg + boff + (uint32_t)((16*LDKW + kk*8))*4u);
            #pragma unroll
            for (int mt=0; mt<4; ++mt)
                #pragma unroll
                for (int nt=0; nt<4; ++nt)
                    mma_f16(acc[mt][nt], af[mt], bf[nt]);
        }
        __syncthreads();
    }
    #undef HISSUE

    // ================= epilogues =================
    if (EPI==EPI_QFEAT){
        // full feature row in CTA (BN=256=Mm): rowmax + diag + exp -> half
        float rmax[4][2];
        #pragma unroll
        for (int mt=0; mt<4; ++mt){
            float m0=-3.402823466e38f, m1=m0;
            #pragma unroll
            for (int nt=0; nt<4; ++nt){
                #pragma unroll
                for (int u=0;u<4;u++) acc[mt][nt][u]*=alpha;
                m0 = fmaxf(m0, fmaxf(acc[mt][nt][0], acc[mt][nt][1]));
                m1 = fmaxf(m1, fmaxf(acc[mt][nt][2], acc[mt][nt][3]));
            }
            m0 = fmaxf(m0, __shfl_xor_sync(0xffffffffu,m0,1));
            m0 = fmaxf(m0, __shfl_xor_sync(0xffffffffu,m0,2));
            m1 = fmaxf(m1, __shfl_xor_sync(0xffffffffu,m1,1));
            m1 = fmaxf(m1, __shfl_xor_sync(0xffffffffu,m1,2));
            rmax[mt][0]=m0; rmax[mt][1]=m1;
        }
        __syncthreads();                       // smem tiles dead; reuse as reduction buf
        float* red = (float*)sh;               // [64][8]
        if (t==0){
            #pragma unroll
            for (int mt=0; mt<4; ++mt){
                red[(mt*16+g)*8 + wid]   = rmax[mt][0];
                red[(mt*16+8+g)*8 + wid] = rmax[mt][1];
            }
        }
        __syncthreads();
        #pragma unroll
        for (int mt=0; mt<4; ++mt){
            const int grow = brow + mt*16 + g;
            float mx0 = red[(mt*16+g)*8], mx1 = red[(mt*16+8+g)*8];
            #pragma unroll
            for (int w=1; w<8; ++w){
                mx0 = fmaxf(mx0, red[(mt*16+g)*8+w]);
                mx1 = fmaxf(mx1, red[(mt*16+8+g)*8+w]);
            }
            const float d0 = rowscale[grow]   + mx0;
            const float d1 = rowscale[grow+8] + mx1;
            #pragma unroll
            for (int nt=0; nt<4; ++nt){
                const int c0 = warp_n + nt*8 + 2*t;
                __half2 o0 = __floats2half2_rn(RATIO_C*(expf(acc[mt][nt][0]-d0)+EPS_K),
                                               RATIO_C*(expf(acc[mt][nt][1]-d0)+EPS_K));
                __half2 o1 = __floats2half2_rn(RATIO_C*(expf(acc[mt][nt][2]-d1)+EPS_K),
                                               RATIO_C*(expf(acc[mt][nt][3]-d1)+EPS_K));
                *reinterpret_cast<__half2*>(Ch + (long long)grow*ldc + c0)     = o0;
                *reinterpret_cast<__half2*>(Ch + (long long)(grow+8)*ldc + c0) = o1;
            }
        }
        return;
    }

    if (EPI==EPI_KMAX){
        // write dd - diag (fp32), track global max of dd via atomic
        float cm = -3.402823466e38f;
        #pragma unroll
        for (int mt=0; mt<4; ++mt){
            const int r0 = brow + warp_m + mt*16 + g;
            const float d0 = rowscale[r0], d1 = rowscale[r0+8];
            #pragma unroll
            for (int nt=0; nt<4; ++nt){
                const int c0 = bcol + warp_n + nt*8 + 2*t;
                float v00 = acc[mt][nt][0]*alpha, v01 = acc[mt][nt][1]*alpha;
                float v10 = acc[mt][nt][2]*alpha, v11 = acc[mt][nt][3]*alpha;
                cm = fmaxf(cm, fmaxf(fmaxf(v00,v01), fmaxf(v10,v11)));
                float2 o0; o0.x=v00-d0; o0.y=v01-d0;
                float2 o1; o1.x=v10-d1; o1.y=v11-d1;
                *reinterpret_cast<float2*>(Cf + (long long)r0*ldc + c0)     = o0;
                *reinterpret_cast<float2*>(Cf + (long long)(r0+8)*ldc + c0) = o1;
            }
        }
        #pragma unroll
        for (int o=16;o;o>>=1) cm = fmaxf(cm, __shfl_xor_sync(0xffffffffu,cm,o));
        if (lane==0) s_wmax[wid] = cm;
        __syncthreads();
        if (tid==0){
            float m = s_wmax[0];
            #pragma unroll
            for (int w=1; w<THREADS/32; ++w) m = fmaxf(m, s_wmax[w]);
            unsigned b = __float_as_uint(m);
            unsigned u = (b & 0x80000000u) ? ~b : (b | 0x80000000u);
            atomicMax(&g_gmax_u, u);
        }
        return;
    }

    #pragma unroll
    for (int mt=0; mt<4; ++mt){
        const int r0 = brow + warp_m + mt*16 + g;
        const int r1 = r0 + 8;
        float rs0 = 1.f, rs1 = 1.f;
        if (EPI==EPI_ATTN){
            rs0 = rowscale[(long long)z*M + r0];
            rs1 = rowscale[(long long)z*M + r1];
        }
        #pragma unroll
        for (int nt=0; nt<4; ++nt){
            const int c0 = bcol + warp_n + nt*8 + 2*t;
            float v00 = acc[mt][nt][0], v01 = acc[mt][nt][1];
            float v10 = acc[mt][nt][2], v11 = acc[mt][nt][3];
            if (EPI==EPI_BIAS_RES || EPI==EPI_BIAS_GELU || EPI==EPI_QKV){
                const float b0 = bias[c0], b1 = bias[c0+1];
                v00 += b0; v01 += b1; v10 += b0; v11 += b1;
            }
            if (EPI==EPI_BIAS_RES){
                v00 += res[(long long)r0*ldc + c0];   v01 += res[(long long)r0*ldc + c0+1];
                v10 += res[(long long)r1*ldc + c0];   v11 += res[(long long)r1*ldc + c0+1];
            }
            if (EPI==EPI_BIAS_GELU){
                v00 = 0.5f*v00*(1.0f+erff(v00*0.70710678118654752f));
                v01 = 0.5f*v01*(1.0f+erff(v01*0.70710678118654752f));
                v10 = 0.5f*v10*(1.0f+erff(v10*0.70710678118654752f));
                v11 = 0.5f*v11*(1.0f+erff(v11*0.70710678118654752f));
            }
            if (EPI==EPI_ATTN){ v00*=rs0; v01*=rs0; v10*=rs1; v11*=rs1; }

            if (EPI==EPI_QKV){
                const int sel = c0/Dd, cc = c0 - sel*Dd;
                const int h_ = cc>>6, dh_ = cc&63;
                const int b0_ = r0>>12, s0_ = r0&4095;
                const int b1_ = r1>>12, s1_ = r1&4095;
                __half* base = (__half*)Cv + (size_t)sel*NHR*DhD;
                *reinterpret_cast<__half2*>(base + ((((long long)(b0_*Hh+h_))<<12)+s0_)*DhD + dh_) = __floats2half2_rn(v00,v01);
                *reinterpret_cast<__half2*>(base + ((((long long)(b1_*Hh+h_))<<12)+s1_)*DhD + dh_) = __floats2half2_rn(v10,v11);
            } else if (EPI==EPI_ATTN){
                const int bb = z/Hh, hh = z - (z/Hh)*Hh;
                __half* base = (__half*)Cv;
                const long long o0 = ((long long)(bb*Ss + r0))*Dd + hh*64 + c0;
                const long long o1 = ((long long)(bb*Ss + r1))*Dd + hh*64 + c0;
                *reinterpret_cast<__half2*>(base + o0) = __floats2half2_rn(v00,v01);
                *reinterpret_cast<__half2*>(base + o1) = __floats2half2_rn(v10,v11);
            } else if (OUTH){
                *reinterpret_cast<__half2*>(Ch + (long long)r0*ldc + c0) = __floats2half2_rn(v00,v01);
                *reinterpret_cast<__half2*>(Ch + (long long)r1*ldc + c0) = __floats2half2_rn(v10,v11);
            } else {
                float2 o0; o0.x=v00; o0.y=v01;
                float2 o1; o1.x=v10; o1.y=v11;
                *reinterpret_cast<float2*>(Cf + (long long)r0*ldc + c0) = o0;
                *reinterpret_cast<float2*>(Cf + (long long)r1*ldc + c0) = o1;
            }
        }
    }
}

#define SMEM_H128x128 (3*(128+128)*20*4)   // 61440
#define SMEM_H64x256  (3*(64+256)*20*4)    // 76800
#define SMEM_H128x64  (3*(128+64)*20*4)    // 46080

// ---------------- small kernels ----------------
__global__ void reset_kernel(){ g_gmax_u = 0u; }

__global__ void f2h_kernel(const float* __restrict__ s, __half* __restrict__ d, int n4)
{
    const int i = blockIdx.x*256 + threadIdx.x;
    if (i >= n4) return;
    float4 v = reinterpret_cast<const float4*>(s)[i];
    __half2* o = reinterpret_cast<__half2*>(d) + 2*i;
    o[0] = __floats2half2_rn(v.x, v.y);
    o[1] = __floats2half2_rn(v.z, v.w);
}
__global__ void bpack_kernel(const float* bq, const float* bk, const float* bv)
{
    const int i = blockIdx.x*256 + threadIdx.x;
    if (i >= 3*Dd) return;
    const int sel = i/Dd, c = i - sel*Dd;
    g_bqkv[i] = sel==0 ? bq[c] : (sel==1 ? bk[c] : bv[c]);
}

// ---------------- LayerNorm (row=768), half output ----------------
__global__ void ln_kernel(const float* __restrict__ x, const float* __restrict__ g,
                          const float* __restrict__ b, __half* __restrict__ out)
{
    const int row = blockIdx.x;
    const float* xr = x + (long long)row*Dd;
    float v[3]; float s=0.f, ss=0.f;
    #pragma unroll
    for (int i=0;i<3;i++){ v[i]=xr[threadIdx.x + i*256]; s+=v[i]; ss+=v[i]*v[i]; }
    #pragma unroll
    for (int o=16;o;o>>=1){ s+=__shfl_xor_sync(0xffffffffu,s,o); ss+=__shfl_xor_sync(0xffffffffu,ss,o); }
    __shared__ float rs_[8], rss_[8];
    const int lane = threadIdx.x & 31, w = threadIdx.x >> 5;
    if (lane==0){ rs_[w]=s; rss_[w]=ss; }
    __syncthreads();
    s=0.f; ss=0.f;
    #pragma unroll
    for (int i=0;i<8;i++){ s+=rs_[i]; ss+=rss_[i]; }
    const float mu  = s*(1.0f/Dd);
    const float var = ss*(1.0f/Dd) - mu*mu;
    const float rstd = rsqrtf(var + LN_EPS);
    __half* outr = out + (long long)row*Dd;
    #pragma unroll
    for (int i=0;i<3;i++){
        int c = threadIdx.x + i*256;
        outr[c] = __float2half((v[i]-mu)*rstd*g[c] + b[c]);
    }
}

// ---------------- diag: 0.0625 * sum(q^2), half input (warp per row) ----------------
__global__ void diag_kernel(const __half* __restrict__ src, float* __restrict__ dst)
{
    const int lane = threadIdx.x & 31, w = threadIdx.x >> 5;
    const long long row = (long long)blockIdx.x*8 + w;
    __half2 v = reinterpret_cast<const __half2*>(src + row*DhD)[lane];
    float2 f = __half22float2(v);
    float s = f.x*f.x + f.y*f.y;
    #pragma unroll
    for (int o=16;o;o>>=1) s += __shfl_xor_sync(0xffffffffu,s,o);
    if (lane==0) dst[row] = DIAG_C * s;
}

// ---------------- k features: exp(ddm - gmax); fp32 in (already -diag), half out -------
__global__ void expk_kernel(const float* __restrict__ ddm, __half* __restrict__ kph)
{
    const long long i4 = (long long)blockIdx.x*blockDim.x + threadIdx.x;
    const unsigned u = g_gmax_u;
    const float gm = (u & 0x80000000u) ? __uint_as_float(u ^ 0x80000000u)
                                       : __uint_as_float(~u);
    float4 v = reinterpret_cast<const float4*>(ddm)[i4];
    __half2* o = reinterpret_cast<__half2*>(kph) + 2*i4;
    o[0] = __floats2half2_rn(RATIO_C*(expf(v.x-gm)+EPS_K), RATIO_C*(expf(v.y-gm)+EPS_K));
    o[1] = __floats2half2_rn(RATIO_C*(expf(v.z-gm)+EPS_K), RATIO_C*(expf(v.w-gm)+EPS_K));
}

// ---------------- k_sum (two stage), half input ----------------
__global__ void ksum_part_kernel(const __half* __restrict__ kp)
{
    const int bh = blockIdx.x, split = blockIdx.y, m = threadIdx.x;
    const __half* p = kp + ((long long)bh*Ss + (long long)split*512)*Mm + m;
    float s = 0.f;
    for (int i=0;i<512;i++) s += __half2float(p[(long long)i*Mm]);
    g_ksum_part[(bh*8+split)*Mm + m] = s;
}
__global__ void ksum_red_kernel()
{
    const int bh = blockIdx.x, m = threadIdx.x;
    float s = 0.f;
    #pragma unroll
    for (int i=0;i<8;i++) s += g_ksum_part[(bh*8+i)*Mm + m];
    g_ksum[bh*Mm + m] = s;
}

// ---------------- ctx^T[bh][dh][m] = sum_s kp[bh,s,m]*v[bh,s,dh]; half in/out ----------
__global__ void __launch_bounds__(256)
ctx_kernel(const __half* __restrict__ kp, const __half* __restrict__ vh, __half* __restrict__ ctxT)
{
    const int z = blockIdx.z;
    const int mtile = blockIdx.y;
    __shared__ float As[32][64];
    __shared__ float Bs[32][64];
    const int tid = threadIdx.x;
    const int tx = tid % 16;
    const int ty = tid / 16;

    const __half* kpb = kp + (long long)z*Ss*Mm + mtile*64;
    const __half* vhb = vh + (long long)z*Ss*DhD;

    float acc[4][4];
    #pragma unroll
    for (int i=0;i<4;i++)
        #pragma unroll
        for (int j=0;j<4;j++) acc[i][j]=0.f;

    for (int s0=0; s0<Ss; s0+=32){
        #pragma unroll
        for (int l=0;l<2;l++){
            const int idx = tid + l*256;
            const int r = idx >> 4, c = idx & 15;
            const __half2* ka = reinterpret_cast<const __half2*>(kpb + (long long)(s0+r)*Mm + c*4);
            float2 k0 = __half22float2(ka[0]), k1 = __half22float2(ka[1]);
            As[r][c*4+0]=k0.x; As[r][c*4+1]=k0.y; As[r][c*4+2]=k1.x; As[r][c*4+3]=k1.y;
            const __half2* va = reinterpret_cast<const __half2*>(vhb + (long long)(s0+r)*DhD + c*4);
            float2 v0 = __half22float2(va[0]), v1 = __half22float2(va[1]);
            Bs[r][c*4+0]=v0.x; Bs[r][c*4+1]=v0.y; Bs[r][c*4+2]=v1.x; Bs[r][c*4+3]=v1.y;
        }
        __syncthreads();
        #pragma unroll
        for (int k=0;k<32;k++){
            float4 a4 = *reinterpret_cast<const float4*>(&As[k][ty*4]);
            float4 b4 = *reinterpret_cast<const float4*>(&Bs[k][tx*4]);
            float ar[4]={a4.x,a4.y,a4.z,a4.w}, br[4]={b4.x,b4.y,b4.z,b4.w};
            #pragma unroll
            for (int i=0;i<4;i++)
                #pragma unroll
                for (int j=0;j<4;j++) acc[i][j] = fmaf(ar[i], br[j], acc[i][j]);
        }
        __syncthreads();
    }
    #pragma unroll
    for (int i=0;i<4;i++)
        #pragma unroll
        for (int j=0;j<4;j++){
            int m_  = mtile*64 + ty*4 + i;
            int dh_ = tx*4 + j;
            ctxT[(long long)z*DhD*Mm + (long long)dh_*Mm + m_] = __float2half(acc[i][j]);
        }
}

// ---------------- d_inv: half qp, fp32 ksum (warp per row) ----------------
__global__ void dinv_kernel(const __half* __restrict__ qp, float* __restrict__ dinv)
{
    const int lane = threadIdx.x & 31, w = threadIdx.x >> 5;
    const long long row = (long long)blockIdx.x*8 + w;
    const int bh = (int)(row >> 12);
    const __half2* p = reinterpret_cast<const __half2*>(qp + row*Mm);
    const float4* ks = reinterpret_cast<const float4*>(g_ksum + (long long)bh*Mm);
    float s = 0.f;
    #pragma unroll
    for (int h=0; h<2; ++h){
        const int li = lane + h*32;
        float2 a0 = __half22float2(p[2*li]), a1 = __half22float2(p[2*li+1]);
        float4 k4 = ks[li];
        s += a0.x*k4.x + a0.y*k4.y + a1.x*k4.z + a1.y*k4.w;
    }
    #pragma unroll
    for (int o=16;o;o>>=1) s += __shfl_xor_sync(0xffffffffu,s,o);
    if (lane==0) dinv[row] = 1.0f/s;
}

// ---------------- host ----------------
extern "C" void kernel_launch(void* const* d_in, const int* in_sizes, int n_in,
                              void* d_out, int out_size)
{
    const float* x    = (const float*)d_in[0];
    const float* proj = (const float*)d_in[1];
    const float* wq   = (const float*)d_in[2];
    const float* bq   = (const float*)d_in[3];
    const float* wk   = (const float*)d_in[4];
    const float* bk   = (const float*)d_in[5];
    const float* wv   = (const float*)d_in[6];
    const float* bv   = (const float*)d_in[7];
    const float* wo   = (const float*)d_in[8];
    const float* bo   = (const float*)d_in[9];
    const float* ln1g = (const float*)d_in[10];
    const float* ln1b = (const float*)d_in[11];
    const float* ln2g = (const float*)d_in[12];
    const float* ln2b = (const float*)d_in[13];
    const float* w1   = (const float*)d_in[14];
    const float* b1   = (const float*)d_in[15];
    const float* w2   = (const float*)d_in[16];
    const float* b2   = (const float*)d_in[17];
    float* out = (float*)d_out;

    void *p;
    __half *wqkvh, *woh, *w1h, *w2h, *projh, *h1h, *qkvh, *qph, *kph, *midh, *ctxTh, *attn2h;
    float *bqkv, *ddk, *x2, *dq, *dk, *dinv;
    cudaGetSymbolAddress(&p, g_wqkvh);  wqkvh  = (__half*)p;
    cudaGetSymbolAddress(&p, g_bqkv);   bqkv   = (float*)p;
    cudaGetSymbolAddress(&p, g_woh);    woh    = (__half*)p;
    cudaGetSymbolAddress(&p, g_w1h);    w1h    = (__half*)p;
    cudaGetSymbolAddress(&p, g_w2h);    w2h    = (__half*)p;
    cudaGetSymbolAddress(&p, g_projh);  projh  = (__half*)p;
    cudaGetSymbolAddress(&p, g_h1h);    h1h    = (__half*)p;
    cudaGetSymbolAddress(&p, g_qkvh);   qkvh   = (__half*)p;
    cudaGetSymbolAddress(&p, g_ddk);    ddk    = (float*)p;
    cudaGetSymbolAddress(&p, g_qph);    qph    = (__half*)p;
    cudaGetSymbolAddress(&p, g_kph);    kph    = (__half*)p;
    cudaGetSymbolAddress(&p, g_midh);   midh   = (__half*)p;
    cudaGetSymbolAddress(&p, g_ctxTh);  ctxTh  = (__half*)p;
    cudaGetSymbolAddress(&p, g_attn2h); attn2h = (__half*)p;
    cudaGetSymbolAddress(&p, g_x2);     x2     = (float*)p;
    cudaGetSymbolAddress(&p, g_diagq);  dq     = (float*)p;
    cudaGetSymbolAddress(&p, g_diagk);  dk     = (float*)p;
    cudaGetSymbolAddress(&p, g_dinv);   dinv   = (float*)p;

    __half* qh = qkvh;
    __half* kh = qkvh + (size_t)NHR*DhD;
    __half* vh = qkvh + 2*(size_t)NHR*DhD;

    cudaFuncSetAttribute(hgemm<128,128,EPI_QKV,true>,       cudaFuncAttributeMaxDynamicSharedMemorySize, SMEM_H128x128);
    cudaFuncSetAttribute(hgemm<64,256,EPI_QFEAT,true>,      cudaFuncAttributeMaxDynamicSharedMemorySize, SMEM_H64x256);
    cudaFuncSetAttribute(hgemm<128,128,EPI_KMAX,false>,     cudaFuncAttributeMaxDynamicSharedMemorySize, SMEM_H128x128);
    cudaFuncSetAttribute(hgemm<128,64,EPI_ATTN,true>,       cudaFuncAttributeMaxDynamicSharedMemorySize, SMEM_H128x64);
    cudaFuncSetAttribute(hgemm<128,128,EPI_BIAS_RES,false>, cudaFuncAttributeMaxDynamicSharedMemorySize, SMEM_H128x128);
    cudaFuncSetAttribute(hgemm<128,128,EPI_BIAS_GELU,true>, cudaFuncAttributeMaxDynamicSharedMemorySize, SMEM_H128x128);

    // 0. resets + weight conversion
    reset_kernel<<<1,1>>>();
    f2h_kernel<<<576, 256>>>(wq, wqkvh,            Dd*Dd/4);
    f2h_kernel<<<576, 256>>>(wk, wqkvh +   Dd*Dd,  Dd*Dd/4);
    f2h_kernel<<<576, 256>>>(wv, wqkvh + 2*Dd*Dd,  Dd*Dd/4);
    f2h_kernel<<<576, 256>>>(wo, woh,              Dd*Dd/4);
    f2h_kernel<<<2304,256>>>(w1, w1h,              FFH*Dd/4);
    f2h_kernel<<<2304,256>>>(w2, w2h,              Dd*FFH/4);
    f2h_kernel<<<16,  256>>>(proj, projh,          Mm*DhD/4);
    bpack_kernel<<<9, 256>>>(bq, bk, bv);

    // 1. LN1 -> half
    ln_kernel<<<NROWS, 256>>>(x, ln1g, ln1b, h1h);

    // 2. fused QKV (N=2304)
    hgemm<128,128,EPI_QKV,true><<<dim3(18,128,1),256,SMEM_H128x128>>>(
        h1h,Dd,0, wqkvh,Dd,0, qkvh,DhD,0, NROWS,3*Dd,Dd, bqkv,nullptr,nullptr,0.f);

    // 3. diag terms
    diag_kernel<<<NHR/8, 256>>>(qh, dq);
    diag_kernel<<<NHR/8, 256>>>(kh, dk);

    // 4a. q features fused: GEMM + rowmax + exp -> qph
    hgemm<64,256,EPI_QFEAT,true><<<dim3(1,NHR/64,1),256,SMEM_H64x256>>>(
        qh,DhD,0, projh,DhD,0, qph,Mm,0, NHR,Mm,DhD, nullptr,nullptr,dq,NORM_C);
    // 4b. k dd fused: GEMM + (dd-diag) + global max atomic
    hgemm<128,128,EPI_KMAX,false><<<dim3(2,NHR/128,1),256,SMEM_H128x128>>>(
        kh,DhD,0, projh,DhD,0, ddk,Mm,0, NHR,Mm,DhD, nullptr,nullptr,dk,NORM_C);

    // 5. k features exp -> kph
    expk_kernel<<<(NHR*(Mm/4))/256, 256>>>(ddk, kph);

    // 6. k_sum
    ksum_part_kernel<<<dim3(NBH,8,1), 256>>>(kph);
    ksum_red_kernel<<<NBH, 256>>>();

    // 7. ctx^T (half)
    ctx_kernel<<<dim3(1,4,NBH), 256>>>(kph, vh, ctxTh);

    // 8. d_inv
    dinv_kernel<<<NHR/8, 256>>>(qph, dinv);

    // 9. attn = d_inv * (qp @ ctx), fused transpose -> attn2h [b,s,D]
    hgemm<128,64,EPI_ATTN,true><<<dim3(1,Ss/128,NBH),128,SMEM_H128x64>>>(
        qph,Mm,(long long)Ss*Mm, ctxTh,Mm,(long long)DhD*Mm, attn2h,DhD,0,
        Ss,DhD,Mm, nullptr,nullptr,dinv,0.f);

    // 10. x2 = x + attn @ wo^T + bo (fp32)
    hgemm<128,128,EPI_BIAS_RES,false><<<dim3(6,128,1),256,SMEM_H128x128>>>(
        attn2h,Dd,0, woh,Dd,0, x2,Dd,0, NROWS,Dd,Dd, bo,x,nullptr,0.f);

    // 11. LN2 -> half
    ln_kernel<<<NROWS, 256>>>(x2, ln2g, ln2b, h1h);

    // 12. mid = gelu(h1 @ w1^T + b1) -> half
    hgemm<128,128,EPI_BIAS_GELU,true><<<dim3(FFH/128,128,1),256,SMEM_H128x128>>>(
        h1h,Dd,0, w1h,Dd,0, midh,FFH,0, NROWS,FFH,Dd, b1,nullptr,nullptr,0.f);

    // 13. out = x2 + mid @ w2^T + b2 (fp32)
    hgemm<128,128,EPI_BIAS_RES,false><<<dim3(6,128,1),256,SMEM_H128x128>>>(
        midh,FFH,0, w2h,FFH,0, out,Dd,0, NROWS,Dd,FFH, b2,x2,nullptr,0.f);
}

// round 8
// speedup vs baseline: 6.0082x; 1.2214x over previous
#include <cuda_runtime.h>
#include <cuda_fp16.h>
#include <math.h>
#include <stdint.h>

// ---------------- problem constants ----------------
#define Bb   4
#define Ss   4096
#define Dd   768
#define Hh   12
#define Mm   256
#define DhD  64
#define NROWS (Bb*Ss)        // 16384
#define NBH   (Bb*Hh)        // 48
#define NHR   (NBH*Ss)       // 196608
#define FFH   (4*Dd)         // 3072

#define NORM_C   0.35355339059327373f
#define RATIO_C  0.0625f
#define DIAG_C   0.0625f
#define EPS_K    1e-4f
#define LN_EPS   1e-5f

// ---------------- scratch (device globals; allocation-free) ----------------
__device__ __half g_wqkvh[3*Dd*Dd];
__device__ float  g_bqkv[3*Dd];
__device__ __half g_woh[Dd*Dd];
__device__ __half g_w1h[FFH*Dd];
__device__ __half g_w2h[Dd*FFH];
__device__ __half g_projh[Mm*DhD];
__device__ __half g_h1h[NROWS*Dd];
__device__ __half g_qkvh[3*(size_t)NHR*DhD];      // q,k,v in [sel][b,h,s,dh]
__device__ __half g_qph[(size_t)NHR*Mm];
__device__ __half g_kph[(size_t)NHR*Mm];          // stored exp(dd - rowmax)
__device__ __half g_midh[(size_t)NROWS*FFH];
__device__ __half g_ctxTh[NBH*DhD*Mm];            // [bh][dh][m]
__device__ __half g_attn2h[(size_t)NROWS*Dd];     // [b,s,D]
__device__ float  g_x2[NROWS*Dd];
__device__ float  g_diag[2*NHR];                  // [q rows | k rows]
__device__ float  g_rowf[NHR];                    // rowmax(dd_k) - diag_k
__device__ float  g_ksum[NBH*Mm];
__device__ float  g_dinv[NHR];
__device__ unsigned g_gmax_u;

// ---------------- epilogue modes ----------------
enum { EPI_BIAS_RES=1, EPI_BIAS_GELU=2, EPI_QKV=5, EPI_QFEAT=6, EPI_KFEAT=7, EPI_ATTN=8 };

__device__ __forceinline__ void cpa16(uint32_t smem_dst, const void* gsrc){
    asm volatile("cp.async.cg.shared.global [%0], [%1], 16;" :: "r"(smem_dst), "l"(gsrc));
}
#define CP_COMMIT() asm volatile("cp.async.commit_group;" ::: "memory")
#define CP_WAIT1()  asm volatile("cp.async.wait_group 1;" ::: "memory")

__device__ __forceinline__ uint32_t smem_u32(const void* p){
    uint32_t a;
    asm("{ .reg .u64 t; cvta.to.shared.u64 t, %1; cvt.u32.u64 %0, t; }" : "=r"(a) : "l"(p));
    return a;
}

__device__ __forceinline__ void mma_f16(float* d, const uint32_t* a, const uint32_t* b){
    asm volatile("mma.sync.aligned.m16n8k16.row.col.f32.f16.f16.f32 "
        "{%0,%1,%2,%3}, {%4,%5,%6,%7}, {%8,%9}, {%0,%1,%2,%3};"
        : "+f"(d[0]),"+f"(d[1]),"+f"(d[2]),"+f"(d[3])
        : "r"(a[0]),"r"(a[1]),"r"(a[2]),"r"(a[3]), "r"(b[0]),"r"(b[1]));
}
#define LDSM4(r0,r1,r2,r3,addr) \
    asm volatile("ldmatrix.sync.aligned.m8n8.x4.shared.b16 {%0,%1,%2,%3}, [%4];" \
        : "=r"(r0),"=r"(r1),"=r"(r2),"=r"(r3) : "r"(addr))
#define LDSM4T(r0,r1,r2,r3,addr) \
    asm volatile("ldmatrix.sync.aligned.m8n8.x4.trans.shared.b16 {%0,%1,%2,%3}, [%4];" \
        : "=r"(r0),"=r"(r1),"=r"(r2),"=r"(r3) : "r"(addr))

__device__ __forceinline__ float gmax_decode(unsigned u){
    return (u & 0x80000000u) ? __uint_as_float(u ^ 0x80000000u) : __uint_as_float(~u);
}

// ================= fp16 NT GEMM: mma.sync m16n8k16 + cp.async(3-stage) + ldmatrix ======
template<int BM,int BN,int EPI,bool OUTH>
__global__ void __launch_bounds__(32*(BM/64)*(BN/32), 2)
hgemm(const __half* __restrict__ A, int lda, long long strA,
      const __half* __restrict__ B, int ldb, long long strB,
      void* __restrict__ Cv, int ldc, long long strC,
      int M, int N, int K,
      const float* __restrict__ bias,
      const float* __restrict__ res,
      const float* __restrict__ rowscale,
      float alpha)
{
    constexpr int WY = BM/64, WX = BN/32, THREADS = 32*WY*WX;
    constexpr int LDKW = 20;
    constexpr int AW = BM*LDKW;
    constexpr int SW = (BM+BN)*LDKW;
    constexpr int ALD = (BM*4)/THREADS;
    constexpr int BLD = (BN*4)/THREADS;

    extern __shared__ uint32_t sh[];
    const uint32_t smb = smem_u32(sh);

    const int z = blockIdx.z;
    A += (long long)z*strA;  B += (long long)z*strB;
    float*  Cf = (float*)Cv  + (long long)z*strC;
    __half* Ch = (__half*)Cv + (long long)z*strC;

    const int brow = blockIdx.y*BM;
    const int bcol = blockIdx.x*BN;
    const int tid  = threadIdx.x;
    const int wid  = tid >> 5;
    const int lane = tid & 31;
    const int wx   = wid % WX, wy = wid / WX;
    const int warp_m = wy*64, warp_n = wx*32;
    const int g = lane >> 2, t = lane & 3;

    const uint32_t aoff = (uint32_t)(((warp_m + (lane&15))*LDKW + (lane>>4)*4))*4u;
    const uint32_t boff = (uint32_t)((AW + (warp_n + (lane>>4)*8 + (lane&7))*LDKW + ((lane>>3)&1)*4))*4u;

    float acc[4][4][4];
    #pragma unroll
    for (int i=0;i<4;i++)
        #pragma unroll
        for (int j=0;j<4;j++)
            #pragma unroll
            for (int u=0;u<4;u++) acc[i][j][u]=0.f;

    const int nc = K >> 5;

    #define HISSUE(chunk) do{                                                  \
        const uint32_t bA_ = smb + (uint32_t)(((chunk)%3)*SW)*4u;              \
        const uint32_t bB_ = bA_ + (uint32_t)AW*4u;                            \
        const __half* Ap_ = A + (long long)brow*lda + (chunk)*32;              \
        const __half* Bp_ = B + (long long)bcol*ldb + (chunk)*32;              \
        _Pragma("unroll")                                                      \
        for (int l=0;l<ALD;l++){                                               \
            const int idx = tid + l*THREADS, r = idx>>2, c4 = idx&3;           \
            cpa16(bA_ + (uint32_t)(r*LDKW + c4*4)*4u,                          \
                  Ap_ + (long long)r*lda + c4*8);                              \
        }                                                                      \
        _Pragma("unroll")                                                      \
        for (int l=0;l<BLD;l++){                                               \
            const int idx = tid + l*THREADS, r = idx>>2, c4 = idx&3;           \
            cpa16(bB_ + (uint32_t)(r*LDKW + c4*4)*4u,                          \
                  Bp_ + (long long)r*ldb + c4*8);                              \
        }                                                                      \
    }while(0)

    if (0 < nc) HISSUE(0);
    CP_COMMIT();
    if (1 < nc) HISSUE(1);
    CP_COMMIT();

    for (int i=0; i<nc; ++i){
        CP_WAIT1();
        __syncthreads();
        if (i+2 < nc) HISSUE(i+2);
        CP_COMMIT();

        const uint32_t stg = smb + (uint32_t)((i%3)*SW)*4u;

        #pragma unroll
        for (int kk=0; kk<2; ++kk){
            uint32_t af[4][4], bf[4][2];
            #pragma unroll
            for (int mt=0; mt<4; ++mt)
                LDSM4(af[mt][0],af[mt][1],af[mt][2],af[mt][3],
                      stg + aoff + (uint32_t)((mt*16*LDKW + kk*8))*4u);
            LDSM4(bf[0][0],bf[0][1],bf[1][0],bf[1][1],
                  stg + boff + (uint32_t)(kk*8)*4u);
            LDSM4(bf[2][0],bf[2][1],bf[3][0],bf[3][1],
                  stg + boff + (uint32_t)((16*LDKW + kk*8))*4u);
            #pragma unroll
            for (int mt=0; mt<4; ++mt)
                #pragma unroll
                for (int nt=0; nt<4; ++nt)
                    mma_f16(acc[mt][nt], af[mt], bf[nt]);
        }
        // no trailing sync: top-of-loop barrier protects stage reuse
    }
    #undef HISSUE

    // ================= epilogues =================
    if (EPI==EPI_QFEAT || EPI==EPI_KFEAT){
        // BM=64, BN=256(=Mm): full feature row in CTA. rowmax + exp -> half.
        float mxs[4][2];
        #pragma unroll
        for (int mt=0; mt<4; ++mt){
            float m0=-3.402823466e38f, m1=m0;
            #pragma unroll
            for (int nt=0; nt<4; ++nt){
                #pragma unroll
                for (int u=0;u<4;u++) acc[mt][nt][u]*=alpha;
                m0 = fmaxf(m0, fmaxf(acc[mt][nt][0], acc[mt][nt][1]));
                m1 = fmaxf(m1, fmaxf(acc[mt][nt][2], acc[mt][nt][3]));
            }
            m0 = fmaxf(m0, __shfl_xor_sync(0xffffffffu,m0,1));
            m0 = fmaxf(m0, __shfl_xor_sync(0xffffffffu,m0,2));
            m1 = fmaxf(m1, __shfl_xor_sync(0xffffffffu,m1,1));
            m1 = fmaxf(m1, __shfl_xor_sync(0xffffffffu,m1,2));
            mxs[mt][0]=m0; mxs[mt][1]=m1;
        }
        __syncthreads();
        float* red = (float*)sh;               // [64][8]
        if (t==0){
            #pragma unroll
            for (int mt=0; mt<4; ++mt){
                red[(mt*16+g)*8 + wid]   = mxs[mt][0];
                red[(mt*16+8+g)*8 + wid] = mxs[mt][1];
            }
        }
        __syncthreads();
        #pragma unroll
        for (int mt=0; mt<4; ++mt){
            const int grow = brow + mt*16 + g;
            float mx0 = red[(mt*16+g)*8], mx1 = red[(mt*16+8+g)*8];
            #pragma unroll
            for (int w=1; w<8; ++w){
                mx0 = fmaxf(mx0, red[(mt*16+g)*8+w]);
                mx1 = fmaxf(mx1, red[(mt*16+8+g)*8+w]);
            }
            mxs[mt][0]=mx0; mxs[mt][1]=mx1;
            float d0, d1;
            if (EPI==EPI_QFEAT){ d0 = rowscale[grow] + mx0; d1 = rowscale[grow+8] + mx1; }
            else               { d0 = mx0;                  d1 = mx1; }
            #pragma unroll
            for (int nt=0; nt<4; ++nt){
                const int c0 = warp_n + nt*8 + 2*t;
                __half2 o0, o1;
                if (EPI==EPI_QFEAT){
                    o0 = __floats2half2_rn(RATIO_C*(expf(acc[mt][nt][0]-d0)+EPS_K),
                                           RATIO_C*(expf(acc[mt][nt][1]-d0)+EPS_K));
                    o1 = __floats2half2_rn(RATIO_C*(expf(acc[mt][nt][2]-d1)+EPS_K),
                                           RATIO_C*(expf(acc[mt][nt][3]-d1)+EPS_K));
                } else {
                    o0 = __floats2half2_rn(expf(acc[mt][nt][0]-d0), expf(acc[mt][nt][1]-d0));
                    o1 = __floats2half2_rn(expf(acc[mt][nt][2]-d1), expf(acc[mt][nt][3]-d1));
                }
                *reinterpret_cast<__half2*>(Ch + (long long)grow*ldc + c0)     = o0;
                *reinterpret_cast<__half2*>(Ch + (long long)(grow+8)*ldc + c0) = o1;
            }
            if (EPI==EPI_KFEAT && wid==0 && t==0){
                float* rowf = const_cast<float*>(res);
                rowf[grow]   = mx0 - rowscale[grow];
                rowf[grow+8] = mx1 - rowscale[grow+8];
            }
        }
        if (EPI==EPI_KFEAT && wid==0){
            float bm = fmaxf(fmaxf(mxs[0][0],mxs[0][1]), fmaxf(mxs[1][0],mxs[1][1]));
            bm = fmaxf(bm, fmaxf(fmaxf(mxs[2][0],mxs[2][1]), fmaxf(mxs[3][0],mxs[3][1])));
            #pragma unroll
            for (int o=16;o;o>>=1) bm = fmaxf(bm, __shfl_xor_sync(0xffffffffu,bm,o));
            if (lane==0){
                unsigned b = __float_as_uint(bm);
                unsigned u = (b & 0x80000000u) ? ~b : (b | 0x80000000u);
                atomicMax(&g_gmax_u, u);
            }
        }
        return;
    }

    #pragma unroll
    for (int mt=0; mt<4; ++mt){
        const int r0 = brow + warp_m + mt*16 + g;
        const int r1 = r0 + 8;
        float rs0 = 1.f, rs1 = 1.f;
        if (EPI==EPI_ATTN){
            rs0 = rowscale[(long long)z*M + r0];
            rs1 = rowscale[(long long)z*M + r1];
        }
        #pragma unroll
        for (int nt=0; nt<4; ++nt){
            const int c0 = bcol + warp_n + nt*8 + 2*t;
            float v00 = acc[mt][nt][0], v01 = acc[mt][nt][1];
            float v10 = acc[mt][nt][2], v11 = acc[mt][nt][3];
            if (EPI==EPI_BIAS_RES || EPI==EPI_BIAS_GELU || EPI==EPI_QKV){
                const float b0 = bias[c0], b1 = bias[c0+1];
                v00 += b0; v01 += b1; v10 += b0; v11 += b1;
            }
            if (EPI==EPI_BIAS_RES){
                v00 += res[(long long)r0*ldc + c0];   v01 += res[(long long)r0*ldc + c0+1];
                v10 += res[(long long)r1*ldc + c0];   v11 += res[(long long)r1*ldc + c0+1];
            }
            if (EPI==EPI_BIAS_GELU){
                v00 = 0.5f*v00*(1.0f+erff(v00*0.70710678118654752f));
                v01 = 0.5f*v01*(1.0f+erff(v01*0.70710678118654752f));
                v10 = 0.5f*v10*(1.0f+erff(v10*0.70710678118654752f));
                v11 = 0.5f*v11*(1.0f+erff(v11*0.70710678118654752f));
            }
            if (EPI==EPI_ATTN){ v00*=rs0; v01*=rs0; v10*=rs1; v11*=rs1; }

            if (EPI==EPI_QKV){
                const int sel = c0/Dd, cc = c0 - sel*Dd;
                const int h_ = cc>>6, dh_ = cc&63;
                const int b0_ = r0>>12, s0_ = r0&4095;
                const int b1_ = r1>>12, s1_ = r1&4095;
                __half* base = (__half*)Cv + (size_t)sel*NHR*DhD;
                *reinterpret_cast<__half2*>(base + ((((long long)(b0_*Hh+h_))<<12)+s0_)*DhD + dh_) = __floats2half2_rn(v00,v01);
                *reinterpret_cast<__half2*>(base + ((((long long)(b1_*Hh+h_))<<12)+s1_)*DhD + dh_) = __floats2half2_rn(v10,v11);
            } else if (EPI==EPI_ATTN){
                const int bb = z/Hh, hh = z - (z/Hh)*Hh;
                __half* base = (__half*)Cv;
                const long long o0 = ((long long)(bb*Ss + r0))*Dd + hh*64 + c0;
                const long long o1 = ((long long)(bb*Ss + r1))*Dd + hh*64 + c0;
                *reinterpret_cast<__half2*>(base + o0) = __floats2half2_rn(v00,v01);
                *reinterpret_cast<__half2*>(base + o1) = __floats2half2_rn(v10,v11);
            } else if (OUTH){
                *reinterpret_cast<__half2*>(Ch + (long long)r0*ldc + c0) = __floats2half2_rn(v00,v01);
                *reinterpret_cast<__half2*>(Ch + (long long)r1*ldc + c0) = __floats2half2_rn(v10,v11);
            } else {
                float2 o0; o0.x=v00; o0.y=v01;
                float2 o1; o1.x=v10; o1.y=v11;
                *reinterpret_cast<float2*>(Cf + (long long)r0*ldc + c0) = o0;
                *reinterpret_cast<float2*>(Cf + (long long)r1*ldc + c0) = o1;
            }
        }
    }
}

#define SMEM_H128x128 (3*(128+128)*20*4)   // 61440
#define SMEM_H64x256  (3*(64+256)*20*4)    // 76800
#define SMEM_H128x64  (3*(128+64)*20*4)    // 46080

// ================ ctx TN mma kernel: ctxT[dh][m] = sum_s kp[s][m]*v[s][dh] =============
// kp rebuilt from stored exp: kp = RATIO*exp(rowf[s]-gmax)*stored + RATIO*eps.
// Also fuses ksum[m] = sum_s kp[s][m]. grid (2 ntiles, 48 bh), 256 threads.
#define CTX_LDV 36
#define CTX_LDP 68
#define CTX_VW  (32*CTX_LDV)
#define CTX_PW  (32*CTX_LDP)
#define SMEM_CTX (3*(CTX_VW+CTX_PW)*4)     // 39936

__global__ void __launch_bounds__(256, 2)
ctx_mma(const __half* __restrict__ kpe, const __half* __restrict__ vh,
        const float* __restrict__ rowf,
        __half* __restrict__ ctxT, float* __restrict__ ksum)
{
    extern __shared__ uint32_t sh[];
    const uint32_t smb = smem_u32(sh);
    const uint32_t pbase = smb + (uint32_t)(3*CTX_VW)*4u;

    const int z = blockIdx.y;
    const int ntile = blockIdx.x;
    const int tid = threadIdx.x, wid = tid>>5, lane = tid&31;
    const int wx = wid & 3, wy = wid >> 2;      // WX=4, WY=2
    const int warp_m = wy*32;                    // dh
    const int warp_n = wx*32;                    // m within tile
    const int g = lane>>2, t = lane&3;
    const int quad = lane>>3, r8 = lane&7;

    const __half* kpb = kpe + (long long)z*Ss*Mm + ntile*128;
    const __half* vhb = vh  + (long long)z*Ss*DhD;
    const float*  rfb = rowf + (long long)z*Ss;

    const float gmax = gmax_decode(g_gmax_u);
    const float epsr = RATIO_C*EPS_K;

    // ldmatrix lane offsets (words)
    const uint32_t a_off0 = (uint32_t)((r8 + ((quad>>1)&1)*8)*CTX_LDV + (warp_m + (quad&1)*8)/2);
    const uint32_t b_off0 = (uint32_t)((r8 + (quad&1)*8)*CTX_LDP + (warp_n + (quad>>1)*8)/2);

    const int srow = tid >> 3;     // 0..31
    const int c8   = tid & 7;      // 16-half group

    float acc[2][4][4];
    #pragma unroll
    for (int i=0;i<2;i++)
        #pragma unroll
        for (int j=0;j<4;j++)
            #pragma unroll
            for (int u=0;u<4;u++) acc[i][j][u]=0.f;
    float ks[16];
    #pragma unroll
    for (int j=0;j<16;j++) ks[j]=0.f;

    #define VISSUE(c) do{ \
        const uint32_t bV = smb + (uint32_t)(((c)%3)*CTX_VW)*4u; \
        cpa16(bV + (uint32_t)(srow*CTX_LDV + c8*4)*4u, \
              vhb + (long long)((c)*32 + srow)*DhD + c8*8); \
    }while(0)

    uint4 cur0, cur1; float curf;
    {
        const __half* pp = kpb + (long long)srow*Mm + c8*16;
        cur0 = *reinterpret_cast<const uint4*>(pp);
        cur1 = *reinterpret_cast<const uint4*>(pp+8);
        curf = rfb[srow];
    }
    VISSUE(0); CP_COMMIT();
    VISSUE(1); CP_COMMIT();

    for (int i=0; i<Ss/32; ++i){
        // stage kp chunk i (scaled) into stage i%3
        {
            const float As = RATIO_C*expf(curf - gmax);
            uint32_t rw[8] = {cur0.x,cur0.y,cur0.z,cur0.w,cur1.x,cur1.y,cur1.z,cur1.w};
            uint32_t ow[8];
            #pragma unroll
            for (int j=0;j<8;j++){
                float2 f = __half22float2(*reinterpret_cast<__half2*>(&rw[j]));
                f.x = fmaf(f.x, As, epsr);
                f.y = fmaf(f.y, As, epsr);
                __half2 h = __floats2half2_rn(f.x, f.y);
                float2 fr = __half22float2(h);        // rounded, for consistent ksum
                ks[2*j]   += fr.x;
                ks[2*j+1] += fr.y;
                ow[j] = *reinterpret_cast<uint32_t*>(&h);
            }
            const uint32_t bP = pbase + (uint32_t)((i%3)*CTX_PW)*4u
                              + (uint32_t)(srow*CTX_LDP + c8*8)*4u;
            uint4 s0 = {ow[0],ow[1],ow[2],ow[3]};
            uint4 s1 = {ow[4],ow[5],ow[6],ow[7]};
            *reinterpret_cast<uint4*>((char*)sh + (bP - smb))      = s0;
            *reinterpret_cast<uint4*>((char*)sh + (bP - smb) + 16) = s1;
        }
        CP_WAIT1();
        __syncthreads();
        if (i+2 < Ss/32) VISSUE(i+2);
        CP_COMMIT();
        if (i+1 < Ss/32){
            const __half* pp = kpb + (long long)((i+1)*32 + srow)*Mm + c8*16;
            cur0 = *reinterpret_cast<const uint4*>(pp);
            cur1 = *reinterpret_cast<const uint4*>(pp+8);
            curf = rfb[(i+1)*32 + srow];
        }

        const uint32_t vstg = smb + (uint32_t)((i%3)*CTX_VW)*4u;
        const uint32_t pstg = pbase + (uint32_t)((i%3)*CTX_PW)*4u;

        #pragma unroll
        for (int kk=0; kk<2; ++kk){
            uint32_t af[2][4], bf[4][2];
            #pragma unroll
            for (int mt=0; mt<2; ++mt)
                LDSM4T(af[mt][0],af[mt][1],af[mt][2],af[mt][3],
                       vstg + (a_off0 + (uint32_t)(kk*16*CTX_LDV + mt*8))*4u);
            #pragma unroll
            for (int pp2=0; pp2<2; ++pp2)
                LDSM4T(bf[2*pp2][0],bf[2*pp2][1],bf[2*pp2+1][0],bf[2*pp2+1][1],
                       pstg + (b_off0 + (uint32_t)(kk*16*CTX_LDP + pp2*8))*4u);
            #pragma unroll
            for (int mt=0; mt<2; ++mt)
                #pragma unroll
                for (int nt=0; nt<4; ++nt)
                    mma_f16(acc[mt][nt], af[mt], bf[nt]);
        }
    }
    #undef VISSUE

    // ctx store (half): rows = dh, cols = m
    #pragma unroll
    for (int mt=0; mt<2; ++mt){
        const int dh0 = warp_m + mt*16 + g;
        const int dh1 = dh0 + 8;
        #pragma unroll
        for (int nt=0; nt<4; ++nt){
            const int col = ntile*128 + warp_n + nt*8 + 2*t;
            *reinterpret_cast<__half2*>(ctxT + (long long)z*DhD*Mm + (long long)dh0*Mm + col)
                = __floats2half2_rn(acc[mt][nt][0], acc[mt][nt][1]);
            *reinterpret_cast<__half2*>(ctxT + (long long)z*DhD*Mm + (long long)dh1*Mm + col)
                = __floats2half2_rn(acc[mt][nt][2], acc[mt][nt][3]);
        }
    }

    // ksum reduction
    __syncthreads();
    float* red = (float*)sh;                // [32][128]
    #pragma unroll
    for (int j=0;j<16;j++) red[srow*128 + c8*16 + j] = ks[j];
    __syncthreads();
    if (tid < 128){
        float s = 0.f;
        #pragma unroll
        for (int r=0;r<32;r++) s += red[r*128 + tid];
        ksum[z*Mm + ntile*128 + tid] = s;
    }
}

// ---------------- small kernels ----------------
__global__ void reset_kernel(){ g_gmax_u = 0u; }

__global__ void f2h_kernel(const float* __restrict__ s, __half* __restrict__ d, int n4)
{
    const int i = blockIdx.x*256 + threadIdx.x;
    if (i >= n4) return;
    float4 v = reinterpret_cast<const float4*>(s)[i];
    __half2* o = reinterpret_cast<__half2*>(d) + 2*i;
    o[0] = __floats2half2_rn(v.x, v.y);
    o[1] = __floats2half2_rn(v.z, v.w);
}
__global__ void bpack_kernel(const float* bq, const float* bk, const float* bv)
{
    const int i = blockIdx.x*256 + threadIdx.x;
    if (i >= 3*Dd) return;
    const int sel = i/Dd, c = i - sel*Dd;
    g_bqkv[i] = sel==0 ? bq[c] : (sel==1 ? bk[c] : bv[c]);
}

// ---------------- LayerNorm (row=768), half output ----------------
__global__ void ln_kernel(const float* __restrict__ x, const float* __restrict__ g,
                          const float* __restrict__ b, __half* __restrict__ out)
{
    const int row = blockIdx.x;
    const float* xr = x + (long long)row*Dd;
    float v[3]; float s=0.f, ss=0.f;
    #pragma unroll
    for (int i=0;i<3;i++){ v[i]=xr[threadIdx.x + i*256]; s+=v[i]; ss+=v[i]*v[i]; }
    #pragma unroll
    for (int o=16;o;o>>=1){ s+=__shfl_xor_sync(0xffffffffu,s,o); ss+=__shfl_xor_sync(0xffffffffu,ss,o); }
    __shared__ float rs_[8], rss_[8];
    const int lane = threadIdx.x & 31, w = threadIdx.x >> 5;
    if (lane==0){ rs_[w]=s; rss_[w]=ss; }
    __syncthreads();
    s=0.f; ss=0.f;
    #pragma unroll
    for (int i=0;i<8;i++){ s+=rs_[i]; ss+=rss_[i]; }
    const float mu  = s*(1.0f/Dd);
    const float var = ss*(1.0f/Dd) - mu*mu;
    const float rstd = rsqrtf(var + LN_EPS);
    __half* outr = out + (long long)row*Dd;
    #pragma unroll
    for (int i=0;i<3;i++){
        int c = threadIdx.x + i*256;
        outr[c] = __float2half((v[i]-mu)*rstd*g[c] + b[c]);
    }
}

// ---------------- diag: 0.0625 * sum(x^2) over 64 halfs (warp per row), q|k fused ------
__global__ void diag_kernel(const __half* __restrict__ src, float* __restrict__ dst)
{
    const int lane = threadIdx.x & 31, w = threadIdx.x >> 5;
    const long long row = (long long)blockIdx.x*8 + w;
    __half2 v = reinterpret_cast<const __half2*>(src + row*DhD)[lane];
    float2 f = __half22float2(v);
    float s = f.x*f.x + f.y*f.y;
    #pragma unroll
    for (int o=16;o;o>>=1) s += __shfl_xor_sync(0xffffffffu,s,o);
    if (lane==0) dst[row] = DIAG_C * s;
}

// ---------------- d_inv: half qp, fp32 ksum (warp per row) ----------------
__global__ void dinv_kernel(const __half* __restrict__ qp, float* __restrict__ dinv)
{
    const int lane = threadIdx.x & 31, w = threadIdx.x >> 5;
    const long long row = (long long)blockIdx.x*8 + w;
    const int bh = (int)(row >> 12);
    const __half2* p = reinterpret_cast<const __half2*>(qp + row*Mm);
    const float4* ks = reinterpret_cast<const float4*>(g_ksum + (long long)bh*Mm);
    float s = 0.f;
    #pragma unroll
    for (int h=0; h<2; ++h){
        const int li = lane + h*32;
        float2 a0 = __half22float2(p[2*li]), a1 = __half22float2(p[2*li+1]);
        float4 k4 = ks[li];
        s += a0.x*k4.x + a0.y*k4.y + a1.x*k4.z + a1.y*k4.w;
    }
    #pragma unroll
    for (int o=16;o;o>>=1) s += __shfl_xor_sync(0xffffffffu,s,o);
    if (lane==0) dinv[row] = 1.0f/s;
}

// ---------------- host ----------------
extern "C" void kernel_launch(void* const* d_in, const int* in_sizes, int n_in,
                              void* d_out, int out_size)
{
    const float* x    = (const float*)d_in[0];
    const float* proj = (const float*)d_in[1];
    const float* wq   = (const float*)d_in[2];
    const float* bq   = (const float*)d_in[3];
    const float* wk   = (const float*)d_in[4];
    const float* bk   = (const float*)d_in[5];
    const float* wv   = (const float*)d_in[6];
    const float* bv   = (const float*)d_in[7];
    const float* wo   = (const float*)d_in[8];
    const float* bo   = (const float*)d_in[9];
    const float* ln1g = (const float*)d_in[10];
    const float* ln1b = (const float*)d_in[11];
    const float* ln2g = (const float*)d_in[12];
    const float* ln2b = (const float*)d_in[13];
    const float* w1   = (const float*)d_in[14];
    const float* b1   = (const float*)d_in[15];
    const float* w2   = (const float*)d_in[16];
    const float* b2   = (const float*)d_in[17];
    float* out = (float*)d_out;

    void *p;
    __half *wqkvh, *woh, *w1h, *w2h, *projh, *h1h, *qkvh, *qph, *kph, *midh, *ctxTh, *attn2h;
    float *ddiag, *rowf, *x2, *dinv, *ksum;
    cudaGetSymbolAddress(&p, g_wqkvh);  wqkvh  = (__half*)p;
    cudaGetSymbolAddress(&p, g_woh);    woh    = (__half*)p;
    cudaGetSymbolAddress(&p, g_w1h);    w1h    = (__half*)p;
    cudaGetSymbolAddress(&p, g_w2h);    w2h    = (__half*)p;
    cudaGetSymbolAddress(&p, g_projh);  projh  = (__half*)p;
    cudaGetSymbolAddress(&p, g_h1h);    h1h    = (__half*)p;
    cudaGetSymbolAddress(&p, g_qkvh);   qkvh   = (__half*)p;
    cudaGetSymbolAddress(&p, g_qph);    qph    = (__half*)p;
    cudaGetSymbolAddress(&p, g_kph);    kph    = (__half*)p;
    cudaGetSymbolAddress(&p, g_midh);   midh   = (__half*)p;
    cudaGetSymbolAddress(&p, g_ctxTh);  ctxTh  = (__half*)p;
    cudaGetSymbolAddress(&p, g_attn2h); attn2h = (__half*)p;
    cudaGetSymbolAddress(&p, g_x2);     x2     = (float*)p;
    cudaGetSymbolAddress(&p, g_diag);   ddiag  = (float*)p;
    cudaGetSymbolAddress(&p, g_rowf);   rowf   = (float*)p;
    cudaGetSymbolAddress(&p, g_dinv);   dinv   = (float*)p;
    cudaGetSymbolAddress(&p, g_ksum);   ksum   = (float*)p;
    float* bqkv; cudaGetSymbolAddress(&p, g_bqkv); bqkv = (float*)p;

    __half* qh = qkvh;
    __half* kh = qkvh + (size_t)NHR*DhD;
    __half* vh = qkvh + 2*(size_t)NHR*DhD;
    float* dq = ddiag;
    float* dk = ddiag + NHR;

    cudaFuncSetAttribute(hgemm<128,128,EPI_QKV,true>,       cudaFuncAttributeMaxDynamicSharedMemorySize, SMEM_H128x128);
    cudaFuncSetAttribute(hgemm<64,256,EPI_QFEAT,true>,      cudaFuncAttributeMaxDynamicSharedMemorySize, SMEM_H64x256);
    cudaFuncSetAttribute(hgemm<64,256,EPI_KFEAT,true>,      cudaFuncAttributeMaxDynamicSharedMemorySize, SMEM_H64x256);
    cudaFuncSetAttribute(hgemm<128,64,EPI_ATTN,true>,       cudaFuncAttributeMaxDynamicSharedMemorySize, SMEM_H128x64);
    cudaFuncSetAttribute(hgemm<128,128,EPI_BIAS_RES,false>, cudaFuncAttributeMaxDynamicSharedMemorySize, SMEM_H128x128);
    cudaFuncSetAttribute(hgemm<128,128,EPI_BIAS_GELU,true>, cudaFuncAttributeMaxDynamicSharedMemorySize, SMEM_H128x128);

    // 0. resets + weight conversion
    reset_kernel<<<1,1>>>();
    f2h_kernel<<<576, 256>>>(wq, wqkvh,            Dd*Dd/4);
    f2h_kernel<<<576, 256>>>(wk, wqkvh +   Dd*Dd,  Dd*Dd/4);
    f2h_kernel<<<576, 256>>>(wv, wqkvh + 2*Dd*Dd,  Dd*Dd/4);
    f2h_kernel<<<576, 256>>>(wo, woh,              Dd*Dd/4);
    f2h_kernel<<<2304,256>>>(w1, w1h,              FFH*Dd/4);
    f2h_kernel<<<2304,256>>>(w2, w2h,              Dd*FFH/4);
    f2h_kernel<<<16,  256>>>(proj, projh,          Mm*DhD/4);
    bpack_kernel<<<9, 256>>>(bq, bk, bv);

    // 1. LN1 -> half
    ln_kernel<<<NROWS, 256>>>(x, ln1g, ln1b, h1h);

    // 2. fused QKV (N=2304)
    hgemm<128,128,EPI_QKV,true><<<dim3(18,128,1),256,SMEM_H128x128>>>(
        h1h,Dd,0, wqkvh,Dd,0, qkvh,DhD,0, NROWS,3*Dd,Dd, bqkv,nullptr,nullptr,0.f);

    // 3. diag q+k in one launch (contiguous rows)
    diag_kernel<<<2*NHR/8, 256>>>(qh, ddiag);

    // 4a. q features fused: GEMM + rowmax + exp -> qph
    hgemm<64,256,EPI_QFEAT,true><<<dim3(1,NHR/64,1),256,SMEM_H64x256>>>(
        qh,DhD,0, projh,DhD,0, qph,Mm,0, NHR,Mm,DhD, nullptr,nullptr,dq,NORM_C);
    // 4b. k features: GEMM + rowmax + exp(dd-rowmax) -> kph, rowf, gmax
    hgemm<64,256,EPI_KFEAT,true><<<dim3(1,NHR/64,1),256,SMEM_H64x256>>>(
        kh,DhD,0, projh,DhD,0, kph,Mm,0, NHR,Mm,DhD, nullptr,rowf,dk,NORM_C);

    // 5. ctx (tensor mma, TN) + fused ksum
    ctx_mma<<<dim3(2,NBH), 256, SMEM_CTX>>>(kph, vh, rowf, ctxTh, ksum);

    // 6. d_inv
    dinv_kernel<<<NHR/8, 256>>>(qph, dinv);

    // 7. attn = d_inv * (qp @ ctx), fused transpose -> attn2h [b,s,D]
    hgemm<128,64,EPI_ATTN,true><<<dim3(1,Ss/128,NBH),128,SMEM_H128x64>>>(
        qph,Mm,(long long)Ss*Mm, ctxTh,Mm,(long long)DhD*Mm, attn2h,DhD,0,
        Ss,DhD,Mm, nullptr,nullptr,dinv,0.f);

    // 8. x2 = x + attn @ wo^T + bo (fp32)
    hgemm<128,128,EPI_BIAS_RES,false><<<dim3(6,128,1),256,SMEM_H128x128>>>(
        attn2h,Dd,0, woh,Dd,0, x2,Dd,0, NROWS,Dd,Dd, bo,x,nullptr,0.f);

    // 9. LN2 -> half
    ln_kernel<<<NROWS, 256>>>(x2, ln2g, ln2b, h1h);

    // 10. mid = gelu(h1 @ w1^T + b1) -> half
    hgemm<128,128,EPI_BIAS_GELU,true><<<dim3(FFH/128,128,1),256,SMEM_H128x128>>>(
        h1h,Dd,0, w1h,Dd,0, midh,FFH,0, NROWS,FFH,Dd, b1,nullptr,nullptr,0.f);

    // 11. out = x2 + mid @ w2^T + b2 (fp32)
    hgemm<128,128,EPI_BIAS_RES,false><<<dim3(6,128,1),256,SMEM_H128x128>>>(
        midh,FFH,0, w2h,FFH,0, out,Dd,0, NROWS,Dd,FFH, b2,x2,nullptr,0.f);
}

// round 9
// speedup vs baseline: 6.1437x; 1.0225x over previous
#include <cuda_runtime.h>
#include <cuda_fp16.h>
#include <math.h>
#include <stdint.h>

// ---------------- problem constants ----------------
#define Bb   4
#define Ss   4096
#define Dd   768
#define Hh   12
#define Mm   256
#define DhD  64
#define NROWS (Bb*Ss)        // 16384
#define NBH   (Bb*Hh)        // 48
#define NHR   (NBH*Ss)       // 196608
#define FFH   (4*Dd)         // 3072

#define NORM_C   0.35355339059327373f
#define RATIO_C  0.0625f
#define DIAG_C   0.0625f
#define EPS_K    1e-4f
#define LN_EPS   1e-5f

// ---------------- scratch (device globals; allocation-free) ----------------
__device__ __half g_wqkvh[3*Dd*Dd];
__device__ float  g_bqkv[3*Dd];
__device__ __half g_woh[Dd*Dd];
__device__ __half g_w1h[FFH*Dd];
__device__ __half g_w2h[Dd*FFH];
__device__ __half g_projh[Mm*DhD];
__device__ __half g_h1h[NROWS*Dd];
__device__ __half g_qkvh[3*(size_t)NHR*DhD];      // q,k,v in [sel][b,h,s,dh]
__device__ __half g_qph[(size_t)NHR*Mm];
__device__ __half g_kph[(size_t)NHR*Mm];          // stored exp(dd - rowmax)
__device__ __half g_midh[(size_t)NROWS*FFH];
__device__ __half g_ctxTh[NBH*DhD*Mm];            // [bh][dh][m]
__device__ __half g_attn2h[(size_t)NROWS*Dd];     // [b,s,D]
__device__ float  g_x2[NROWS*Dd];
__device__ float  g_diag[2*NHR];                  // [q rows | k rows]
__device__ float  g_rowf[NHR];                    // rowmax(dd_k) - diag_k
__device__ float  g_ksum[NBH*Mm];
__device__ float  g_dinv[NHR];
__device__ unsigned g_gmax_u;

// ---------------- epilogue modes ----------------
enum { EPI_BIAS_RES=1, EPI_BIAS_GELU=2, EPI_QKV=5, EPI_QFEAT=6, EPI_KFEAT=7, EPI_ATTN=8 };

__device__ __forceinline__ void cpa16(uint32_t smem_dst, const void* gsrc){
    asm volatile("cp.async.cg.shared.global [%0], [%1], 16;" :: "r"(smem_dst), "l"(gsrc));
}
#define CP_COMMIT() asm volatile("cp.async.commit_group;" ::: "memory")
#define CP_WAIT1()  asm volatile("cp.async.wait_group 1;" ::: "memory")

__device__ __forceinline__ uint32_t smem_u32(const void* p){
    uint32_t a;
    asm("{ .reg .u64 t; cvta.to.shared.u64 t, %1; cvt.u32.u64 %0, t; }" : "=r"(a) : "l"(p));
    return a;
}

__device__ __forceinline__ void mma_f16(float* d, const uint32_t* a, const uint32_t* b){
    asm volatile("mma.sync.aligned.m16n8k16.row.col.f32.f16.f16.f32 "
        "{%0,%1,%2,%3}, {%4,%5,%6,%7}, {%8,%9}, {%0,%1,%2,%3};"
        : "+f"(d[0]),"+f"(d[1]),"+f"(d[2]),"+f"(d[3])
        : "r"(a[0]),"r"(a[1]),"r"(a[2]),"r"(a[3]), "r"(b[0]),"r"(b[1]));
}
#define LDSM4(r0,r1,r2,r3,addr) \
    asm volatile("ldmatrix.sync.aligned.m8n8.x4.shared.b16 {%0,%1,%2,%3}, [%4];" \
        : "=r"(r0),"=r"(r1),"=r"(r2),"=r"(r3) : "r"(addr))
#define LDSM4T(r0,r1,r2,r3,addr) \
    asm volatile("ldmatrix.sync.aligned.m8n8.x4.trans.shared.b16 {%0,%1,%2,%3}, [%4];" \
        : "=r"(r0),"=r"(r1),"=r"(r2),"=r"(r3) : "r"(addr))

__device__ __forceinline__ float gmax_decode(unsigned u){
    return (u & 0x80000000u) ? __uint_as_float(u ^ 0x80000000u) : __uint_as_float(~u);
}

// ================= fp16 NT GEMM: mma.sync m16n8k16 + cp.async(3-stage) + ldmatrix ======
template<int BM,int BN,int EPI,bool OUTH>
__global__ void __launch_bounds__(32*(BM/64)*(BN/32), 2)
hgemm(const __half* __restrict__ A, int lda, long long strA,
      const __half* __restrict__ B, int ldb, long long strB,
      void* __restrict__ Cv, int ldc, long long strC,
      int M, int N, int K,
      const float* __restrict__ bias,
      const float* __restrict__ res,
      const float* __restrict__ rowscale,
      float alpha)
{
    constexpr int WY = BM/64, WX = BN/32, THREADS = 32*WY*WX;
    constexpr int LDKW = 20;
    constexpr int AW = BM*LDKW;
    constexpr int SW = (BM+BN)*LDKW;
    constexpr int ALD = (BM*4)/THREADS;
    constexpr int BLD = (BN*4)/THREADS;

    extern __shared__ uint32_t sh[];
    const uint32_t smb = smem_u32(sh);

    const int z = blockIdx.z;
    A += (long long)z*strA;  B += (long long)z*strB;
    float*  Cf = (float*)Cv  + (long long)z*strC;
    __half* Ch = (__half*)Cv + (long long)z*strC;

    const int brow = blockIdx.y*BM;
    const int bcol = blockIdx.x*BN;
    const int tid  = threadIdx.x;
    const int wid  = tid >> 5;
    const int lane = tid & 31;
    const int wx   = wid % WX, wy = wid / WX;
    const int warp_m = wy*64, warp_n = wx*32;
    const int g = lane >> 2, t = lane & 3;

    const uint32_t aoff = (uint32_t)(((warp_m + (lane&15))*LDKW + (lane>>4)*4))*4u;
    const uint32_t boff = (uint32_t)((AW + (warp_n + (lane>>4)*8 + (lane&7))*LDKW + ((lane>>3)&1)*4))*4u;

    float acc[4][4][4];
    #pragma unroll
    for (int i=0;i<4;i++)
        #pragma unroll
        for (int j=0;j<4;j++)
            #pragma unroll
            for (int u=0;u<4;u++) acc[i][j][u]=0.f;

    const int nc = K >> 5;

    #define HISSUE(chunk) do{                                                  \
        const uint32_t bA_ = smb + (uint32_t)(((chunk)%3)*SW)*4u;              \
        const uint32_t bB_ = bA_ + (uint32_t)AW*4u;                            \
        const __half* Ap_ = A + (long long)brow*lda + (chunk)*32;              \
        const __half* Bp_ = B + (long long)bcol*ldb + (chunk)*32;              \
        _Pragma("unroll")                                                      \
        for (int l=0;l<ALD;l++){                                               \
            const int idx = tid + l*THREADS, r = idx>>2, c4 = idx&3;           \
            cpa16(bA_ + (uint32_t)(r*LDKW + c4*4)*4u,                          \
                  Ap_ + (long long)r*lda + c4*8);                              \
        }                                                                      \
        _Pragma("unroll")                                                      \
        for (int l=0;l<BLD;l++){                                               \
            const int idx = tid + l*THREADS, r = idx>>2, c4 = idx&3;           \
            cpa16(bB_ + (uint32_t)(r*LDKW + c4*4)*4u,                          \
                  Bp_ + (long long)r*ldb + c4*8);                              \
        }                                                                      \
    }while(0)

    if (0 < nc) HISSUE(0);
    CP_COMMIT();
    if (1 < nc) HISSUE(1);
    CP_COMMIT();

    for (int i=0; i<nc; ++i){
        CP_WAIT1();
        __syncthreads();
        if (i+2 < nc) HISSUE(i+2);
        CP_COMMIT();

        const uint32_t stg = smb + (uint32_t)((i%3)*SW)*4u;

        #pragma unroll
        for (int kk=0; kk<2; ++kk){
            uint32_t af[4][4], bf[4][2];
            #pragma unroll
            for (int mt=0; mt<4; ++mt)
                LDSM4(af[mt][0],af[mt][1],af[mt][2],af[mt][3],
                      stg + aoff + (uint32_t)((mt*16*LDKW + kk*8))*4u);
            LDSM4(bf[0][0],bf[0][1],bf[1][0],bf[1][1],
                  stg + boff + (uint32_t)(kk*8)*4u);
            LDSM4(bf[2][0],bf[2][1],bf[3][0],bf[3][1],
                  stg + boff + (uint32_t)((16*LDKW + kk*8))*4u);
            #pragma unroll
            for (int mt=0; mt<4; ++mt)
                #pragma unroll
                for (int nt=0; nt<4; ++nt)
                    mma_f16(acc[mt][nt], af[mt], bf[nt]);
        }
    }
    #undef HISSUE

    // ================= epilogues =================
    if (EPI==EPI_QFEAT || EPI==EPI_KFEAT){
        float mxs[4][2];
        #pragma unroll
        for (int mt=0; mt<4; ++mt){
            float m0=-3.402823466e38f, m1=m0;
            #pragma unroll
            for (int nt=0; nt<4; ++nt){
                #pragma unroll
                for (int u=0;u<4;u++) acc[mt][nt][u]*=alpha;
                m0 = fmaxf(m0, fmaxf(acc[mt][nt][0], acc[mt][nt][1]));
                m1 = fmaxf(m1, fmaxf(acc[mt][nt][2], acc[mt][nt][3]));
            }
            m0 = fmaxf(m0, __shfl_xor_sync(0xffffffffu,m0,1));
            m0 = fmaxf(m0, __shfl_xor_sync(0xffffffffu,m0,2));
            m1 = fmaxf(m1, __shfl_xor_sync(0xffffffffu,m1,1));
            m1 = fmaxf(m1, __shfl_xor_sync(0xffffffffu,m1,2));
            mxs[mt][0]=m0; mxs[mt][1]=m1;
        }
        __syncthreads();
        float* red = (float*)sh;               // [64][8]
        if (t==0){
            #pragma unroll
            for (int mt=0; mt<4; ++mt){
                red[(mt*16+g)*8 + wid]   = mxs[mt][0];
                red[(mt*16+8+g)*8 + wid] = mxs[mt][1];
            }
        }
        __syncthreads();
        #pragma unroll
        for (int mt=0; mt<4; ++mt){
            const int grow = brow + mt*16 + g;
            float mx0 = red[(mt*16+g)*8], mx1 = red[(mt*16+8+g)*8];
            #pragma unroll
            for (int w=1; w<8; ++w){
                mx0 = fmaxf(mx0, red[(mt*16+g)*8+w]);
                mx1 = fmaxf(mx1, red[(mt*16+8+g)*8+w]);
            }
            mxs[mt][0]=mx0; mxs[mt][1]=mx1;
            float d0, d1;
            if (EPI==EPI_QFEAT){ d0 = rowscale[grow] + mx0; d1 = rowscale[grow+8] + mx1; }
            else               { d0 = mx0;                  d1 = mx1; }
            #pragma unroll
            for (int nt=0; nt<4; ++nt){
                const int c0 = warp_n + nt*8 + 2*t;
                __half2 o0, o1;
                if (EPI==EPI_QFEAT){
                    o0 = __floats2half2_rn(RATIO_C*(expf(acc[mt][nt][0]-d0)+EPS_K),
                                           RATIO_C*(expf(acc[mt][nt][1]-d0)+EPS_K));
                    o1 = __floats2half2_rn(RATIO_C*(expf(acc[mt][nt][2]-d1)+EPS_K),
                                           RATIO_C*(expf(acc[mt][nt][3]-d1)+EPS_K));
                } else {
                    o0 = __floats2half2_rn(expf(acc[mt][nt][0]-d0), expf(acc[mt][nt][1]-d0));
                    o1 = __floats2half2_rn(expf(acc[mt][nt][2]-d1), expf(acc[mt][nt][3]-d1));
                }
                *reinterpret_cast<__half2*>(Ch + (long long)grow*ldc + c0)     = o0;
                *reinterpret_cast<__half2*>(Ch + (long long)(grow+8)*ldc + c0) = o1;
            }
            if (EPI==EPI_KFEAT && wid==0 && t==0){
                float* rowf = const_cast<float*>(res);
                rowf[grow]   = mx0 - rowscale[grow];
                rowf[grow+8] = mx1 - rowscale[grow+8];
            }
        }
        if (EPI==EPI_KFEAT && wid==0){
            float bm = fmaxf(fmaxf(mxs[0][0],mxs[0][1]), fmaxf(mxs[1][0],mxs[1][1]));
            bm = fmaxf(bm, fmaxf(fmaxf(mxs[2][0],mxs[2][1]), fmaxf(mxs[3][0],mxs[3][1])));
            #pragma unroll
            for (int o=16;o;o>>=1) bm = fmaxf(bm, __shfl_xor_sync(0xffffffffu,bm,o));
            if (lane==0){
                unsigned b = __float_as_uint(bm);
                unsigned u = (b & 0x80000000u) ? ~b : (b | 0x80000000u);
                atomicMax(&g_gmax_u, u);
            }
        }
        return;
    }

    #pragma unroll
    for (int mt=0; mt<4; ++mt){
        const int r0 = brow + warp_m + mt*16 + g;
        const int r1 = r0 + 8;
        float rs0 = 1.f, rs1 = 1.f;
        if (EPI==EPI_ATTN){
            rs0 = rowscale[(long long)z*M + r0];
            rs1 = rowscale[(long long)z*M + r1];
        }
        #pragma unroll
        for (int nt=0; nt<4; ++nt){
            const int c0 = bcol + warp_n + nt*8 + 2*t;
            float v00 = acc[mt][nt][0], v01 = acc[mt][nt][1];
            float v10 = acc[mt][nt][2], v11 = acc[mt][nt][3];
            if (EPI==EPI_BIAS_RES || EPI==EPI_BIAS_GELU || EPI==EPI_QKV){
                const float b0 = bias[c0], b1 = bias[c0+1];
                v00 += b0; v01 += b1; v10 += b0; v11 += b1;
            }
            if (EPI==EPI_BIAS_RES){
                v00 += res[(long long)r0*ldc + c0];   v01 += res[(long long)r0*ldc + c0+1];
                v10 += res[(long long)r1*ldc + c0];   v11 += res[(long long)r1*ldc + c0+1];
            }
            if (EPI==EPI_BIAS_GELU){
                v00 = 0.5f*v00*(1.0f+erff(v00*0.70710678118654752f));
                v01 = 0.5f*v01*(1.0f+erff(v01*0.70710678118654752f));
                v10 = 0.5f*v10*(1.0f+erff(v10*0.70710678118654752f));
                v11 = 0.5f*v11*(1.0f+erff(v11*0.70710678118654752f));
            }
            if (EPI==EPI_ATTN){ v00*=rs0; v01*=rs0; v10*=rs1; v11*=rs1; }

            if (EPI==EPI_QKV){
                const int sel = c0/Dd, cc = c0 - sel*Dd;
                const int h_ = cc>>6, dh_ = cc&63;
                const int b0_ = r0>>12, s0_ = r0&4095;
                const int b1_ = r1>>12, s1_ = r1&4095;
                __half* base = (__half*)Cv + (size_t)sel*NHR*DhD;
                *reinterpret_cast<__half2*>(base + ((((long long)(b0_*Hh+h_))<<12)+s0_)*DhD + dh_) = __floats2half2_rn(v00,v01);
                *reinterpret_cast<__half2*>(base + ((((long long)(b1_*Hh+h_))<<12)+s1_)*DhD + dh_) = __floats2half2_rn(v10,v11);
            } else if (EPI==EPI_ATTN){
                const int bb = z/Hh, hh = z - (z/Hh)*Hh;
                __half* base = (__half*)Cv;
                const long long o0 = ((long long)(bb*Ss + r0))*Dd + hh*64 + c0;
                const long long o1 = ((long long)(bb*Ss + r1))*Dd + hh*64 + c0;
                *reinterpret_cast<__half2*>(base + o0) = __floats2half2_rn(v00,v01);
                *reinterpret_cast<__half2*>(base + o1) = __floats2half2_rn(v10,v11);
            } else if (OUTH){
                *reinterpret_cast<__half2*>(Ch + (long long)r0*ldc + c0) = __floats2half2_rn(v00,v01);
                *reinterpret_cast<__half2*>(Ch + (long long)r1*ldc + c0) = __floats2half2_rn(v10,v11);
            } else {
                float2 o0; o0.x=v00; o0.y=v01;
                float2 o1; o1.x=v10; o1.y=v11;
                *reinterpret_cast<float2*>(Cf + (long long)r0*ldc + c0) = o0;
                *reinterpret_cast<float2*>(Cf + (long long)r1*ldc + c0) = o1;
            }
        }
    }
}

#define SMEM_H128x128 (3*(128+128)*20*4)   // 61440
#define SMEM_H64x256  (3*(64+256)*20*4)    // 76800
#define SMEM_H128x64  (3*(128+64)*20*4)    // 46080

// ================ ctx TN mma kernel, 4-way m split ====================================
// ctxT[dh][m] = sum_s kp[s][m]*v[s][dh], kp = RATIO*exp(rowf[s]-gmax)*stored + RATIO*eps.
// Fused ksum. grid (4 ntiles of 64 m, 48 bh), 256 threads.
#define CTX_LDV 36
#define CTX_LDP 36
#define CTX_VW  (32*CTX_LDV)
#define CTX_PW  (32*CTX_LDP)
#define SMEM_CTX (3*(CTX_VW+CTX_PW)*4)     // 27648

__global__ void __launch_bounds__(256, 2)
ctx_mma(const __half* __restrict__ kpe, const __half* __restrict__ vh,
        const float* __restrict__ rowf,
        __half* __restrict__ ctxT, float* __restrict__ ksum)
{
    extern __shared__ uint32_t sh[];
    const uint32_t smb = smem_u32(sh);
    const uint32_t pbase = smb + (uint32_t)(3*CTX_VW)*4u;

    const int z = blockIdx.y;
    const int ntile = blockIdx.x;               // 0..3, 64 m-cols each
    const int tid = threadIdx.x, wid = tid>>5, lane = tid&31;
    const int warp_m = (wid & 3)*16;            // dh tile
    const int warp_n = (wid >> 2)*32;           // m tile
    const int g = lane>>2, t = lane&3;
    const int quad = lane>>3, r8 = lane&7;

    const __half* kpb = kpe + (long long)z*Ss*Mm + ntile*64;
    const __half* vhb = vh  + (long long)z*Ss*DhD;
    const float*  rfb = rowf + (long long)z*Ss;

    const float gmax = gmax_decode(g_gmax_u);
    const float epsr = RATIO_C*EPS_K;

    const uint32_t a_off0 = (uint32_t)((r8 + ((quad>>1)&1)*8)*CTX_LDV + (warp_m + (quad&1)*8)/2);
    const uint32_t b_off0 = (uint32_t)((r8 + (quad&1)*8)*CTX_LDP + (warp_n + (quad>>1)*8)/2);

    const int srow = tid >> 3;     // 0..31
    const int c8   = tid & 7;      // 8-half group

    float acc[4][4];
    #pragma unroll
    for (int j=0;j<4;j++)
        #pragma unroll
        for (int u=0;u<4;u++) acc[j][u]=0.f;
    float ks[8];
    #pragma unroll
    for (int j=0;j<8;j++) ks[j]=0.f;

    #define VISSUE(c) do{ \
        const uint32_t bV = smb + (uint32_t)(((c)%3)*CTX_VW)*4u; \
        cpa16(bV + (uint32_t)(srow*CTX_LDV + c8*4)*4u, \
              vhb + (long long)((c)*32 + srow)*DhD + c8*8); \
    }while(0)

    uint4 cur; float curf;
    cur  = *reinterpret_cast<const uint4*>(kpb + (long long)srow*Mm + c8*8);
    curf = rfb[srow];
    VISSUE(0); CP_COMMIT();
    VISSUE(1); CP_COMMIT();

    for (int i=0; i<Ss/32; ++i){
        {
            const float As = RATIO_C*expf(curf - gmax);
            uint32_t rw[4] = {cur.x,cur.y,cur.z,cur.w};
            uint32_t ow[4];
            #pragma unroll
            for (int j=0;j<4;j++){
                float2 f = __half22float2(*reinterpret_cast<__half2*>(&rw[j]));
                f.x = fmaf(f.x, As, epsr);
                f.y = fmaf(f.y, As, epsr);
                __half2 h = __floats2half2_rn(f.x, f.y);
                float2 fr = __half22float2(h);
                ks[2*j]   += fr.x;
                ks[2*j+1] += fr.y;
                ow[j] = *reinterpret_cast<uint32_t*>(&h);
            }
            const uint32_t bP = pbase + (uint32_t)((i%3)*CTX_PW)*4u
                              + (uint32_t)(srow*CTX_LDP + c8*4)*4u;
            uint4 s0 = {ow[0],ow[1],ow[2],ow[3]};
            *reinterpret_cast<uint4*>((char*)sh + (bP - smb)) = s0;
        }
        CP_WAIT1();
        __syncthreads();
        if (i+2 < Ss/32) VISSUE(i+2);
        CP_COMMIT();
        if (i+1 < Ss/32){
            cur  = *reinterpret_cast<const uint4*>(kpb + (long long)((i+1)*32 + srow)*Mm + c8*8);
            curf = rfb[(i+1)*32 + srow];
        }

        const uint32_t vstg = smb + (uint32_t)((i%3)*CTX_VW)*4u;
        const uint32_t pstg = pbase + (uint32_t)((i%3)*CTX_PW)*4u;

        #pragma unroll
        for (int kk=0; kk<2; ++kk){
            uint32_t af[4], bf[4][2];
            LDSM4T(af[0],af[1],af[2],af[3],
                   vstg + (a_off0 + (uint32_t)(kk*16*CTX_LDV))*4u);
            #pragma unroll
            for (int pp2=0; pp2<2; ++pp2)
                LDSM4T(bf[2*pp2][0],bf[2*pp2][1],bf[2*pp2+1][0],bf[2*pp2+1][1],
                       pstg + (b_off0 + (uint32_t)(kk*16*CTX_LDP + pp2*8))*4u);
            #pragma unroll
            for (int nt=0; nt<4; ++nt)
                mma_f16(acc[nt], af, bf[nt]);
        }
    }
    #undef VISSUE

    const int dh0 = warp_m + g;
    const int dh1 = dh0 + 8;
    #pragma unroll
    for (int nt=0; nt<4; ++nt){
        const int col = ntile*64 + warp_n + nt*8 + 2*t;
        *reinterpret_cast<__half2*>(ctxT + (long long)z*DhD*Mm + (long long)dh0*Mm + col)
            = __floats2half2_rn(acc[nt][0], acc[nt][1]);
        *reinterpret_cast<__half2*>(ctxT + (long long)z*DhD*Mm + (long long)dh1*Mm + col)
            = __floats2half2_rn(acc[nt][2], acc[nt][3]);
    }

    __syncthreads();
    float* red = (float*)sh;                // [32][64]
    #pragma unroll
    for (int j=0;j<8;j++) red[srow*64 + c8*8 + j] = ks[j];
    __syncthreads();
    if (tid < 64){
        float s = 0.f;
        #pragma unroll
        for (int r=0;r<32;r++) s += red[r*64 + tid];
        ksum[z*Mm + ntile*64 + tid] = s;
    }
}

// ---------------- setup kernels ----------------
__global__ void reset_kernel(){ g_gmax_u = 0u; }

// merged weight conversions: qkv + wo  (4 segments of Dd*Dd/4 float4)
__global__ void f2h_qkvo(const float* __restrict__ wq, const float* __restrict__ wk,
                         const float* __restrict__ wv, const float* __restrict__ wo)
{
    const int i = blockIdx.x*256 + threadIdx.x;          // 0 .. 4*147456-1
    const int seg = i / (Dd*Dd/4);
    const int off = i - seg*(Dd*Dd/4);
    const float* s = (seg==0) ? wq : (seg==1) ? wk : (seg==2) ? wv : wo;
    __half* d = (seg<3) ? (g_wqkvh + (size_t)seg*Dd*Dd) : g_woh;
    float4 v = reinterpret_cast<const float4*>(s)[off];
    __half2* o = reinterpret_cast<__half2*>(d) + 2*off;
    o[0] = __floats2half2_rn(v.x, v.y);
    o[1] = __floats2half2_rn(v.z, v.w);
}
// merged: w1, w2, proj
__global__ void f2h_ffn(const float* __restrict__ w1, const float* __restrict__ w2,
                        const float* __restrict__ proj)
{
    const int i = blockIdx.x*256 + threadIdx.x;
    const int W = FFH*Dd/4;                               // 589824
    const float* s; __half* d; int off;
    if (i < W)            { s = w1;   d = g_w1h;   off = i; }
    else if (i < 2*W)     { s = w2;   d = g_w2h;   off = i - W; }
    else if (i < 2*W + Mm*DhD/4) { s = proj; d = g_projh; off = i - 2*W; }
    else return;
    float4 v = reinterpret_cast<const float4*>(s)[off];
    __half2* o = reinterpret_cast<__half2*>(d) + 2*off;
    o[0] = __floats2half2_rn(v.x, v.y);
    o[1] = __floats2half2_rn(v.z, v.w);
}
__global__ void bpack_kernel(const float* bq, const float* bk, const float* bv)
{
    const int i = blockIdx.x*256 + threadIdx.x;
    if (i >= 3*Dd) return;
    const int sel = i/Dd, c = i - sel*Dd;
    g_bqkv[i] = sel==0 ? bq[c] : (sel==1 ? bk[c] : bv[c]);
}

// ---------------- LayerNorm (row=768), half output ----------------
__global__ void ln_kernel(const float* __restrict__ x, const float* __restrict__ g,
                          const float* __restrict__ b, __half* __restrict__ out)
{
    const int row = blockIdx.x;
    const float* xr = x + (long long)row*Dd;
    float v[3]; float s=0.f, ss=0.f;
    #pragma unroll
    for (int i=0;i<3;i++){ v[i]=xr[threadIdx.x + i*256]; s+=v[i]; ss+=v[i]*v[i]; }
    #pragma unroll
    for (int o=16;o;o>>=1){ s+=__shfl_xor_sync(0xffffffffu,s,o); ss+=__shfl_xor_sync(0xffffffffu,ss,o); }
    __shared__ float rs_[8], rss_[8];
    const int lane = threadIdx.x & 31, w = threadIdx.x >> 5;
    if (lane==0){ rs_[w]=s; rss_[w]=ss; }
    __syncthreads();
    s=0.f; ss=0.f;
    #pragma unroll
    for (int i=0;i<8;i++){ s+=rs_[i]; ss+=rss_[i]; }
    const float mu  = s*(1.0f/Dd);
    const float var = ss*(1.0f/Dd) - mu*mu;
    const float rstd = rsqrtf(var + LN_EPS);
    __half* outr = out + (long long)row*Dd;
    #pragma unroll
    for (int i=0;i<3;i++){
        int c = threadIdx.x + i*256;
        outr[c] = __float2half((v[i]-mu)*rstd*g[c] + b[c]);
    }
}

// ---------------- diag: 0.0625 * sum(x^2) over 64 halfs (warp per row), q|k fused ------
__global__ void diag_kernel(const __half* __restrict__ src, float* __restrict__ dst)
{
    const int lane = threadIdx.x & 31, w = threadIdx.x >> 5;
    const long long row = (long long)blockIdx.x*8 + w;
    __half2 v = reinterpret_cast<const __half2*>(src + row*DhD)[lane];
    float2 f = __half22float2(v);
    float s = f.x*f.x + f.y*f.y;
    #pragma unroll
    for (int o=16;o;o>>=1) s += __shfl_xor_sync(0xffffffffu,s,o);
    if (lane==0) dst[row] = DIAG_C * s;
}

// ---------------- d_inv: half qp, fp32 ksum (warp per row) ----------------
__global__ void dinv_kernel(const __half* __restrict__ qp, float* __restrict__ dinv)
{
    const int lane = threadIdx.x & 31, w = threadIdx.x >> 5;
    const long long row = (long long)blockIdx.x*8 + w;
    const int bh = (int)(row >> 12);
    const __half2* p = reinterpret_cast<const __half2*>(qp + row*Mm);
    const float4* ks = reinterpret_cast<const float4*>(g_ksum + (long long)bh*Mm);
    float s = 0.f;
    #pragma unroll
    for (int h=0; h<2; ++h){
        const int li = lane + h*32;
        float2 a0 = __half22float2(p[2*li]), a1 = __half22float2(p[2*li+1]);
        float4 k4 = ks[li];
        s += a0.x*k4.x + a0.y*k4.y + a1.x*k4.z + a1.y*k4.w;
    }
    #pragma unroll
    for (int o=16;o;o>>=1) s += __shfl_xor_sync(0xffffffffu,s,o);
    if (lane==0) dinv[row] = 1.0f/s;
}

// ---------------- host ----------------
extern "C" void kernel_launch(void* const* d_in, const int* in_sizes, int n_in,
                              void* d_out, int out_size)
{
    const float* x    = (const float*)d_in[0];
    const float* proj = (const float*)d_in[1];
    const float* wq   = (const float*)d_in[2];
    const float* bq   = (const float*)d_in[3];
    const float* wk   = (const float*)d_in[4];
    const float* bk   = (const float*)d_in[5];
    const float* wv   = (const float*)d_in[6];
    const float* bv   = (const float*)d_in[7];
    const float* wo   = (const float*)d_in[8];
    const float* bo   = (const float*)d_in[9];
    const float* ln1g = (const float*)d_in[10];
    const float* ln1b = (const float*)d_in[11];
    const float* ln2g = (const float*)d_in[12];
    const float* ln2b = (const float*)d_in[13];
    const float* w1   = (const float*)d_in[14];
    const float* b1   = (const float*)d_in[15];
    const float* w2   = (const float*)d_in[16];
    const float* b2   = (const float*)d_in[17];
    float* out = (float*)d_out;

    void *p;
    __half *wqkvh, *woh, *w1h, *w2h, *projh, *h1h, *qkvh, *qph, *kph, *midh, *ctxTh, *attn2h;
    float *ddiag, *rowf, *x2, *dinv, *ksum;
    cudaGetSymbolAddress(&p, g_wqkvh);  wqkvh  = (__half*)p;
    cudaGetSymbolAddress(&p, g_woh);    woh    = (__half*)p;
    cudaGetSymbolAddress(&p, g_w1h);    w1h    = (__half*)p;
    cudaGetSymbolAddress(&p, g_w2h);    w2h    = (__half*)p;
    cudaGetSymbolAddress(&p, g_projh);  projh  = (__half*)p;
    cudaGetSymbolAddress(&p, g_h1h);    h1h    = (__half*)p;
    cudaGetSymbolAddress(&p, g_qkvh);   qkvh   = (__half*)p;
    cudaGetSymbolAddress(&p, g_qph);    qph    = (__half*)p;
    cudaGetSymbolAddress(&p, g_kph);    kph    = (__half*)p;
    cudaGetSymbolAddress(&p, g_midh);   midh   = (__half*)p;
    cudaGetSymbolAddress(&p, g_ctxTh);  ctxTh  = (__half*)p;
    cudaGetSymbolAddress(&p, g_attn2h); attn2h = (__half*)p;
    cudaGetSymbolAddress(&p, g_x2);     x2     = (float*)p;
    cudaGetSymbolAddress(&p, g_diag);   ddiag  = (float*)p;
    cudaGetSymbolAddress(&p, g_rowf);   rowf   = (float*)p;
    cudaGetSymbolAddress(&p, g_dinv);   dinv   = (float*)p;
    cudaGetSymbolAddress(&p, g_ksum);   ksum   = (float*)p;
    float* bqkv; cudaGetSymbolAddress(&p, g_bqkv); bqkv = (float*)p;

    __half* qh = qkvh;
    __half* kh = qkvh + (size_t)NHR*DhD;
    __half* vh = qkvh + 2*(size_t)NHR*DhD;
    float* dq = ddiag;
    float* dk = ddiag + NHR;

    cudaFuncSetAttribute(hgemm<128,128,EPI_QKV,true>,       cudaFuncAttributeMaxDynamicSharedMemorySize, SMEM_H128x128);
    cudaFuncSetAttribute(hgemm<64,256,EPI_QFEAT,true>,      cudaFuncAttributeMaxDynamicSharedMemorySize, SMEM_H64x256);
    cudaFuncSetAttribute(hgemm<64,256,EPI_KFEAT,true>,      cudaFuncAttributeMaxDynamicSharedMemorySize, SMEM_H64x256);
    cudaFuncSetAttribute(hgemm<128,64,EPI_ATTN,true>,       cudaFuncAttributeMaxDynamicSharedMemorySize, SMEM_H128x64);
    cudaFuncSetAttribute(hgemm<128,128,EPI_BIAS_RES,false>, cudaFuncAttributeMaxDynamicSharedMemorySize, SMEM_H128x128);
    cudaFuncSetAttribute(hgemm<128,128,EPI_BIAS_GELU,true>, cudaFuncAttributeMaxDynamicSharedMemorySize, SMEM_H128x128);

    // 1-5: setup (ordered so the QKV GEMM is the 6th launch -> ncu target)
    f2h_qkvo<<<4*(Dd*Dd/4)/256, 256>>>(wq, wk, wv, wo);
    f2h_ffn<<<(2*(FFH*Dd/4) + Mm*DhD/4 + 255)/256, 256>>>(w1, w2, proj);
    reset_kernel<<<1,1>>>();
    bpack_kernel<<<9, 256>>>(bq, bk, bv);
    ln_kernel<<<NROWS, 256>>>(x, ln1g, ln1b, h1h);

    // 6. fused QKV (N=2304)
    hgemm<128,128,EPI_QKV,true><<<dim3(18,128,1),256,SMEM_H128x128>>>(
        h1h,Dd,0, wqkvh,Dd,0, qkvh,DhD,0, NROWS,3*Dd,Dd, bqkv,nullptr,nullptr,0.f);

    // 7. diag q+k in one launch
    diag_kernel<<<2*NHR/8, 256>>>(qh, ddiag);

    // 8. q features fused: GEMM + rowmax + exp -> qph
    hgemm<64,256,EPI_QFEAT,true><<<dim3(1,NHR/64,1),256,SMEM_H64x256>>>(
        qh,DhD,0, projh,DhD,0, qph,Mm,0, NHR,Mm,DhD, nullptr,nullptr,dq,NORM_C);
    // 9. k features: GEMM + rowmax + exp(dd-rowmax) -> kph, rowf, gmax
    hgemm<64,256,EPI_KFEAT,true><<<dim3(1,NHR/64,1),256,SMEM_H64x256>>>(
        kh,DhD,0, projh,DhD,0, kph,Mm,0, NHR,Mm,DhD, nullptr,rowf,dk,NORM_C);

    // 10. ctx (tensor mma, TN, 4-way m split) + fused ksum
    ctx_mma<<<dim3(4,NBH), 256, SMEM_CTX>>>(kph, vh, rowf, ctxTh, ksum);

    // 11. d_inv
    dinv_kernel<<<NHR/8, 256>>>(qph, dinv);

    // 12. attn = d_inv * (qp @ ctx), fused transpose -> attn2h [b,s,D]
    hgemm<128,64,EPI_ATTN,true><<<dim3(1,Ss/128,NBH),128,SMEM_H128x64>>>(
        qph,Mm,(long long)Ss*Mm, ctxTh,Mm,(long long)DhD*Mm, attn2h,DhD,0,
        Ss,DhD,Mm, nullptr,nullptr,dinv,0.f);

    // 13. x2 = x + attn @ wo^T + bo (fp32)
    hgemm<128,128,EPI_BIAS_RES,false><<<dim3(6,128,1),256,SMEM_H128x128>>>(
        attn2h,Dd,0, woh,Dd,0, x2,Dd,0, NROWS,Dd,Dd, bo,x,nullptr,0.f);

    // 14. LN2 -> half
    ln_kernel<<<NROWS, 256>>>(x2, ln2g, ln2b, h1h);

    // 15. mid = gelu(h1 @ w1^T + b1) -> half
    hgemm<128,128,EPI_BIAS_GELU,true><<<dim3(FFH/128,128,1),256,SMEM_H128x128>>>(
        h1h,Dd,0, w1h,Dd,0, midh,FFH,0, NROWS,FFH,Dd, b1,nullptr,nullptr,0.f);

    // 16. out = x2 + mid @ w2^T + b2 (fp32)
    hgemm<128,128,EPI_BIAS_RES,false><<<dim3(6,128,1),256,SMEM_H128x128>>>(
        midh,FFH,0, w2h,FFH,0, out,Dd,0, NROWS,Dd,FFH, b2,x2,nullptr,0.f);
}

// round 10
// speedup vs baseline: 6.5655x; 1.0687x over previous
#include <cuda_runtime.h>
#include <cuda_fp16.h>
#include <math.h>
#include <stdint.h>

// ---------------- problem constants ----------------
#define Bb   4
#define Ss   4096
#define Dd   768
#define Hh   12
#define Mm   256
#define DhD  64
#define NROWS (Bb*Ss)        // 16384
#define NBH   (Bb*Hh)        // 48
#define NHR   (NBH*Ss)       // 196608
#define FFH   (4*Dd)         // 3072

#define NORM_C   0.35355339059327373f
#define RATIO_C  0.0625f
#define DIAG_C   0.0625f
#define EPS_K    1e-4f
#define LN_EPS   1e-5f

// ---------------- scratch (device globals; allocation-free) ----------------
__device__ __half g_wqkvh[3*Dd*Dd];
__device__ float  g_bqkv[3*Dd];
__device__ __half g_woh[Dd*Dd];
__device__ __half g_w1h[FFH*Dd];
__device__ __half g_w2h[Dd*FFH];
__device__ __half g_projh[Mm*DhD];
__device__ __half g_h1h[NROWS*Dd];
__device__ __half g_qkvh[3*(size_t)NHR*DhD];      // q,k,v in [sel][b,h,s,dh]
__device__ __half g_qph[(size_t)NHR*Mm];
__device__ __half g_kph[(size_t)NHR*Mm];          // stored exp(dd - rowmax)
__device__ __half g_midh[(size_t)NROWS*FFH];
__device__ __half g_ctxTh[NBH*DhD*Mm];            // [bh][dh][m]
__device__ __half g_attn2h[(size_t)NROWS*Dd];     // [b,s,D]
__device__ float  g_x2[NROWS*Dd];
__device__ float  g_diag[2*NHR];                  // [q rows | k rows]
__device__ float  g_rowf[NHR];                    // rowmax(dd_k) - diag_k
__device__ float  g_ksum[NBH*Mm];
__device__ float  g_dinv[NHR];
__device__ unsigned g_gmax_u;

// ---------------- epilogue modes ----------------
enum { EPI_BIAS_RES=1, EPI_BIAS_GELU=2, EPI_QKV=5, EPI_QFEAT=6, EPI_KFEAT=7, EPI_ATTN=8 };

__device__ __forceinline__ void cpa16(uint32_t smem_dst, const void* gsrc){
    asm volatile("cp.async.cg.shared.global [%0], [%1], 16;" :: "r"(smem_dst), "l"(gsrc));
}
#define CP_COMMIT() asm volatile("cp.async.commit_group;" ::: "memory")
#define CP_WAIT0()  asm volatile("cp.async.wait_group 0;" ::: "memory")
#define CP_WAIT1()  asm volatile("cp.async.wait_group 1;" ::: "memory")

__device__ __forceinline__ uint32_t smem_u32(const void* p){
    uint32_t a;
    asm("{ .reg .u64 t; cvta.to.shared.u64 t, %1; cvt.u32.u64 %0, t; }" : "=r"(a) : "l"(p));
    return a;
}

__device__ __forceinline__ void mma_f16(float* d, const uint32_t* a, const uint32_t* b){
    asm volatile("mma.sync.aligned.m16n8k16.row.col.f32.f16.f16.f32 "
        "{%0,%1,%2,%3}, {%4,%5,%6,%7}, {%8,%9}, {%0,%1,%2,%3};"
        : "+f"(d[0]),"+f"(d[1]),"+f"(d[2]),"+f"(d[3])
        : "r"(a[0]),"r"(a[1]),"r"(a[2]),"r"(a[3]), "r"(b[0]),"r"(b[1]));
}
#define LDSM4(r0,r1,r2,r3,addr) \
    asm volatile("ldmatrix.sync.aligned.m8n8.x4.shared.b16 {%0,%1,%2,%3}, [%4];" \
        : "=r"(r0),"=r"(r1),"=r"(r2),"=r"(r3) : "r"(addr))
#define LDSM4T(r0,r1,r2,r3,addr) \
    asm volatile("ldmatrix.sync.aligned.m8n8.x4.trans.shared.b16 {%0,%1,%2,%3}, [%4];" \
        : "=r"(r0),"=r"(r1),"=r"(r2),"=r"(r3) : "r"(addr))

__device__ __forceinline__ float gmax_decode(unsigned u){
    return (u & 0x80000000u) ? __uint_as_float(u ^ 0x80000000u) : __uint_as_float(~u);
}

// ================= fp16 NT GEMM: mma.sync m16n8k16, BK=64, 2-stage cp.async ============
// C[m,n] = sum_k A[m,k]*B[n,k]. Warp tile 64x32; rows = 64 halfs + pad (LDKW=36 words).
template<int BM,int BN,int EPI,bool OUTH>
__global__ void __launch_bounds__(32*(BM/64)*(BN/32), 2)
hgemm(const __half* __restrict__ A, int lda, long long strA,
      const __half* __restrict__ B, int ldb, long long strB,
      void* __restrict__ Cv, int ldc, long long strC,
      int M, int N, int K,
      const float* __restrict__ bias,
      const float* __restrict__ res,
      const float* __restrict__ rowscale,
      float alpha)
{
    constexpr int WY = BM/64, WX = BN/32, THREADS = 32*WY*WX;
    constexpr int LDKW = 36;                 // 32 data words (64 halfs) + 4 pad
    constexpr int AW = BM*LDKW;
    constexpr int SW = (BM+BN)*LDKW;
    constexpr int ALD = (BM*8)/THREADS;      // 16B chunks per thread (A), 8 per row
    constexpr int BLD = (BN*8)/THREADS;

    extern __shared__ uint32_t sh[];
    const uint32_t smb = smem_u32(sh);

    const int z = blockIdx.z;
    A += (long long)z*strA;  B += (long long)z*strB;
    float*  Cf = (float*)Cv  + (long long)z*strC;
    __half* Ch = (__half*)Cv + (long long)z*strC;

    const int brow = blockIdx.y*BM;
    const int bcol = blockIdx.x*BN;
    const int tid  = threadIdx.x;
    const int wid  = tid >> 5;
    const int lane = tid & 31;
    const int wx   = wid % WX, wy = wid / WX;
    const int warp_m = wy*64, warp_n = wx*32;
    const int g = lane >> 2, t = lane & 3;

    const uint32_t aoff = (uint32_t)(((warp_m + (lane&15))*LDKW + (lane>>4)*4))*4u;
    const uint32_t boff = (uint32_t)((AW + (warp_n + (lane>>4)*8 + (lane&7))*LDKW + ((lane>>3)&1)*4))*4u;

    float acc[4][4][4];
    #pragma unroll
    for (int i=0;i<4;i++)
        #pragma unroll
        for (int j=0;j<4;j++)
            #pragma unroll
            for (int u=0;u<4;u++) acc[i][j][u]=0.f;

    const int nc = K >> 6;                   // 64-half chunks

    #define HISSUE(chunk) do{                                                  \
        const uint32_t bA_ = smb + (uint32_t)(((chunk)&1)*SW)*4u;              \
        const uint32_t bB_ = bA_ + (uint32_t)AW*4u;                            \
        const __half* Ap_ = A + (long long)brow*lda + (chunk)*64;              \
        const __half* Bp_ = B + (long long)bcol*ldb + (chunk)*64;              \
        _Pragma("unroll")                                                      \
        for (int l=0;l<ALD;l++){                                               \
            const int idx = tid + l*THREADS, r = idx>>3, c4 = idx&7;           \
            cpa16(bA_ + (uint32_t)(r*LDKW + c4*4)*4u,                          \
                  Ap_ + (long long)r*lda + c4*8);                              \
        }                                                                      \
        _Pragma("unroll")                                                      \
        for (int l=0;l<BLD;l++){                                               \
            const int idx = tid + l*THREADS, r = idx>>3, c4 = idx&7;           \
            cpa16(bB_ + (uint32_t)(r*LDKW + c4*4)*4u,                          \
                  Bp_ + (long long)r*ldb + c4*8);                              \
        }                                                                      \
    }while(0)

    HISSUE(0);
    CP_COMMIT();

    for (int i=0; i<nc; ++i){
        CP_WAIT0();
        __syncthreads();
        if (i+1 < nc){ HISSUE(i+1); CP_COMMIT(); }

        const uint32_t stg = smb + (uint32_t)((i&1)*SW)*4u;

        #pragma unroll
        for (int kk=0; kk<4; ++kk){
            uint32_t af[4][4], bf[4][2];
            #pragma unroll
            for (int mt=0; mt<4; ++mt)
                LDSM4(af[mt][0],af[mt][1],af[mt][2],af[mt][3],
                      stg + aoff + (uint32_t)((mt*16*LDKW + kk*8))*4u);
            LDSM4(bf[0][0],bf[0][1],bf[1][0],bf[1][1],
                  stg + boff + (uint32_t)(kk*8)*4u);
            LDSM4(bf[2][0],bf[2][1],bf[3][0],bf[3][1],
                  stg + boff + (uint32_t)((16*LDKW + kk*8))*4u);
            #pragma unroll
            for (int mt=0; mt<4; ++mt)
                #pragma unroll
                for (int nt=0; nt<4; ++nt)
                    mma_f16(acc[mt][nt], af[mt], bf[nt]);
        }
        __syncthreads();          // stage (i&1) consumed before next overwrite
    }
    #undef HISSUE

    // ================= epilogues =================
    if (EPI==EPI_QFEAT || EPI==EPI_KFEAT){
        float mxs[4][2];
        #pragma unroll
        for (int mt=0; mt<4; ++mt){
            float m0=-3.402823466e38f, m1=m0;
            #pragma unroll
            for (int nt=0; nt<4; ++nt){
                #pragma unroll
                for (int u=0;u<4;u++) acc[mt][nt][u]*=alpha;
                m0 = fmaxf(m0, fmaxf(acc[mt][nt][0], acc[mt][nt][1]));
                m1 = fmaxf(m1, fmaxf(acc[mt][nt][2], acc[mt][nt][3]));
            }
            m0 = fmaxf(m0, __shfl_xor_sync(0xffffffffu,m0,1));
            m0 = fmaxf(m0, __shfl_xor_sync(0xffffffffu,m0,2));
            m1 = fmaxf(m1, __shfl_xor_sync(0xffffffffu,m1,1));
            m1 = fmaxf(m1, __shfl_xor_sync(0xffffffffu,m1,2));
            mxs[mt][0]=m0; mxs[mt][1]=m1;
        }
        __syncthreads();
        float* red = (float*)sh;               // [64][8]
        if (t==0){
            #pragma unroll
            for (int mt=0; mt<4; ++mt){
                red[(mt*16+g)*8 + wid]   = mxs[mt][0];
                red[(mt*16+8+g)*8 + wid] = mxs[mt][1];
            }
        }
        __syncthreads();
        #pragma unroll
        for (int mt=0; mt<4; ++mt){
            const int grow = brow + mt*16 + g;
            float mx0 = red[(mt*16+g)*8], mx1 = red[(mt*16+8+g)*8];
            #pragma unroll
            for (int w=1; w<8; ++w){
                mx0 = fmaxf(mx0, red[(mt*16+g)*8+w]);
                mx1 = fmaxf(mx1, red[(mt*16+8+g)*8+w]);
            }
            mxs[mt][0]=mx0; mxs[mt][1]=mx1;
            float d0, d1;
            if (EPI==EPI_QFEAT){ d0 = rowscale[grow] + mx0; d1 = rowscale[grow+8] + mx1; }
            else               { d0 = mx0;                  d1 = mx1; }
            #pragma unroll
            for (int nt=0; nt<4; ++nt){
                const int c0 = warp_n + nt*8 + 2*t;
                __half2 o0, o1;
                if (EPI==EPI_QFEAT){
                    o0 = __floats2half2_rn(RATIO_C*(expf(acc[mt][nt][0]-d0)+EPS_K),
                                           RATIO_C*(expf(acc[mt][nt][1]-d0)+EPS_K));
                    o1 = __floats2half2_rn(RATIO_C*(expf(acc[mt][nt][2]-d1)+EPS_K),
                                           RATIO_C*(expf(acc[mt][nt][3]-d1)+EPS_K));
                } else {
                    o0 = __floats2half2_rn(expf(acc[mt][nt][0]-d0), expf(acc[mt][nt][1]-d0));
                    o1 = __floats2half2_rn(expf(acc[mt][nt][2]-d1), expf(acc[mt][nt][3]-d1));
                }
                *reinterpret_cast<__half2*>(Ch + (long long)grow*ldc + c0)     = o0;
                *reinterpret_cast<__half2*>(Ch + (long long)(grow+8)*ldc + c0) = o1;
            }
            if (EPI==EPI_KFEAT && wid==0 && t==0){
                float* rowf = const_cast<float*>(res);
                rowf[grow]   = mx0 - rowscale[grow];
                rowf[grow+8] = mx1 - rowscale[grow+8];
            }
        }
        if (EPI==EPI_KFEAT && wid==0){
            float bm = fmaxf(fmaxf(mxs[0][0],mxs[0][1]), fmaxf(mxs[1][0],mxs[1][1]));
            bm = fmaxf(bm, fmaxf(fmaxf(mxs[2][0],mxs[2][1]), fmaxf(mxs[3][0],mxs[3][1])));
            #pragma unroll
            for (int o=16;o;o>>=1) bm = fmaxf(bm, __shfl_xor_sync(0xffffffffu,bm,o));
            if (lane==0){
                unsigned b = __float_as_uint(bm);
                unsigned u = (b & 0x80000000u) ? ~b : (b | 0x80000000u);
                atomicMax(&g_gmax_u, u);
            }
        }
        return;
    }

    #pragma unroll
    for (int mt=0; mt<4; ++mt){
        const int r0 = brow + warp_m + mt*16 + g;
        const int r1 = r0 + 8;
        float rs0 = 1.f, rs1 = 1.f;
        if (EPI==EPI_ATTN){
            rs0 = rowscale[(long long)z*M + r0];
            rs1 = rowscale[(long long)z*M + r1];
        }
        #pragma unroll
        for (int nt=0; nt<4; ++nt){
            const int c0 = bcol + warp_n + nt*8 + 2*t;
            float v00 = acc[mt][nt][0], v01 = acc[mt][nt][1];
            float v10 = acc[mt][nt][2], v11 = acc[mt][nt][3];
            if (EPI==EPI_BIAS_RES || EPI==EPI_BIAS_GELU || EPI==EPI_QKV){
                const float b0 = bias[c0], b1 = bias[c0+1];
                v00 += b0; v01 += b1; v10 += b0; v11 += b1;
            }
            if (EPI==EPI_BIAS_RES){
                v00 += res[(long long)r0*ldc + c0];   v01 += res[(long long)r0*ldc + c0+1];
                v10 += res[(long long)r1*ldc + c0];   v11 += res[(long long)r1*ldc + c0+1];
            }
            if (EPI==EPI_BIAS_GELU){
                v00 = 0.5f*v00*(1.0f+erff(v00*0.70710678118654752f));
                v01 = 0.5f*v01*(1.0f+erff(v01*0.70710678118654752f));
                v10 = 0.5f*v10*(1.0f+erff(v10*0.70710678118654752f));
                v11 = 0.5f*v11*(1.0f+erff(v11*0.70710678118654752f));
            }
            if (EPI==EPI_ATTN){ v00*=rs0; v01*=rs0; v10*=rs1; v11*=rs1; }

            if (EPI==EPI_QKV){
                const int sel = c0/Dd, cc = c0 - sel*Dd;
                const int h_ = cc>>6, dh_ = cc&63;
                const int b0_ = r0>>12, s0_ = r0&4095;
                const int b1_ = r1>>12, s1_ = r1&4095;
                __half* base = (__half*)Cv + (size_t)sel*NHR*DhD;
                *reinterpret_cast<__half2*>(base + ((((long long)(b0_*Hh+h_))<<12)+s0_)*DhD + dh_) = __floats2half2_rn(v00,v01);
                *reinterpret_cast<__half2*>(base + ((((long long)(b1_*Hh+h_))<<12)+s1_)*DhD + dh_) = __floats2half2_rn(v10,v11);
            } else if (EPI==EPI_ATTN){
                const int bb = z/Hh, hh = z - (z/Hh)*Hh;
                __half* base = (__half*)Cv;
                const long long o0 = ((long long)(bb*Ss + r0))*Dd + hh*64 + c0;
                const long long o1 = ((long long)(bb*Ss + r1))*Dd + hh*64 + c0;
                *reinterpret_cast<__half2*>(base + o0) = __floats2half2_rn(v00,v01);
                *reinterpret_cast<__half2*>(base + o1) = __floats2half2_rn(v10,v11);
            } else if (OUTH){
                *reinterpret_cast<__half2*>(Ch + (long long)r0*ldc + c0) = __floats2half2_rn(v00,v01);
                *reinterpret_cast<__half2*>(Ch + (long long)r1*ldc + c0) = __floats2half2_rn(v10,v11);
            } else {
                float2 o0; o0.x=v00; o0.y=v01;
                float2 o1; o1.x=v10; o1.y=v11;
                *reinterpret_cast<float2*>(Cf + (long long)r0*ldc + c0) = o0;
                *reinterpret_cast<float2*>(Cf + (long long)r1*ldc + c0) = o1;
            }
        }
    }
}

#define SMEM_H128x128 (2*(128+128)*36*4)   // 73728
#define SMEM_H64x256  (2*(64+256)*36*4)    // 92160
#define SMEM_H128x64  (2*(128+64)*36*4)    // 55296

// ================ ctx TN mma kernel, 4-way m split (BK=32, 3-stage) ====================
#define CTX_LDV 36
#define CTX_LDP 36
#define CTX_VW  (32*CTX_LDV)
#define CTX_PW  (32*CTX_LDP)
#define SMEM_CTX (3*(CTX_VW+CTX_PW)*4)     // 27648

__global__ void __launch_bounds__(256, 2)
ctx_mma(const __half* __restrict__ kpe, const __half* __restrict__ vh,
        const float* __restrict__ rowf,
        __half* __restrict__ ctxT, float* __restrict__ ksum)
{
    extern __shared__ uint32_t sh[];
    const uint32_t smb = smem_u32(sh);
    const uint32_t pbase = smb + (uint32_t)(3*CTX_VW)*4u;

    const int z = blockIdx.y;
    const int ntile = blockIdx.x;               // 0..3, 64 m-cols each
    const int tid = threadIdx.x, wid = tid>>5, lane = tid&31;
    const int warp_m = (wid & 3)*16;            // dh tile
    const int warp_n = (wid >> 2)*32;           // m tile
    const int g = lane>>2, t = lane&3;
    const int quad = lane>>3, r8 = lane&7;

    const __half* kpb = kpe + (long long)z*Ss*Mm + ntile*64;
    const __half* vhb = vh  + (long long)z*Ss*DhD;
    const float*  rfb = rowf + (long long)z*Ss;

    const float gmax = gmax_decode(g_gmax_u);
    const float epsr = RATIO_C*EPS_K;

    const uint32_t a_off0 = (uint32_t)((r8 + ((quad>>1)&1)*8)*CTX_LDV + (warp_m + (quad&1)*8)/2);
    const uint32_t b_off0 = (uint32_t)((r8 + (quad&1)*8)*CTX_LDP + (warp_n + (quad>>1)*8)/2);

    const int srow = tid >> 3;     // 0..31
    const int c8   = tid & 7;      // 8-half group

    float acc[4][4];
    #pragma unroll
    for (int j=0;j<4;j++)
        #pragma unroll
        for (int u=0;u<4;u++) acc[j][u]=0.f;
    float ks[8];
    #pragma unroll
    for (int j=0;j<8;j++) ks[j]=0.f;

    #define VISSUE(c) do{ \
        const uint32_t bV = smb + (uint32_t)(((c)%3)*CTX_VW)*4u; \
        cpa16(bV + (uint32_t)(srow*CTX_LDV + c8*4)*4u, \
              vhb + (long long)((c)*32 + srow)*DhD + c8*8); \
    }while(0)

    uint4 cur; float curf;
    cur  = *reinterpret_cast<const uint4*>(kpb + (long long)srow*Mm + c8*8);
    curf = rfb[srow];
    VISSUE(0); CP_COMMIT();
    VISSUE(1); CP_COMMIT();

    for (int i=0; i<Ss/32; ++i){
        {
            const float As = RATIO_C*expf(curf - gmax);
            uint32_t rw[4] = {cur.x,cur.y,cur.z,cur.w};
            uint32_t ow[4];
            #pragma unroll
            for (int j=0;j<4;j++){
                float2 f = __half22float2(*reinterpret_cast<__half2*>(&rw[j]));
                f.x = fmaf(f.x, As, epsr);
                f.y = fmaf(f.y, As, epsr);
                __half2 h = __floats2half2_rn(f.x, f.y);
                float2 fr = __half22float2(h);
                ks[2*j]   += fr.x;
                ks[2*j+1] += fr.y;
                ow[j] = *reinterpret_cast<uint32_t*>(&h);
            }
            const uint32_t bP = pbase + (uint32_t)((i%3)*CTX_PW)*4u
                              + (uint32_t)(srow*CTX_LDP + c8*4)*4u;
            uint4 s0 = {ow[0],ow[1],ow[2],ow[3]};
            *reinterpret_cast<uint4*>((char*)sh + (bP - smb)) = s0;
        }
        CP_WAIT1();
        __syncthreads();
        if (i+2 < Ss/32) VISSUE(i+2);
        CP_COMMIT();
        if (i+1 < Ss/32){
            cur  = *reinterpret_cast<const uint4*>(kpb + (long long)((i+1)*32 + srow)*Mm + c8*8);
            curf = rfb[(i+1)*32 + srow];
        }

        const uint32_t vstg = smb + (uint32_t)((i%3)*CTX_VW)*4u;
        const uint32_t pstg = pbase + (uint32_t)((i%3)*CTX_PW)*4u;

        #pragma unroll
        for (int kk=0; kk<2; ++kk){
            uint32_t af[4], bf[4][2];
            LDSM4T(af[0],af[1],af[2],af[3],
                   vstg + (a_off0 + (uint32_t)(kk*16*CTX_LDV))*4u);
            #pragma unroll
            for (int pp2=0; pp2<2; ++pp2)
                LDSM4T(bf[2*pp2][0],bf[2*pp2][1],bf[2*pp2+1][0],bf[2*pp2+1][1],
                       pstg + (b_off0 + (uint32_t)(kk*16*CTX_LDP + pp2*8))*4u);
            #pragma unroll
            for (int nt=0; nt<4; ++nt)
                mma_f16(acc[nt], af, bf[nt]);
        }
    }
    #undef VISSUE

    const int dh0 = warp_m + g;
    const int dh1 = dh0 + 8;
    #pragma unroll
    for (int nt=0; nt<4; ++nt){
        const int col = ntile*64 + warp_n + nt*8 + 2*t;
        *reinterpret_cast<__half2*>(ctxT + (long long)z*DhD*Mm + (long long)dh0*Mm + col)
            = __floats2half2_rn(acc[nt][0], acc[nt][1]);
        *reinterpret_cast<__half2*>(ctxT + (long long)z*DhD*Mm + (long long)dh1*Mm + col)
            = __floats2half2_rn(acc[nt][2], acc[nt][3]);
    }

    __syncthreads();
    float* red = (float*)sh;                // [32][64]
    #pragma unroll
    for (int j=0;j<8;j++) red[srow*64 + c8*8 + j] = ks[j];
    __syncthreads();
    if (tid < 64){
        float s = 0.f;
        #pragma unroll
        for (int r=0;r<32;r++) s += red[r*64 + tid];
        ksum[z*Mm + ntile*64 + tid] = s;
    }
}

// ---------------- setup kernels ----------------
__global__ void reset_kernel(){ g_gmax_u = 0u; }

__global__ void f2h_qkvo(const float* __restrict__ wq, const float* __restrict__ wk,
                         const float* __restrict__ wv, const float* __restrict__ wo)
{
    const int i = blockIdx.x*256 + threadIdx.x;
    const int seg = i / (Dd*Dd/4);
    const int off = i - seg*(Dd*Dd/4);
    const float* s = (seg==0) ? wq : (seg==1) ? wk : (seg==2) ? wv : wo;
    __half* d = (seg<3) ? (g_wqkvh + (size_t)seg*Dd*Dd) : g_woh;
    float4 v = reinterpret_cast<const float4*>(s)[off];
    __half2* o = reinterpret_cast<__half2*>(d) + 2*off;
    o[0] = __floats2half2_rn(v.x, v.y);
    o[1] = __floats2half2_rn(v.z, v.w);
}
__global__ void f2h_ffn(const float* __restrict__ w1, const float* __restrict__ w2,
                        const float* __restrict__ proj)
{
    const int i = blockIdx.x*256 + threadIdx.x;
    const int W = FFH*Dd/4;
    const float* s; __half* d; int off;
    if (i < W)            { s = w1;   d = g_w1h;   off = i; }
    else if (i < 2*W)     { s = w2;   d = g_w2h;   off = i - W; }
    else if (i < 2*W + Mm*DhD/4) { s = proj; d = g_projh; off = i - 2*W; }
    else return;
    float4 v = reinterpret_cast<const float4*>(s)[off];
    __half2* o = reinterpret_cast<__half2*>(d) + 2*off;
    o[0] = __floats2half2_rn(v.x, v.y);
    o[1] = __floats2half2_rn(v.z, v.w);
}
__global__ void bpack_kernel(const float* bq, const float* bk, const float* bv)
{
    const int i = blockIdx.x*256 + threadIdx.x;
    if (i >= 3*Dd) return;
    const int sel = i/Dd, c = i - sel*Dd;
    g_bqkv[i] = sel==0 ? bq[c] : (sel==1 ? bk[c] : bv[c]);
}

// ---------------- LayerNorm (row=768), half output ----------------
__global__ void ln_kernel(const float* __restrict__ x, const float* __restrict__ g,
                          const float* __restrict__ b, __half* __restrict__ out)
{
    const int row = blockIdx.x;
    const float* xr = x + (long long)row*Dd;
    float v[3]; float s=0.f, ss=0.f;
    #pragma unroll
    for (int i=0;i<3;i++){ v[i]=xr[threadIdx.x + i*256]; s+=v[i]; ss+=v[i]*v[i]; }
    #pragma unroll
    for (int o=16;o;o>>=1){ s+=__shfl_xor_sync(0xffffffffu,s,o); ss+=__shfl_xor_sync(0xffffffffu,ss,o); }
    __shared__ float rs_[8], rss_[8];
    const int lane = threadIdx.x & 31, w = threadIdx.x >> 5;
    if (lane==0){ rs_[w]=s; rss_[w]=ss; }
    __syncthreads();
    s=0.f; ss=0.f;
    #pragma unroll
    for (int i=0;i<8;i++){ s+=rs_[i]; ss+=rss_[i]; }
    const float mu  = s*(1.0f/Dd);
    const float var = ss*(1.0f/Dd) - mu*mu;
    const float rstd = rsqrtf(var + LN_EPS);
    __half* outr = out + (long long)row*Dd;
    #pragma unroll
    for (int i=0;i<3;i++){
        int c = threadIdx.x + i*256;
        outr[c] = __float2half((v[i]-mu)*rstd*g[c] + b[c]);
    }
}

// ---------------- diag: 0.0625 * sum(x^2) over 64 halfs (warp per row), q|k fused ------
__global__ void diag_kernel(const __half* __restrict__ src, float* __restrict__ dst)
{
    const int lane = threadIdx.x & 31, w = threadIdx.x >> 5;
    const long long row = (long long)blockIdx.x*8 + w;
    __half2 v = reinterpret_cast<const __half2*>(src + row*DhD)[lane];
    float2 f = __half22float2(v);
    float s = f.x*f.x + f.y*f.y;
    #pragma unroll
    for (int o=16;o;o>>=1) s += __shfl_xor_sync(0xffffffffu,s,o);
    if (lane==0) dst[row] = DIAG_C * s;
}

// ---------------- d_inv: half qp, fp32 ksum (warp per row) ----------------
__global__ void dinv_kernel(const __half* __restrict__ qp, float* __restrict__ dinv)
{
    const int lane = threadIdx.x & 31, w = threadIdx.x >> 5;
    const long long row = (long long)blockIdx.x*8 + w;
    const int bh = (int)(row >> 12);
    const __half2* p = reinterpret_cast<const __half2*>(qp + row*Mm);
    const float4* ks = reinterpret_cast<const float4*>(g_ksum + (long long)bh*Mm);
    float s = 0.f;
    #pragma unroll
    for (int h=0; h<2; ++h){
        const int li = lane + h*32;
        float2 a0 = __half22float2(p[2*li]), a1 = __half22float2(p[2*li+1]);
        float4 k4 = ks[li];
        s += a0.x*k4.x + a0.y*k4.y + a1.x*k4.z + a1.y*k4.w;
    }
    #pragma unroll
    for (int o=16;o;o>>=1) s += __shfl_xor_sync(0xffffffffu,s,o);
    if (lane==0) dinv[row] = 1.0f/s;
}

// ---------------- host ----------------
extern "C" void kernel_launch(void* const* d_in, const int* in_sizes, int n_in,
                              void* d_out, int out_size)
{
    const float* x    = (const float*)d_in[0];
    const float* proj = (const float*)d_in[1];
    const float* wq   = (const float*)d_in[2];
    const float* bq   = (const float*)d_in[3];
    const float* wk   = (const float*)d_in[4];
    const float* bk   = (const float*)d_in[5];
    const float* wv   = (const float*)d_in[6];
    const float* bv   = (const float*)d_in[7];
    const float* wo   = (const float*)d_in[8];
    const float* bo   = (const float*)d_in[9];
    const float* ln1g = (const float*)d_in[10];
    const float* ln1b = (const float*)d_in[11];
    const float* ln2g = (const float*)d_in[12];
    const float* ln2b = (const float*)d_in[13];
    const float* w1   = (const float*)d_in[14];
    const float* b1   = (const float*)d_in[15];
    const float* w2   = (const float*)d_in[16];
    const float* b2   = (const float*)d_in[17];
    float* out = (float*)d_out;

    void *p;
    __half *wqkvh, *woh, *w1h, *w2h, *projh, *h1h, *qkvh, *qph, *kph, *midh, *ctxTh, *attn2h;
    float *ddiag, *rowf, *x2, *dinv, *ksum;
    cudaGetSymbolAddress(&p, g_wqkvh);  wqkvh  = (__half*)p;
    cudaGetSymbolAddress(&p, g_woh);    woh    = (__half*)p;
    cudaGetSymbolAddress(&p, g_w1h);    w1h    = (__half*)p;
    cudaGetSymbolAddress(&p, g_w2h);    w2h    = (__half*)p;
    cudaGetSymbolAddress(&p, g_projh);  projh  = (__half*)p;
    cudaGetSymbolAddress(&p, g_h1h);    h1h    = (__half*)p;
    cudaGetSymbolAddress(&p, g_qkvh);   qkvh   = (__half*)p;
    cudaGetSymbolAddress(&p, g_qph);    qph    = (__half*)p;
    cudaGetSymbolAddress(&p, g_kph);    kph    = (__half*)p;
    cudaGetSymbolAddress(&p, g_midh);   midh   = (__half*)p;
    cudaGetSymbolAddress(&p, g_ctxTh);  ctxTh  = (__half*)p;
    cudaGetSymbolAddress(&p, g_attn2h); attn2h = (__half*)p;
    cudaGetSymbolAddress(&p, g_x2);     x2     = (float*)p;
    cudaGetSymbolAddress(&p, g_diag);   ddiag  = (float*)p;
    cudaGetSymbolAddress(&p, g_rowf);   rowf   = (float*)p;
    cudaGetSymbolAddress(&p, g_dinv);   dinv   = (float*)p;
    cudaGetSymbolAddress(&p, g_ksum);   ksum   = (float*)p;
    float* bqkv; cudaGetSymbolAddress(&p, g_bqkv); bqkv = (float*)p;

    __half* qh = qkvh;
    __half* kh = qkvh + (size_t)NHR*DhD;
    __half* vh = qkvh + 2*(size_t)NHR*DhD;
    float* dq = ddiag;
    float* dk = ddiag + NHR;

    cudaFuncSetAttribute(hgemm<128,128,EPI_QKV,true>,       cudaFuncAttributeMaxDynamicSharedMemorySize, SMEM_H128x128);
    cudaFuncSetAttribute(hgemm<64,256,EPI_QFEAT,true>,      cudaFuncAttributeMaxDynamicSharedMemorySize, SMEM_H64x256);
    cudaFuncSetAttribute(hgemm<64,256,EPI_KFEAT,true>,      cudaFuncAttributeMaxDynamicSharedMemorySize, SMEM_H64x256);
    cudaFuncSetAttribute(hgemm<128,64,EPI_ATTN,true>,       cudaFuncAttributeMaxDynamicSharedMemorySize, SMEM_H128x64);
    cudaFuncSetAttribute(hgemm<128,128,EPI_BIAS_RES,false>, cudaFuncAttributeMaxDynamicSharedMemorySize, SMEM_H128x128);
    cudaFuncSetAttribute(hgemm<128,128,EPI_BIAS_GELU,true>, cudaFuncAttributeMaxDynamicSharedMemorySize, SMEM_H128x128);

    // setup
    f2h_qkvo<<<4*(Dd*Dd/4)/256, 256>>>(wq, wk, wv, wo);
    f2h_ffn<<<(2*(FFH*Dd/4) + Mm*DhD/4 + 255)/256, 256>>>(w1, w2, proj);
    reset_kernel<<<1,1>>>();
    bpack_kernel<<<9, 256>>>(bq, bk, bv);
    ln_kernel<<<NROWS, 256>>>(x, ln1g, ln1b, h1h);

    // fused QKV (N=2304)
    hgemm<128,128,EPI_QKV,true><<<dim3(18,128,1),256,SMEM_H128x128>>>(
        h1h,Dd,0, wqkvh,Dd,0, qkvh,DhD,0, NROWS,3*Dd,Dd, bqkv,nullptr,nullptr,0.f);

    // diag q+k in one launch
    diag_kernel<<<2*NHR/8, 256>>>(qh, ddiag);

    // q features fused: GEMM + rowmax + exp -> qph
    hgemm<64,256,EPI_QFEAT,true><<<dim3(1,NHR/64,1),256,SMEM_H64x256>>>(
        qh,DhD,0, projh,DhD,0, qph,Mm,0, NHR,Mm,DhD, nullptr,nullptr,dq,NORM_C);
    // k features: GEMM + rowmax + exp(dd-rowmax) -> kph, rowf, gmax
    hgemm<64,256,EPI_KFEAT,true><<<dim3(1,NHR/64,1),256,SMEM_H64x256>>>(
        kh,DhD,0, projh,DhD,0, kph,Mm,0, NHR,Mm,DhD, nullptr,rowf,dk,NORM_C);

    // ctx (tensor mma, TN, 4-way m split) + fused ksum
    ctx_mma<<<dim3(4,NBH), 256, SMEM_CTX>>>(kph, vh, rowf, ctxTh, ksum);

    // d_inv
    dinv_kernel<<<NHR/8, 256>>>(qph, dinv);

    // attn = d_inv * (qp @ ctx), fused transpose -> attn2h [b,s,D]
    hgemm<128,64,EPI_ATTN,true><<<dim3(1,Ss/128,NBH),128,SMEM_H128x64>>>(
        qph,Mm,(long long)Ss*Mm, ctxTh,Mm,(long long)DhD*Mm, attn2h,DhD,0,
        Ss,DhD,Mm, nullptr,nullptr,dinv,0.f);

    // x2 = x + attn @ wo^T + bo (fp32)
    hgemm<128,128,EPI_BIAS_RES,false><<<dim3(6,128,1),256,SMEM_H128x128>>>(
        attn2h,Dd,0, woh,Dd,0, x2,Dd,0, NROWS,Dd,Dd, bo,x,nullptr,0.f);

    // LN2 -> half
    ln_kernel<<<NROWS, 256>>>(x2, ln2g, ln2b, h1h);

    // mid = gelu(h1 @ w1^T + b1) -> half
    hgemm<128,128,EPI_BIAS_GELU,true><<<dim3(FFH/128,128,1),256,SMEM_H128x128>>>(
        h1h,Dd,0, w1h,Dd,0, midh,FFH,0, NROWS,FFH,Dd, b1,nullptr,nullptr,0.f);

    // out = x2 + mid @ w2^T + b2 (fp32)
    hgemm<128,128,EPI_BIAS_RES,false><<<dim3(6,128,1),256,SMEM_H128x128>>>(
        midh,FFH,0, w2h,FFH,0, out,Dd,0, NROWS,Dd,FFH, b2,x2,nullptr,0.f);
}

// round 11
// speedup vs baseline: 6.7886x; 1.0340x over previous
#include <cuda_runtime.h>
#include <cuda_fp16.h>
#include <math.h>
#include <stdint.h>

// ---------------- problem constants ----------------
#define Bb   4
#define Ss   4096
#define Dd   768
#define Hh   12
#define Mm   256
#define DhD  64
#define NROWS (Bb*Ss)        // 16384
#define NBH   (Bb*Hh)        // 48
#define NHR   (NBH*Ss)       // 196608
#define FFH   (4*Dd)         // 3072

#define NORM_C   0.35355339059327373f
#define RATIO_C  0.0625f
#define DIAG_C   0.0625f
#define EPS_K    1e-4f
#define LN_EPS   1e-5f

// ---------------- scratch (device globals; allocation-free) ----------------
__device__ __half g_wqkvh[3*Dd*Dd];
__device__ float  g_bqkv[3*Dd];
__device__ __half g_woh[Dd*Dd];
__device__ __half g_w1h[FFH*Dd];
__device__ __half g_w2h[Dd*FFH];
__device__ __half g_projh[Mm*DhD];
__device__ __half g_h1h[NROWS*Dd];
__device__ __half g_qkvh[3*(size_t)NHR*DhD];      // q,k,v in [sel][b,h,s,dh]
__device__ __half g_qph[(size_t)NHR*Mm];
__device__ __half g_kph[(size_t)NHR*Mm];          // stored exp(dd - rowmax)
__device__ __half g_midh[(size_t)NROWS*FFH];
__device__ __half g_ctxTh[NBH*DhD*Mm];            // [bh][dh][m]
__device__ __half g_attn2h[(size_t)NROWS*Dd];     // [b,s,D]
__device__ float  g_x2[NROWS*Dd];
__device__ float  g_diag[2*NHR];                  // [q rows | k rows]
__device__ float  g_rowf[NHR];                    // rowmax(dd_k) - diag_k
__device__ float  g_ksum[NBH*Mm];
__device__ float  g_dinv[NHR];
__device__ unsigned g_gmax_u;

// ---------------- epilogue modes ----------------
enum { EPI_BIAS_RES=1, EPI_BIAS_GELU=2, EPI_QKV=5, EPI_QFEAT=6, EPI_KFEAT=7, EPI_ATTN=8 };

__device__ __forceinline__ void cpa16(uint32_t smem_dst, const void* gsrc){
    asm volatile("cp.async.cg.shared.global [%0], [%1], 16;" :: "r"(smem_dst), "l"(gsrc));
}
#define CP_COMMIT() asm volatile("cp.async.commit_group;" ::: "memory")
#define CP_WAIT0()  asm volatile("cp.async.wait_group 0;" ::: "memory")
#define CP_WAIT1()  asm volatile("cp.async.wait_group 1;" ::: "memory")

__device__ __forceinline__ uint32_t smem_u32(const void* p){
    uint32_t a;
    asm("{ .reg .u64 t; cvta.to.shared.u64 t, %1; cvt.u32.u64 %0, t; }" : "=r"(a) : "l"(p));
    return a;
}

__device__ __forceinline__ void mma_f16(float* d, const uint32_t* a, const uint32_t* b){
    asm volatile("mma.sync.aligned.m16n8k16.row.col.f32.f16.f16.f32 "
        "{%0,%1,%2,%3}, {%4,%5,%6,%7}, {%8,%9}, {%0,%1,%2,%3};"
        : "+f"(d[0]),"+f"(d[1]),"+f"(d[2]),"+f"(d[3])
        : "r"(a[0]),"r"(a[1]),"r"(a[2]),"r"(a[3]), "r"(b[0]),"r"(b[1]));
}
#define LDSM4(r0,r1,r2,r3,addr) \
    asm volatile("ldmatrix.sync.aligned.m8n8.x4.shared.b16 {%0,%1,%2,%3}, [%4];" \
        : "=r"(r0),"=r"(r1),"=r"(r2),"=r"(r3) : "r"(addr))
#define LDSM4T(r0,r1,r2,r3,addr) \
    asm volatile("ldmatrix.sync.aligned.m8n8.x4.trans.shared.b16 {%0,%1,%2,%3}, [%4];" \
        : "=r"(r0),"=r"(r1),"=r"(r2),"=r"(r3) : "r"(addr))

__device__ __forceinline__ float gmax_decode(unsigned u){
    return (u & 0x80000000u) ? __uint_as_float(u ^ 0x80000000u) : __uint_as_float(~u);
}

// ================= fp16 NT GEMM: mma.sync m16n8k16, BK=64, 2-stage cp.async ============
template<int BM,int BN,int EPI,bool OUTH>
__global__ void __launch_bounds__(32*(BM/64)*(BN/32), (BM==128 && BN==64) ? 3 : 2)
hgemm(const __half* __restrict__ A, int lda, long long strA,
      const __half* __restrict__ B, int ldb, long long strB,
      void* __restrict__ Cv, int ldc, long long strC,
      int M, int N, int K,
      const float* __restrict__ bias,
      const float* __restrict__ res,
      const float* __restrict__ rowscale,
      float alpha)
{
    constexpr int WY = BM/64, WX = BN/32, THREADS = 32*WY*WX;
    constexpr int LDKW = 36;                 // 32 data words (64 halfs) + 4 pad
    constexpr int AW = BM*LDKW;
    constexpr int SW = (BM+BN)*LDKW;
    constexpr int ALD = (BM*8)/THREADS;
    constexpr int BLD = (BN*8)/THREADS;

    extern __shared__ uint32_t sh[];
    const uint32_t smb = smem_u32(sh);

    const int z = blockIdx.z;
    A += (long long)z*strA;  B += (long long)z*strB;
    float*  Cf = (float*)Cv  + (long long)z*strC;
    __half* Ch = (__half*)Cv + (long long)z*strC;

    const int brow = blockIdx.y*BM;
    const int bcol = blockIdx.x*BN;
    const int tid  = threadIdx.x;
    const int wid  = tid >> 5;
    const int lane = tid & 31;
    const int wx   = wid % WX, wy = wid / WX;
    const int warp_m = wy*64, warp_n = wx*32;
    const int g = lane >> 2, t = lane & 3;

    const uint32_t aoff = (uint32_t)(((warp_m + (lane&15))*LDKW + (lane>>4)*4))*4u;
    const uint32_t boff = (uint32_t)((AW + (warp_n + (lane>>4)*8 + (lane&7))*LDKW + ((lane>>3)&1)*4))*4u;

    float acc[4][4][4];
    #pragma unroll
    for (int i=0;i<4;i++)
        #pragma unroll
        for (int j=0;j<4;j++)
            #pragma unroll
            for (int u=0;u<4;u++) acc[i][j][u]=0.f;

    const int nc = K >> 6;

    #define HISSUE(chunk) do{                                                  \
        const uint32_t bA_ = smb + (uint32_t)(((chunk)&1)*SW)*4u;              \
        const uint32_t bB_ = bA_ + (uint32_t)AW*4u;                            \
        const __half* Ap_ = A + (long long)brow*lda + (chunk)*64;              \
        const __half* Bp_ = B + (long long)bcol*ldb + (chunk)*64;              \
        _Pragma("unroll")                                                      \
        for (int l=0;l<ALD;l++){                                               \
            const int idx = tid + l*THREADS, r = idx>>3, c4 = idx&7;           \
            cpa16(bA_ + (uint32_t)(r*LDKW + c4*4)*4u,                          \
                  Ap_ + (long long)r*lda + c4*8);                              \
        }                                                                      \
        _Pragma("unroll")                                                      \
        for (int l=0;l<BLD;l++){                                               \
            const int idx = tid + l*THREADS, r = idx>>3, c4 = idx&7;           \
            cpa16(bB_ + (uint32_t)(r*LDKW + c4*4)*4u,                          \
                  Bp_ + (long long)r*ldb + c4*8);                              \
        }                                                                      \
    }while(0)

    HISSUE(0);
    CP_COMMIT();

    for (int i=0; i<nc; ++i){
        CP_WAIT0();
        __syncthreads();
        if (i+1 < nc){ HISSUE(i+1); CP_COMMIT(); }

        const uint32_t stg = smb + (uint32_t)((i&1)*SW)*4u;

        #pragma unroll
        for (int kk=0; kk<4; ++kk){
            uint32_t af[4][4], bf[4][2];
            #pragma unroll
            for (int mt=0; mt<4; ++mt)
                LDSM4(af[mt][0],af[mt][1],af[mt][2],af[mt][3],
                      stg + aoff + (uint32_t)((mt*16*LDKW + kk*8))*4u);
            LDSM4(bf[0][0],bf[0][1],bf[1][0],bf[1][1],
                  stg + boff + (uint32_t)(kk*8)*4u);
            LDSM4(bf[2][0],bf[2][1],bf[3][0],bf[3][1],
                  stg + boff + (uint32_t)((16*LDKW + kk*8))*4u);
            #pragma unroll
            for (int mt=0; mt<4; ++mt)
                #pragma unroll
                for (int nt=0; nt<4; ++nt)
                    mma_f16(acc[mt][nt], af[mt], bf[nt]);
        }
        __syncthreads();
    }
    #undef HISSUE

    // ================= epilogues =================
    if (EPI==EPI_QFEAT || EPI==EPI_KFEAT){
        float mxs[4][2];
        #pragma unroll
        for (int mt=0; mt<4; ++mt){
            float m0=-3.402823466e38f, m1=m0;
            #pragma unroll
            for (int nt=0; nt<4; ++nt){
                #pragma unroll
                for (int u=0;u<4;u++) acc[mt][nt][u]*=alpha;
                m0 = fmaxf(m0, fmaxf(acc[mt][nt][0], acc[mt][nt][1]));
                m1 = fmaxf(m1, fmaxf(acc[mt][nt][2], acc[mt][nt][3]));
            }
            m0 = fmaxf(m0, __shfl_xor_sync(0xffffffffu,m0,1));
            m0 = fmaxf(m0, __shfl_xor_sync(0xffffffffu,m0,2));
            m1 = fmaxf(m1, __shfl_xor_sync(0xffffffffu,m1,1));
            m1 = fmaxf(m1, __shfl_xor_sync(0xffffffffu,m1,2));
            mxs[mt][0]=m0; mxs[mt][1]=m1;
        }
        __syncthreads();
        float* red = (float*)sh;               // [64][8]
        if (t==0){
            #pragma unroll
            for (int mt=0; mt<4; ++mt){
                red[(mt*16+g)*8 + wid]   = mxs[mt][0];
                red[(mt*16+8+g)*8 + wid] = mxs[mt][1];
            }
        }
        __syncthreads();
        #pragma unroll
        for (int mt=0; mt<4; ++mt){
            const int grow = brow + mt*16 + g;
            float mx0 = red[(mt*16+g)*8], mx1 = red[(mt*16+8+g)*8];
            #pragma unroll
            for (int w=1; w<8; ++w){
                mx0 = fmaxf(mx0, red[(mt*16+g)*8+w]);
                mx1 = fmaxf(mx1, red[(mt*16+8+g)*8+w]);
            }
            mxs[mt][0]=mx0; mxs[mt][1]=mx1;
            float d0, d1;
            if (EPI==EPI_QFEAT){ d0 = rowscale[grow] + mx0; d1 = rowscale[grow+8] + mx1; }
            else               { d0 = mx0;                  d1 = mx1; }
            #pragma unroll
            for (int nt=0; nt<4; ++nt){
                const int c0 = warp_n + nt*8 + 2*t;
                __half2 o0, o1;
                if (EPI==EPI_QFEAT){
                    o0 = __floats2half2_rn(RATIO_C*(expf(acc[mt][nt][0]-d0)+EPS_K),
                                           RATIO_C*(expf(acc[mt][nt][1]-d0)+EPS_K));
                    o1 = __floats2half2_rn(RATIO_C*(expf(acc[mt][nt][2]-d1)+EPS_K),
                                           RATIO_C*(expf(acc[mt][nt][3]-d1)+EPS_K));
                } else {
                    o0 = __floats2half2_rn(expf(acc[mt][nt][0]-d0), expf(acc[mt][nt][1]-d0));
                    o1 = __floats2half2_rn(expf(acc[mt][nt][2]-d1), expf(acc[mt][nt][3]-d1));
                }
                *reinterpret_cast<__half2*>(Ch + (long long)grow*ldc + c0)     = o0;
                *reinterpret_cast<__half2*>(Ch + (long long)(grow+8)*ldc + c0) = o1;
            }
            if (EPI==EPI_KFEAT && wid==0 && t==0){
                float* rowf = const_cast<float*>(res);
                rowf[grow]   = mx0 - rowscale[grow];
                rowf[grow+8] = mx1 - rowscale[grow+8];
            }
        }
        if (EPI==EPI_KFEAT && wid==0){
            float bm = fmaxf(fmaxf(mxs[0][0],mxs[0][1]), fmaxf(mxs[1][0],mxs[1][1]));
            bm = fmaxf(bm, fmaxf(fmaxf(mxs[2][0],mxs[2][1]), fmaxf(mxs[3][0],mxs[3][1])));
            #pragma unroll
            for (int o=16;o;o>>=1) bm = fmaxf(bm, __shfl_xor_sync(0xffffffffu,bm,o));
            if (lane==0){
                unsigned b = __float_as_uint(bm);
                unsigned u = (b & 0x80000000u) ? ~b : (b | 0x80000000u);
                atomicMax(&g_gmax_u, u);
            }
        }
        return;
    }

    float sq[4][2];
    if (EPI==EPI_QKV){
        #pragma unroll
        for (int mt=0; mt<4; ++mt){ sq[mt][0]=0.f; sq[mt][1]=0.f; }
    }

    #pragma unroll
    for (int mt=0; mt<4; ++mt){
        const int r0 = brow + warp_m + mt*16 + g;
        const int r1 = r0 + 8;
        float rs0 = 1.f, rs1 = 1.f;
        if (EPI==EPI_ATTN){
            rs0 = rowscale[(long long)z*M + r0];
            rs1 = rowscale[(long long)z*M + r1];
        }
        #pragma unroll
        for (int nt=0; nt<4; ++nt){
            const int c0 = bcol + warp_n + nt*8 + 2*t;
            float v00 = acc[mt][nt][0], v01 = acc[mt][nt][1];
            float v10 = acc[mt][nt][2], v11 = acc[mt][nt][3];
            if (EPI==EPI_BIAS_RES || EPI==EPI_BIAS_GELU || EPI==EPI_QKV){
                const float b0 = bias[c0], b1 = bias[c0+1];
                v00 += b0; v01 += b1; v10 += b0; v11 += b1;
            }
            if (EPI==EPI_BIAS_RES){
                v00 += res[(long long)r0*ldc + c0];   v01 += res[(long long)r0*ldc + c0+1];
                v10 += res[(long long)r1*ldc + c0];   v11 += res[(long long)r1*ldc + c0+1];
            }
            if (EPI==EPI_BIAS_GELU){
                v00 = 0.5f*v00*(1.0f+erff(v00*0.70710678118654752f));
                v01 = 0.5f*v01*(1.0f+erff(v01*0.70710678118654752f));
                v10 = 0.5f*v10*(1.0f+erff(v10*0.70710678118654752f));
                v11 = 0.5f*v11*(1.0f+erff(v11*0.70710678118654752f));
            }
            if (EPI==EPI_ATTN){ v00*=rs0; v01*=rs0; v10*=rs1; v11*=rs1; }

            if (EPI==EPI_QKV){
                sq[mt][0] += v00*v00 + v01*v01;
                sq[mt][1] += v10*v10 + v11*v11;
                const int sel = c0/Dd, cc = c0 - sel*Dd;
                const int h_ = cc>>6, dh_ = cc&63;
                const int b0_ = r0>>12, s0_ = r0&4095;
                const int b1_ = r1>>12, s1_ = r1&4095;
                __half* base = (__half*)Cv + (size_t)sel*NHR*DhD;
                *reinterpret_cast<__half2*>(base + ((((long long)(b0_*Hh+h_))<<12)+s0_)*DhD + dh_) = __floats2half2_rn(v00,v01);
                *reinterpret_cast<__half2*>(base + ((((long long)(b1_*Hh+h_))<<12)+s1_)*DhD + dh_) = __floats2half2_rn(v10,v11);
            } else if (EPI==EPI_ATTN){
                const int bb = z/Hh, hh = z - (z/Hh)*Hh;
                __half* base = (__half*)Cv;
                const long long o0 = ((long long)(bb*Ss + r0))*Dd + hh*64 + c0;
                const long long o1 = ((long long)(bb*Ss + r1))*Dd + hh*64 + c0;
                *reinterpret_cast<__half2*>(base + o0) = __floats2half2_rn(v00,v01);
                *reinterpret_cast<__half2*>(base + o1) = __floats2half2_rn(v10,v11);
            } else if (OUTH){
                *reinterpret_cast<__half2*>(Ch + (long long)r0*ldc + c0) = __floats2half2_rn(v00,v01);
                *reinterpret_cast<__half2*>(Ch + (long long)r1*ldc + c0) = __floats2half2_rn(v10,v11);
            } else {
                float2 o0; o0.x=v00; o0.y=v01;
                float2 o1; o1.x=v10; o1.y=v11;
                *reinterpret_cast<float2*>(Cf + (long long)r0*ldc + c0) = o0;
                *reinterpret_cast<float2*>(Cf + (long long)r1*ldc + c0) = o1;
            }
        }
    }

    // fused diag for q/k tiles: g_diag[sel*NHR + row] = DIAG_C * sum(head 64 cols of v^2)
    if (EPI==EPI_QKV){
        const int sel_t = bcol/Dd;
        const int cc0   = bcol - sel_t*Dd;
        float* red = (float*)sh;               // [128 rows][4 wx]
        #pragma unroll
        for (int mt=0; mt<4; ++mt){
            #pragma unroll
            for (int j=0;j<2;j++){
                float v = sq[mt][j];
                v += __shfl_xor_sync(0xffffffffu, v, 1);
                v += __shfl_xor_sync(0xffffffffu, v, 2);
                if (t==0) red[(warp_m + mt*16 + j*8 + g)*4 + wx] = v;
            }
        }
        __syncthreads();
        if (sel_t < 2){
            const int row  = tid >> 1;         // 0..127
            const int head = tid & 1;          // 0..1
            const float ssum = red[row*4 + 2*head] + red[row*4 + 2*head + 1];
            const int gr = brow + row;
            const int b_ = gr>>12, s_ = gr&4095;
            const int h_ = (cc0>>6) + head;
            g_diag[(size_t)sel_t*NHR + (((long long)(b_*Hh+h_))<<12) + s_] = DIAG_C*ssum;
        }
    }
}

#define SMEM_H128x128 (2*(128+128)*36*4)   // 73728
#define SMEM_H64x256  (2*(64+256)*36*4)    // 92160
#define SMEM_H128x64  (2*(128+64)*36*4)    // 55296

// ================ ctx TN mma kernel, 4-way m split (BK=32, 3-stage) ====================
#define CTX_LDV 36
#define CTX_LDP 36
#define CTX_VW  (32*CTX_LDV)
#define CTX_PW  (32*CTX_LDP)
#define SMEM_CTX (3*(CTX_VW+CTX_PW)*4)     // 27648

__global__ void __launch_bounds__(256, 2)
ctx_mma(const __half* __restrict__ kpe, const __half* __restrict__ vh,
        const float* __restrict__ rowf,
        __half* __restrict__ ctxT, float* __restrict__ ksum)
{
    extern __shared__ uint32_t sh[];
    const uint32_t smb = smem_u32(sh);
    const uint32_t pbase = smb + (uint32_t)(3*CTX_VW)*4u;

    const int z = blockIdx.y;
    const int ntile = blockIdx.x;               // 0..3, 64 m-cols each
    const int tid = threadIdx.x, wid = tid>>5, lane = tid&31;
    const int warp_m = (wid & 3)*16;            // dh tile
    const int warp_n = (wid >> 2)*32;           // m tile
    const int g = lane>>2, t = lane&3;
    const int quad = lane>>3, r8 = lane&7;

    const __half* kpb = kpe + (long long)z*Ss*Mm + ntile*64;
    const __half* vhb = vh  + (long long)z*Ss*DhD;
    const float*  rfb = rowf + (long long)z*Ss;

    const float gmax = gmax_decode(g_gmax_u);
    const float epsr = RATIO_C*EPS_K;

    const uint32_t a_off0 = (uint32_t)((r8 + ((quad>>1)&1)*8)*CTX_LDV + (warp_m + (quad&1)*8)/2);
    const uint32_t b_off0 = (uint32_t)((r8 + (quad&1)*8)*CTX_LDP + (warp_n + (quad>>1)*8)/2);

    const int srow = tid >> 3;     // 0..31
    const int c8   = tid & 7;      // 8-half group

    float acc[4][4];
    #pragma unroll
    for (int j=0;j<4;j++)
        #pragma unroll
        for (int u=0;u<4;u++) acc[j][u]=0.f;
    float ks[8];
    #pragma unroll
    for (int j=0;j<8;j++) ks[j]=0.f;

    #define VISSUE(c) do{ \
        const uint32_t bV = smb + (uint32_t)(((c)%3)*CTX_VW)*4u; \
        cpa16(bV + (uint32_t)(srow*CTX_LDV + c8*4)*4u, \
              vhb + (long long)((c)*32 + srow)*DhD + c8*8); \
    }while(0)

    uint4 cur; float curf;
    cur  = *reinterpret_cast<const uint4*>(kpb + (long long)srow*Mm + c8*8);
    curf = rfb[srow];
    VISSUE(0); CP_COMMIT();
    VISSUE(1); CP_COMMIT();

    for (int i=0; i<Ss/32; ++i){
        {
            const float As = RATIO_C*expf(curf - gmax);
            uint32_t rw[4] = {cur.x,cur.y,cur.z,cur.w};
            uint32_t ow[4];
            #pragma unroll
            for (int j=0;j<4;j++){
                float2 f = __half22float2(*reinterpret_cast<__half2*>(&rw[j]));
                f.x = fmaf(f.x, As, epsr);
                f.y = fmaf(f.y, As, epsr);
                __half2 h = __floats2half2_rn(f.x, f.y);
                float2 fr = __half22float2(h);
                ks[2*j]   += fr.x;
                ks[2*j+1] += fr.y;
                ow[j] = *reinterpret_cast<uint32_t*>(&h);
            }
            const uint32_t bP = pbase + (uint32_t)((i%3)*CTX_PW)*4u
                              + (uint32_t)(srow*CTX_LDP + c8*4)*4u;
            uint4 s0 = {ow[0],ow[1],ow[2],ow[3]};
            *reinterpret_cast<uint4*>((char*)sh + (bP - smb)) = s0;
        }
        CP_WAIT1();
        __syncthreads();
        if (i+2 < Ss/32) VISSUE(i+2);
        CP_COMMIT();
        if (i+1 < Ss/32){
            cur  = *reinterpret_cast<const uint4*>(kpb + (long long)((i+1)*32 + srow)*Mm + c8*8);
            curf = rfb[(i+1)*32 + srow];
        }

        const uint32_t vstg = smb + (uint32_t)((i%3)*CTX_VW)*4u;
        const uint32_t pstg = pbase + (uint32_t)((i%3)*CTX_PW)*4u;

        #pragma unroll
        for (int kk=0; kk<2; ++kk){
            uint32_t af[4], bf[4][2];
            LDSM4T(af[0],af[1],af[2],af[3],
                   vstg + (a_off0 + (uint32_t)(kk*16*CTX_LDV))*4u);
            #pragma unroll
            for (int pp2=0; pp2<2; ++pp2)
                LDSM4T(bf[2*pp2][0],bf[2*pp2][1],bf[2*pp2+1][0],bf[2*pp2+1][1],
                       pstg + (b_off0 + (uint32_t)(kk*16*CTX_LDP + pp2*8))*4u);
            #pragma unroll
            for (int nt=0; nt<4; ++nt)
                mma_f16(acc[nt], af, bf[nt]);
        }
    }
    #undef VISSUE

    const int dh0 = warp_m + g;
    const int dh1 = dh0 + 8;
    #pragma unroll
    for (int nt=0; nt<4; ++nt){
        const int col = ntile*64 + warp_n + nt*8 + 2*t;
        *reinterpret_cast<__half2*>(ctxT + (long long)z*DhD*Mm + (long long)dh0*Mm + col)
            = __floats2half2_rn(acc[nt][0], acc[nt][1]);
        *reinterpret_cast<__half2*>(ctxT + (long long)z*DhD*Mm + (long long)dh1*Mm + col)
            = __floats2half2_rn(acc[nt][2], acc[nt][3]);
    }

    __syncthreads();
    float* red = (float*)sh;                // [32][64]
    #pragma unroll
    for (int j=0;j<8;j++) red[srow*64 + c8*8 + j] = ks[j];
    __syncthreads();
    if (tid < 64){
        float s = 0.f;
        #pragma unroll
        for (int r=0;r<32;r++) s += red[r*64 + tid];
        ksum[z*Mm + ntile*64 + tid] = s;
    }
}

// ---------------- single setup kernel: all weight f2h + bias pack + gmax reset --------
__global__ void setup_kernel(const float* __restrict__ wq, const float* __restrict__ wk,
                             const float* __restrict__ wv, const float* __restrict__ wo,
                             const float* __restrict__ w1, const float* __restrict__ w2,
                             const float* __restrict__ proj,
                             const float* __restrict__ bq, const float* __restrict__ bk,
                             const float* __restrict__ bv)
{
    const long long i = (long long)blockIdx.x*256 + threadIdx.x;
    const long long Q = Dd*Dd/4;           // 147456
    const long long W = (long long)FFH*Dd/4; // 589824
    const long long P = Mm*DhD/4;          // 4096
    const long long T0 = 4*Q, T1 = T0 + 2*W + P, T2 = T1 + 3*Dd;
    if (i < T0){
        const int seg = (int)(i/Q), off = (int)(i - seg*Q);
        const float* s = (seg==0)?wq:(seg==1)?wk:(seg==2)?wv:wo;
        __half* d = (seg<3) ? (g_wqkvh + (size_t)seg*Dd*Dd) : g_woh;
        float4 v = reinterpret_cast<const float4*>(s)[off];
        __half2* o = reinterpret_cast<__half2*>(d) + 2*off;
        o[0] = __floats2half2_rn(v.x, v.y);
        o[1] = __floats2half2_rn(v.z, v.w);
    } else if (i < T1){
        long long j = i - T0;
        const float* s; __half* d; int off;
        if (j < W)          { s = w1;   d = g_w1h;   off = (int)j; }
        else if (j < 2*W)   { s = w2;   d = g_w2h;   off = (int)(j - W); }
        else                { s = proj; d = g_projh; off = (int)(j - 2*W); }
        float4 v = reinterpret_cast<const float4*>(s)[off];
        __half2* o = reinterpret_cast<__half2*>(d) + 2*off;
        o[0] = __floats2half2_rn(v.x, v.y);
        o[1] = __floats2half2_rn(v.z, v.w);
    } else if (i < T2){
        const int j = (int)(i - T1);
        const int sel = j/Dd, c = j - sel*Dd;
        g_bqkv[j] = sel==0 ? bq[c] : (sel==1 ? bk[c] : bv[c]);
    } else if (i == T2){
        g_gmax_u = 0u;
    }
}
#define SETUP_N (4LL*(Dd*Dd/4) + 2LL*((long long)FFH*Dd/4) + Mm*DhD/4 + 3*Dd + 1)

// ---------------- LayerNorm (row=768), half output ----------------
__global__ void ln_kernel(const float* __restrict__ x, const float* __restrict__ g,
                          const float* __restrict__ b, __half* __restrict__ out)
{
    const int row = blockIdx.x;
    const float* xr = x + (long long)row*Dd;
    float v[3]; float s=0.f, ss=0.f;
    #pragma unroll
    for (int i=0;i<3;i++){ v[i]=xr[threadIdx.x + i*256]; s+=v[i]; ss+=v[i]*v[i]; }
    #pragma unroll
    for (int o=16;o;o>>=1){ s+=__shfl_xor_sync(0xffffffffu,s,o); ss+=__shfl_xor_sync(0xffffffffu,ss,o); }
    __shared__ float rs_[8], rss_[8];
    const int lane = threadIdx.x & 31, w = threadIdx.x >> 5;
    if (lane==0){ rs_[w]=s; rss_[w]=ss; }
    __syncthreads();
    s=0.f; ss=0.f;
    #pragma unroll
    for (int i=0;i<8;i++){ s+=rs_[i]; ss+=rss_[i]; }
    const float mu  = s*(1.0f/Dd);
    const float var = ss*(1.0f/Dd) - mu*mu;
    const float rstd = rsqrtf(var + LN_EPS);
    __half* outr = out + (long long)row*Dd;
    #pragma unroll
    for (int i=0;i<3;i++){
        int c = threadIdx.x + i*256;
        outr[c] = __float2half((v[i]-mu)*rstd*g[c] + b[c]);
    }
}

// ---------------- d_inv: half qp, fp32 ksum (warp per row) ----------------
__global__ void dinv_kernel(const __half* __restrict__ qp, float* __restrict__ dinv)
{
    const int lane = threadIdx.x & 31, w = threadIdx.x >> 5;
    const long long row = (long long)blockIdx.x*8 + w;
    const int bh = (int)(row >> 12);
    const __half2* p = reinterpret_cast<const __half2*>(qp + row*Mm);
    const float4* ks = reinterpret_cast<const float4*>(g_ksum + (long long)bh*Mm);
    float s = 0.f;
    #pragma unroll
    for (int h=0; h<2; ++h){
        const int li = lane + h*32;
        float2 a0 = __half22float2(p[2*li]), a1 = __half22float2(p[2*li+1]);
        float4 k4 = ks[li];
        s += a0.x*k4.x + a0.y*k4.y + a1.x*k4.z + a1.y*k4.w;
    }
    #pragma unroll
    for (int o=16;o;o>>=1) s += __shfl_xor_sync(0xffffffffu,s,o);
    if (lane==0) dinv[row] = 1.0f/s;
}

// ---------------- host ----------------
extern "C" void kernel_launch(void* const* d_in, const int* in_sizes, int n_in,
                              void* d_out, int out_size)
{
    const float* x    = (const float*)d_in[0];
    const float* proj = (const float*)d_in[1];
    const float* wq   = (const float*)d_in[2];
    const float* bq   = (const float*)d_in[3];
    const float* wk   = (const float*)d_in[4];
    const float* bk   = (const float*)d_in[5];
    const float* wv   = (const float*)d_in[6];
    const float* bv   = (const float*)d_in[7];
    const float* wo   = (const float*)d_in[8];
    const float* bo   = (const float*)d_in[9];
    const float* ln1g = (const float*)d_in[10];
    const float* ln1b = (const float*)d_in[11];
    const float* ln2g = (const float*)d_in[12];
    const float* ln2b = (const float*)d_in[13];
    const float* w1   = (const float*)d_in[14];
    const float* b1   = (const float*)d_in[15];
    const float* w2   = (const float*)d_in[16];
    const float* b2   = (const float*)d_in[17];
    float* out = (float*)d_out;

    void *p;
    __half *wqkvh, *h1h, *qkvh, *qph, *kph, *midh, *ctxTh, *attn2h, *woh, *w1h, *w2h, *projh;
    float *ddiag, *rowf, *x2, *dinv, *ksum, *bqkv;
    cudaGetSymbolAddress(&p, g_wqkvh);  wqkvh  = (__half*)p;
    cudaGetSymbolAddress(&p, g_woh);    woh    = (__half*)p;
    cudaGetSymbolAddress(&p, g_w1h);    w1h    = (__half*)p;
    cudaGetSymbolAddress(&p, g_w2h);    w2h    = (__half*)p;
    cudaGetSymbolAddress(&p, g_projh);  projh  = (__half*)p;
    cudaGetSymbolAddress(&p, g_h1h);    h1h    = (__half*)p;
    cudaGetSymbolAddress(&p, g_qkvh);   qkvh   = (__half*)p;
    cudaGetSymbolAddress(&p, g_qph);    qph    = (__half*)p;
    cudaGetSymbolAddress(&p, g_kph);    kph    = (__half*)p;
    cudaGetSymbolAddress(&p, g_midh);   midh   = (__half*)p;
    cudaGetSymbolAddress(&p, g_ctxTh);  ctxTh  = (__half*)p;
    cudaGetSymbolAddress(&p, g_attn2h); attn2h = (__half*)p;
    cudaGetSymbolAddress(&p, g_x2);     x2     = (float*)p;
    cudaGetSymbolAddress(&p, g_diag);   ddiag  = (float*)p;
    cudaGetSymbolAddress(&p, g_rowf);   rowf   = (float*)p;
    cudaGetSymbolAddress(&p, g_dinv);   dinv   = (float*)p;
    cudaGetSymbolAddress(&p, g_ksum);   ksum   = (float*)p;
    cudaGetSymbolAddress(&p, g_bqkv);   bqkv   = (float*)p;

    __half* qh = qkvh;
    __half* kh = qkvh + (size_t)NHR*DhD;
    __half* vh = qkvh + 2*(size_t)NHR*DhD;
    float* dq = ddiag;
    float* dk = ddiag + NHR;

    cudaFuncSetAttribute(hgemm<128,128,EPI_QKV,true>,       cudaFuncAttributeMaxDynamicSharedMemorySize, SMEM_H128x128);
    cudaFuncSetAttribute(hgemm<64,256,EPI_QFEAT,true>,      cudaFuncAttributeMaxDynamicSharedMemorySize, SMEM_H64x256);
    cudaFuncSetAttribute(hgemm<64,256,EPI_KFEAT,true>,      cudaFuncAttributeMaxDynamicSharedMemorySize, SMEM_H64x256);
    cudaFuncSetAttribute(hgemm<128,64,EPI_ATTN,true>,       cudaFuncAttributeMaxDynamicSharedMemorySize, SMEM_H128x64);
    cudaFuncSetAttribute(hgemm<128,128,EPI_BIAS_RES,false>, cudaFuncAttributeMaxDynamicSharedMemorySize, SMEM_H128x128);
    cudaFuncSetAttribute(hgemm<128,128,EPI_BIAS_GELU,true>, cudaFuncAttributeMaxDynamicSharedMemorySize, SMEM_H128x128);

    // setup: one launch (weights fp16, bias pack, gmax reset)
    setup_kernel<<<(int)((SETUP_N + 255)/256), 256>>>(wq,wk,wv,wo,w1,w2,proj,bq,bk,bv);
    ln_kernel<<<NROWS, 256>>>(x, ln1g, ln1b, h1h);

    // fused QKV (N=2304) + fused diag (q,k)
    hgemm<128,128,EPI_QKV,true><<<dim3(18,128,1),256,SMEM_H128x128>>>(
        h1h,Dd,0, wqkvh,Dd,0, qkvh,DhD,0, NROWS,3*Dd,Dd, bqkv,nullptr,nullptr,0.f);

    // q features fused: GEMM + rowmax + exp -> qph
    hgemm<64,256,EPI_QFEAT,true><<<dim3(1,NHR/64,1),256,SMEM_H64x256>>>(
        qh,DhD,0, projh,DhD,0, qph,Mm,0, NHR,Mm,DhD, nullptr,nullptr,dq,NORM_C);
    // k features: GEMM + rowmax + exp(dd-rowmax) -> kph, rowf, gmax
    hgemm<64,256,EPI_KFEAT,true><<<dim3(1,NHR/64,1),256,SMEM_H64x256>>>(
        kh,DhD,0, projh,DhD,0, kph,Mm,0, NHR,Mm,DhD, nullptr,rowf,dk,NORM_C);

    // ctx (tensor mma, TN, 4-way m split) + fused ksum
    ctx_mma<<<dim3(4,NBH), 256, SMEM_CTX>>>(kph, vh, rowf, ctxTh, ksum);

    // d_inv
    dinv_kernel<<<NHR/8, 256>>>(qph, dinv);

    // attn = d_inv * (qp @ ctx), fused transpose -> attn2h [b,s,D]
    hgemm<128,64,EPI_ATTN,true><<<dim3(1,Ss/128,NBH),128,SMEM_H128x64>>>(
        qph,Mm,(long long)Ss*Mm, ctxTh,Mm,(long long)DhD*Mm, attn2h,DhD,0,
        Ss,DhD,Mm, nullptr,nullptr,dinv,0.f);

    // x2 = x + attn @ wo^T + bo (fp32)
    hgemm<128,128,EPI_BIAS_RES,false><<<dim3(6,128,1),256,SMEM_H128x128>>>(
        attn2h,Dd,0, woh,Dd,0, x2,Dd,0, NROWS,Dd,Dd, bo,x,nullptr,0.f);

    // LN2 -> half
    ln_kernel<<<NROWS, 256>>>(x2, ln2g, ln2b, h1h);

    // mid = gelu(h1 @ w1^T + b1) -> half
    hgemm<128,128,EPI_BIAS_GELU,true><<<dim3(FFH/128,128,1),256,SMEM_H128x128>>>(
        h1h,Dd,0, w1h,Dd,0, midh,FFH,0, NROWS,FFH,Dd, b1,nullptr,nullptr,0.f);

    // out = x2 + mid @ w2^T + b2 (fp32)
    hgemm<128,128,EPI_BIAS_RES,false><<<dim3(6,128,1),256,SMEM_H128x128>>>(
        midh,FFH,0, w2h,FFH,0, out,Dd,0, NROWS,Dd,FFH, b2,x2,nullptr,0.f);
}